// round 9
// baseline (speedup 1.0000x reference)
#include <cuda_runtime.h>
#include <mma.h>
#include <cstdint>

using namespace nvcuda;

// ---------------------------------------------------------------------------
// PAM, wmma tf32, cp.async everywhere, 512-thread CTAs (16 warps/SM).
// All GEMM inputs pre-rounded/split to tf32 at producer time.
//   split_x, W producers -> qk GEMM (split, hi/lo out) -> v GEMM (plain,
//   transposed rounded store) -> S = q k^T (split) -> softmax (rounded P)
//   -> out = gamma*(P v) + x (plain)
// ---------------------------------------------------------------------------

#define B_    4
#define NTOK  4096
#define CC    512
#define CRD   64
#define BNTOT (B_ * NTOK)

__device__ float g_xH[(size_t)BNTOT * CC];
__device__ float g_xL[(size_t)BNTOT * CC];
__device__ float g_qkH[(size_t)BNTOT * 128];
__device__ float g_qkL[(size_t)BNTOT * 128];
__device__ float g_vT[(size_t)B_ * CC * NTOK];   // [b][c][tok], rounded
__device__ float g_S[(size_t)B_ * NTOK * NTOK];  // scores -> rounded probs
__device__ float g_WqkTH[128 * CC];
__device__ float g_WqkTL[128 * CC];
__device__ float g_WdT[CC * CC];                 // rounded

__device__ __forceinline__ float f2tf(float f) {
    uint32_t u;
    asm("cvt.rna.tf32.f32 %0, %1;" : "=r"(u) : "f"(f));
    return __uint_as_float(u);
}
__device__ __forceinline__ uint32_t smem_u32(const void* p) {
    uint32_t a;
    asm("{ .reg .u64 t; cvta.to.shared.u64 t, %1; cvt.u32.u64 %0, t; }"
        : "=r"(a) : "l"(p));
    return a;
}
__device__ __forceinline__ void cp16(uint32_t saddr, const void* g) {
    asm volatile("cp.async.cg.shared.global [%0], [%1], 16;" ::"r"(saddr),
                 "l"(g));
}
#define CP_COMMIT() asm volatile("cp.async.commit_group;" ::: "memory")
#define CP_WAIT0()  asm volatile("cp.async.wait_group 0;" ::: "memory")

// ---------------- producers --------------------------------------------------
__global__ void split_x(const float4* __restrict__ in, float4* __restrict__ oh,
                        float4* __restrict__ ol, int n4) {
    int i = blockIdx.x * 256 + threadIdx.x;
    if (i < n4) {
        float4 v = in[i];
        float4 h, l;
        h.x = f2tf(v.x); l.x = f2tf(v.x - h.x);
        h.y = f2tf(v.y); l.y = f2tf(v.y - h.y);
        h.z = f2tf(v.z); l.z = f2tf(v.z - h.z);
        h.w = f2tf(v.w); l.w = f2tf(v.w - h.w);
        oh[i] = h;
        ol[i] = l;
    }
}
__global__ void transpose_w_round(const float* __restrict__ W,
                                  float* __restrict__ WT, int K, int N) {
    int i = blockIdx.x * 256 + threadIdx.x;
    if (i < K * N) {
        int n = i / K, k = i - n * K;
        WT[i] = f2tf(W[(size_t)k * N + n]);
    }
}
__global__ void transpose_wqk_split(const float* __restrict__ Wb,
                                    const float* __restrict__ Wc,
                                    float* __restrict__ WTH,
                                    float* __restrict__ WTL) {
    int i = blockIdx.x * 256 + threadIdx.x;
    if (i < 128 * CC) {
        int n = i / CC, k = i - n * CC;
        float v = (n < CRD) ? Wb[(size_t)k * CRD + n]
                            : Wc[(size_t)k * CRD + (n - CRD)];
        float h = f2tf(v);
        WTH[i] = h;
        WTL[i] = f2tf(v - h);
    }
}

// ---------------- cp.async wmma GEMM engine, 512 threads --------------------
// D tile 128 x TN. 16 warps as 4(m) x 4(n); warp tile 32 x (TN/4). K-chunk 32,
// 2-stage cp.async pipeline. Inputs must be tf32-exact in gmem.
// SPLIT: acc += AH*BL + AL*BH + AH*BH.
// EPI 0: C = acc           EPI 1: transposed vT store (rounded)
// EPI 2: C = gamma*acc+x   EPI 3: hi/lo split store to C / C2
template <int TN, int EPI, bool SPLIT>
__global__ __launch_bounds__(512) void gemm_async(
    const float* __restrict__ AH, const float* __restrict__ AL,
    const float* __restrict__ BH, const float* __restrict__ BL,
    float* __restrict__ C, float* __restrict__ C2, int K, int ldA, int ldB,
    int ldC, size_t sA, size_t sB, size_t sC, const float* __restrict__ xres,
    const float* __restrict__ gamma) {
    extern __shared__ float sm[];
    constexpr int ASZ = 128 * 36, BSZ = TN * 36;
    constexpr int CMP = SPLIT ? 2 : 1;
    constexpr int STG = CMP * (ASZ + BSZ);  // floats per stage
    constexpr int NT = TN / 64;             // 16-col wmma tiles per warp
    constexpr int NBL = TN / 64;            // B cp16 per thread (=TN*8/512)
    constexpr int H = TN / 128;             // epilogue col-halves

    const int t = threadIdx.x, wid = t >> 5;
    const int warp_m = wid & 3, warp_n = wid >> 2;
    const int bx = blockIdx.x, by = blockIdx.y, bz = blockIdx.z;
    const uint32_t smb = smem_u32(sm);

    const float* AtH = AH + bz * sA + (size_t)(by * 128) * ldA;
    const float* BtH = BH + bz * sB + (size_t)(bx * TN) * ldB;
    const float* AtL = SPLIT ? AL + bz * sA + (size_t)(by * 128) * ldA : nullptr;
    const float* BtL = SPLIT ? BL + bz * sB + (size_t)(bx * TN) * ldB : nullptr;

    wmma::fragment<wmma::accumulator, 16, 16, 8, float> acc[2][NT];
#pragma unroll
    for (int i = 0; i < 2; i++)
#pragma unroll
        for (int j = 0; j < NT; j++) wmma::fill_fragment(acc[i][j], 0.f);

    auto issue = [&](int s, int k0) {
        uint32_t ab = smb + s * STG * 4;
        uint32_t bb = ab + CMP * ASZ * 4;
#pragma unroll
        for (int i = 0; i < 2; i++) {
            int id = t + i * 512, r = id >> 3, c = id & 7;
            uint32_t so = (r * 36 + c * 4) * 4;
            cp16(ab + so, AtH + (size_t)r * ldA + k0 + c * 4);
            if (SPLIT)
                cp16(ab + ASZ * 4 + so, AtL + (size_t)r * ldA + k0 + c * 4);
        }
#pragma unroll
        for (int i = 0; i < NBL; i++) {
            int id = t + i * 512, r = id >> 3, c = id & 7;
            uint32_t so = (r * 36 + c * 4) * 4;
            cp16(bb + so, BtH + (size_t)r * ldB + k0 + c * 4);
            if (SPLIT)
                cp16(bb + BSZ * 4 + so, BtL + (size_t)r * ldB + k0 + c * 4);
        }
    };

    issue(0, 0);
    CP_COMMIT();
    CP_WAIT0();
    __syncthreads();

    const int KB = K / 32;
    for (int kb = 0; kb < KB; kb++) {
        const int p = kb & 1;
        if (kb + 1 < KB) {
            issue(p ^ 1, (kb + 1) * 32);
            CP_COMMIT();
        }
        float* AsH = sm + p * STG;
        float* AsL = AsH + ASZ;
        float* BsH = AsH + CMP * ASZ;
        float* BsL = BsH + BSZ;
#pragma unroll
        for (int ks = 0; ks < 4; ks++) {
            if (SPLIT) {
                wmma::fragment<wmma::matrix_a, 16, 16, 8,
                               wmma::precision::tf32, wmma::row_major>
                    faH[2], faL[2];
#pragma unroll
                for (int i = 0; i < 2; i++) {
                    int off = (warp_m * 32 + i * 16) * 36 + ks * 8;
                    wmma::load_matrix_sync(faH[i], AsH + off, 36);
                    wmma::load_matrix_sync(faL[i], AsL + off, 36);
                }
#pragma unroll
                for (int j = 0; j < NT; j++) {
                    int off = (warp_n * (TN / 4) + j * 16) * 36 + ks * 8;
                    wmma::fragment<wmma::matrix_b, 16, 16, 8,
                                   wmma::precision::tf32, wmma::col_major>
                        fbH, fbL;
                    wmma::load_matrix_sync(fbH, BsH + off, 36);
                    wmma::load_matrix_sync(fbL, BsL + off, 36);
#pragma unroll
                    for (int i = 0; i < 2; i++) {
                        wmma::mma_sync(acc[i][j], faH[i], fbL, acc[i][j]);
                        wmma::mma_sync(acc[i][j], faL[i], fbH, acc[i][j]);
                        wmma::mma_sync(acc[i][j], faH[i], fbH, acc[i][j]);
                    }
                }
            } else {
                wmma::fragment<wmma::matrix_a, 16, 16, 8,
                               wmma::precision::tf32, wmma::row_major> fa[2];
#pragma unroll
                for (int i = 0; i < 2; i++)
                    wmma::load_matrix_sync(
                        fa[i], AsH + (warp_m * 32 + i * 16) * 36 + ks * 8, 36);
#pragma unroll
                for (int j = 0; j < NT; j++) {
                    wmma::fragment<wmma::matrix_b, 16, 16, 8,
                                   wmma::precision::tf32, wmma::col_major> fb;
                    wmma::load_matrix_sync(
                        fb, BsH + (warp_n * (TN / 4) + j * 16) * 36 + ks * 8,
                        36);
#pragma unroll
                    for (int i = 0; i < 2; i++)
                        wmma::mma_sync(acc[i][j], fa[i], fb, acc[i][j]);
                }
            }
        }
        if (kb + 1 < KB) CP_WAIT0();
        __syncthreads();
    }

    // ---------------- epilogue (per 128-col half) ----------------------------
    float* Cs = sm;
    const float g = (EPI == 2) ? gamma[0] : 0.f;
#pragma unroll
    for (int h = 0; h < H; h++) {
        if (H == 1 || (warp_n >> 1) == h) {
            int cb = (H == 1) ? warp_n * (TN / 4) : (warp_n & 1) * 64;
#pragma unroll
            for (int i = 0; i < 2; i++)
#pragma unroll
                for (int j = 0; j < NT; j++)
                    wmma::store_matrix_sync(
                        Cs + (warp_m * 32 + i * 16) * 132 + cb + j * 16,
                        acc[i][j], 132, wmma::mem_row_major);
        }
        __syncthreads();
        const int col0 = bx * TN + h * 128;
        if (EPI == 1) {
            const int tok0 = by * 128;
            const int bglob = tok0 >> 12;
            const int tokin0 = tok0 & (NTOK - 1);
            for (int e = t; e < 128 * 32; e += 512) {
                int j = e >> 5, tq = e & 31;
                float4 o;
                o.x = f2tf(Cs[(tq * 4 + 0) * 132 + j]);
                o.y = f2tf(Cs[(tq * 4 + 1) * 132 + j]);
                o.z = f2tf(Cs[(tq * 4 + 2) * 132 + j]);
                o.w = f2tf(Cs[(tq * 4 + 3) * 132 + j]);
                *(float4*)&C[((size_t)bglob * CC + col0 + j) * NTOK + tokin0 +
                             tq * 4] = o;
            }
        } else if (EPI == 3) {
            for (int e = t; e < 128 * 32; e += 512) {
                int r = e >> 5, c4 = e & 31;
                float4 v = *(float4*)&Cs[r * 132 + c4 * 4];
                float4 hh, ll;
                hh.x = f2tf(v.x); ll.x = f2tf(v.x - hh.x);
                hh.y = f2tf(v.y); ll.y = f2tf(v.y - hh.y);
                hh.z = f2tf(v.z); ll.z = f2tf(v.z - hh.z);
                hh.w = f2tf(v.w); ll.w = f2tf(v.w - hh.w);
                size_t idx = (size_t)(by * 128 + r) * ldC + col0 + c4 * 4;
                *(float4*)&C[idx] = hh;
                *(float4*)&C2[idx] = ll;
            }
        } else {
            for (int e = t; e < 128 * 32; e += 512) {
                int r = e >> 5, c4 = e & 31;
                float4 o = *(float4*)&Cs[r * 132 + c4 * 4];
                size_t base =
                    bz * sC + (size_t)(by * 128 + r) * ldC + col0 + c4 * 4;
                if (EPI == 2) {
                    float4 xr = *(const float4*)&xres[base];
                    o.x = g * o.x + xr.x;
                    o.y = g * o.y + xr.y;
                    o.z = g * o.z + xr.z;
                    o.w = g * o.w + xr.w;
                }
                *(float4*)&C[base] = o;
            }
        }
        if (h + 1 < H) __syncthreads();
    }
}

// ---------------- row softmax (writes tf32-rounded probs) --------------------
__global__ __launch_bounds__(256) void softmax_kernel(float* __restrict__ S) {
    __shared__ float red[8];
    const size_t row = blockIdx.x;
    float4* p = (float4*)(S + row * NTOK);
    const int t = threadIdx.x, w = t >> 5, lane = t & 31;

    float4 v[4];
#pragma unroll
    for (int j = 0; j < 4; j++) v[j] = p[t + j * 256];

    float mx = -3.4e38f;
#pragma unroll
    for (int j = 0; j < 4; j++)
        mx = fmaxf(mx, fmaxf(fmaxf(v[j].x, v[j].y), fmaxf(v[j].z, v[j].w)));
#pragma unroll
    for (int o = 16; o; o >>= 1) mx = fmaxf(mx, __shfl_xor_sync(~0u, mx, o));
    if (lane == 0) red[w] = mx;
    __syncthreads();
    mx = red[0];
#pragma unroll
    for (int i = 1; i < 8; i++) mx = fmaxf(mx, red[i]);
    __syncthreads();

    float sum = 0.f;
#pragma unroll
    for (int j = 0; j < 4; j++) {
        v[j].x = __expf(v[j].x - mx);
        v[j].y = __expf(v[j].y - mx);
        v[j].z = __expf(v[j].z - mx);
        v[j].w = __expf(v[j].w - mx);
        sum += v[j].x + v[j].y + v[j].z + v[j].w;
    }
#pragma unroll
    for (int o = 16; o; o >>= 1) sum += __shfl_xor_sync(~0u, sum, o);
    if (lane == 0) red[w] = sum;
    __syncthreads();
    sum = red[0];
#pragma unroll
    for (int i = 1; i < 8; i++) sum += red[i];
    float inv = 1.f / sum;
#pragma unroll
    for (int j = 0; j < 4; j++) {
        v[j].x = f2tf(v[j].x * inv);
        v[j].y = f2tf(v[j].y * inv);
        v[j].z = f2tf(v[j].z * inv);
        v[j].w = f2tf(v[j].w * inv);
        p[t + j * 256] = v[j];
    }
}

// ---------------------------------------------------------------------------
static inline int smem_async(int TN, bool split) {
    int stage = (split ? 2 : 1) * (128 + TN) * 36 * 4;
    int buf = 2 * stage;
    int cs = 128 * 132 * 4;
    return buf > cs ? buf : cs;
}

extern "C" void kernel_launch(void* const* d_in, const int* in_sizes, int n_in,
                              void* d_out, int out_size) {
    const float* x = (const float*)d_in[0];
    const float* Wb = (const float*)d_in[1];
    const float* Wc = (const float*)d_in[2];
    const float* Wd = (const float*)d_in[3];
    const float* gamma = (const float*)d_in[4];
    float* out = (float*)d_out;

    float *xH, *xL, *qkH, *qkL, *vTp, *Sp, *WqkTH, *WqkTL, *WdT;
    cudaGetSymbolAddress((void**)&xH, g_xH);
    cudaGetSymbolAddress((void**)&xL, g_xL);
    cudaGetSymbolAddress((void**)&qkH, g_qkH);
    cudaGetSymbolAddress((void**)&qkL, g_qkL);
    cudaGetSymbolAddress((void**)&vTp, g_vT);
    cudaGetSymbolAddress((void**)&Sp, g_S);
    cudaGetSymbolAddress((void**)&WqkTH, g_WqkTH);
    cudaGetSymbolAddress((void**)&WqkTL, g_WqkTL);
    cudaGetSymbolAddress((void**)&WdT, g_WdT);

    cudaFuncSetAttribute(gemm_async<128, 3, true>,
                         cudaFuncAttributeMaxDynamicSharedMemorySize,
                         smem_async(128, true));
    cudaFuncSetAttribute(gemm_async<128, 0, true>,
                         cudaFuncAttributeMaxDynamicSharedMemorySize,
                         smem_async(128, true));
    cudaFuncSetAttribute(gemm_async<256, 1, false>,
                         cudaFuncAttributeMaxDynamicSharedMemorySize,
                         smem_async(256, false));
    cudaFuncSetAttribute(gemm_async<256, 2, false>,
                         cudaFuncAttributeMaxDynamicSharedMemorySize,
                         smem_async(256, false));

    // producers
    split_x<<<(BNTOT * CC / 4 + 255) / 256, 256>>>(
        (const float4*)x, (float4*)xH, (float4*)xL, BNTOT * CC / 4);
    transpose_wqk_split<<<(128 * CC + 255) / 256, 256>>>(Wb, Wc, WqkTH, WqkTL);
    transpose_w_round<<<(CC * CC + 255) / 256, 256>>>(Wd, WdT, CC, CC);

    // qk = X @ [Wb|Wc] (split; hi/lo out; M=16384, N=128, K=512)
    gemm_async<128, 3, true><<<dim3(1, BNTOT / 128, 1), 512,
                               smem_async(128, true)>>>(
        xH, xL, WqkTH, WqkTL, qkH, qkL, CC, CC, CC, 128, 0, 0, 0, nullptr,
        nullptr);
    // vT: v = X @ Wd transposed+rounded store (plain)
    gemm_async<256, 1, false><<<dim3(CC / 256, BNTOT / 128, 1), 512,
                                smem_async(256, false)>>>(
        xH, nullptr, WdT, nullptr, vTp, nullptr, CC, CC, CC, 0, 0, 0, 0,
        nullptr, nullptr);
    // S = q k^T per batch (split; K=64)
    gemm_async<128, 0, true><<<dim3(NTOK / 128, NTOK / 128, B_), 512,
                               smem_async(128, true)>>>(
        qkH, qkL, qkH + CRD, qkL + CRD, Sp, nullptr, CRD, 128, 128, NTOK,
        (size_t)NTOK * 128, (size_t)NTOK * 128, (size_t)NTOK * NTOK, nullptr,
        nullptr);
    // softmax rows (writes rounded P)
    softmax_kernel<<<B_ * NTOK, 256>>>(Sp);
    // out = gamma * (P @ v) + x (plain; K=4096)
    gemm_async<256, 2, false><<<dim3(CC / 256, NTOK / 128, B_), 512,
                                smem_async(256, false)>>>(
        Sp, nullptr, vTp, nullptr, out, nullptr, NTOK, NTOK, NTOK, CC,
        (size_t)NTOK * NTOK, (size_t)CC * NTOK, (size_t)NTOK * CC, x, gamma);
}

// round 10
// speedup vs baseline: 1.1365x; 1.1365x over previous
#include <cuda_runtime.h>
#include <mma.h>
#include <cstdint>

using namespace nvcuda;

// ---------------------------------------------------------------------------
// PAM, wmma tf32, cp.async, 256-thread CTAs (round-8 engine).
// Softmax folded into S epilogue via fixed-shift exp (shift-invariant), row
// sums reduced separately; PV epilogue applies 1/l row scaling.
//   round_x, W producers -> qk GEMM (split, hi/lo out) -> v GEMM (plain,
//   transposed rounded store) -> S/P = exp(q k^T - 40) (split, rowsum out)
//   -> reduce_l -> out = gamma*(P v)*linv + x (plain)
// ---------------------------------------------------------------------------

#define B_    4
#define NTOK  4096
#define CC    512
#define CRD   64
#define BNTOT (B_ * NTOK)
#define ESHIFT 40.0f

__device__ float g_qkH[(size_t)BNTOT * 128];
__device__ float g_qkL[(size_t)BNTOT * 128];
__device__ float g_xr[(size_t)BNTOT * CC];       // tf32-rounded x
__device__ float g_vT[(size_t)B_ * CC * NTOK];   // [b][c][tok], rounded
__device__ float g_S[(size_t)B_ * NTOK * NTOK];  // exp'd rounded probs (raw)
__device__ float g_lpart[(size_t)B_ * 32 * NTOK];
__device__ float g_linv[(size_t)B_ * NTOK];
__device__ float g_WqkT[128 * CC];               // raw (split in-kernel)
__device__ float g_WdT[CC * CC];                 // rounded

__device__ __forceinline__ float f2tf(float f) {
    uint32_t u;
    asm("cvt.rna.tf32.f32 %0, %1;" : "=r"(u) : "f"(f));
    return __uint_as_float(u);
}
__device__ __forceinline__ uint32_t smem_u32(const void* p) {
    uint32_t a;
    asm("{ .reg .u64 t; cvta.to.shared.u64 t, %1; cvt.u32.u64 %0, t; }"
        : "=r"(a) : "l"(p));
    return a;
}
__device__ __forceinline__ void cp16(uint32_t saddr, const void* g) {
    asm volatile("cp.async.cg.shared.global [%0], [%1], 16;" ::"r"(saddr),
                 "l"(g));
}
#define CP_COMMIT() asm volatile("cp.async.commit_group;" ::: "memory")
#define CP_WAIT0()  asm volatile("cp.async.wait_group 0;" ::: "memory")

// ---------------- producers --------------------------------------------------
__global__ void round_x(const float4* __restrict__ in, float4* __restrict__ o,
                        int n4) {
    int i = blockIdx.x * 256 + threadIdx.x;
    if (i < n4) {
        float4 v = in[i];
        v.x = f2tf(v.x); v.y = f2tf(v.y); v.z = f2tf(v.z); v.w = f2tf(v.w);
        o[i] = v;
    }
}
__global__ void transpose_w_round(const float* __restrict__ W,
                                  float* __restrict__ WT, int K, int N) {
    int i = blockIdx.x * 256 + threadIdx.x;
    if (i < K * N) {
        int n = i / K, k = i - n * K;
        WT[i] = f2tf(W[(size_t)k * N + n]);
    }
}
__global__ void transpose_wqk(const float* __restrict__ Wb,
                              const float* __restrict__ Wc,
                              float* __restrict__ WT) {
    int i = blockIdx.x * 256 + threadIdx.x;
    if (i < 128 * CC) {
        int n = i / CC, k = i - n * CC;
        WT[i] = (n < CRD) ? Wb[(size_t)k * CRD + n]
                          : Wc[(size_t)k * CRD + (n - CRD)];
    }
}
__global__ void reduce_l(const float* __restrict__ lp,
                         float* __restrict__ linv) {
    int i = blockIdx.x * 256 + threadIdx.x;
    if (i < B_ * NTOK) {
        int b = i >> 12, row = i & (NTOK - 1);
        float s = 0.f;
#pragma unroll
        for (int j = 0; j < 32; j++)
            s += lp[((size_t)b * 32 + j) * NTOK + row];
        linv[i] = 1.f / s;
    }
}

// ---------------- qk GEMM: register-staged split, hi/lo output ---------------
__global__ __launch_bounds__(256) void gemm_qk(const float* __restrict__ A,
                                               const float* __restrict__ B,
                                               float* __restrict__ CH,
                                               float* __restrict__ CL) {
    extern __shared__ float sm[];
    constexpr int ASZ = 128 * 36, BSZ = 128 * 36;
    constexpr int STG = 2 * (ASZ + BSZ);
    const int t = threadIdx.x, wid = t >> 5;
    const int warp_m = wid >> 2, warp_n = wid & 3;
    const int by = blockIdx.y;

    const float* At = A + (size_t)(by * 128) * CC;

    wmma::fragment<wmma::accumulator, 16, 16, 8, float> acc[4][2];
#pragma unroll
    for (int i = 0; i < 4; i++)
#pragma unroll
        for (int j = 0; j < 2; j++) wmma::fill_fragment(acc[i][j], 0.f);

    float4 ra[4], rb[4];
    auto ldg = [&](int k0) {
#pragma unroll
        for (int i = 0; i < 4; i++) {
            int id = t + i * 256, r = id >> 3, c = id & 7;
            ra[i] = *(const float4*)&At[(size_t)r * CC + k0 + c * 4];
            rb[i] = *(const float4*)&B[(size_t)r * CC + k0 + c * 4];
        }
    };
    auto sts = [&](int s) {
        float* AsH = sm + s * STG;
        float* AsL = AsH + ASZ;
        float* BsH = AsL + ASZ;
        float* BsL = BsH + BSZ;
        auto split4 = [](float4 v, float* dh, float* dl) {
            float h;
            h = f2tf(v.x); dh[0] = h; dl[0] = f2tf(v.x - h);
            h = f2tf(v.y); dh[1] = h; dl[1] = f2tf(v.y - h);
            h = f2tf(v.z); dh[2] = h; dl[2] = f2tf(v.z - h);
            h = f2tf(v.w); dh[3] = h; dl[3] = f2tf(v.w - h);
        };
#pragma unroll
        for (int i = 0; i < 4; i++) {
            int id = t + i * 256, r = id >> 3, c = id & 7;
            split4(ra[i], &AsH[r * 36 + c * 4], &AsL[r * 36 + c * 4]);
            split4(rb[i], &BsH[r * 36 + c * 4], &BsL[r * 36 + c * 4]);
        }
    };

    ldg(0);
    sts(0);
    __syncthreads();

    const int KB = CC / 32;
    for (int kb = 0; kb < KB; kb++) {
        const int p = kb & 1;
        if (kb + 1 < KB) ldg((kb + 1) * 32);
        float* AsH = sm + p * STG;
        float* AsL = AsH + ASZ;
        float* BsH = AsL + ASZ;
        float* BsL = BsH + BSZ;
#pragma unroll
        for (int ks = 0; ks < 4; ks++) {
            wmma::fragment<wmma::matrix_a, 16, 16, 8, wmma::precision::tf32,
                           wmma::row_major> faH[4], faL[4];
            wmma::fragment<wmma::matrix_b, 16, 16, 8, wmma::precision::tf32,
                           wmma::col_major> fbH[2], fbL[2];
#pragma unroll
            for (int i = 0; i < 4; i++) {
                int off = (warp_m * 64 + i * 16) * 36 + ks * 8;
                wmma::load_matrix_sync(faH[i], AsH + off, 36);
                wmma::load_matrix_sync(faL[i], AsL + off, 36);
            }
#pragma unroll
            for (int j = 0; j < 2; j++) {
                int off = (warp_n * 32 + j * 16) * 36 + ks * 8;
                wmma::load_matrix_sync(fbH[j], BsH + off, 36);
                wmma::load_matrix_sync(fbL[j], BsL + off, 36);
            }
#pragma unroll
            for (int i = 0; i < 4; i++)
#pragma unroll
                for (int j = 0; j < 2; j++) {
                    wmma::mma_sync(acc[i][j], faH[i], fbL[j], acc[i][j]);
                    wmma::mma_sync(acc[i][j], faL[i], fbH[j], acc[i][j]);
                    wmma::mma_sync(acc[i][j], faH[i], fbH[j], acc[i][j]);
                }
        }
        if (kb + 1 < KB) sts(p ^ 1);
        __syncthreads();
    }

    float* Cs = sm;
#pragma unroll
    for (int i = 0; i < 4; i++)
#pragma unroll
        for (int j = 0; j < 2; j++)
            wmma::store_matrix_sync(
                Cs + (warp_m * 64 + i * 16) * 132 + warp_n * 32 + j * 16,
                acc[i][j], 132, wmma::mem_row_major);
    __syncthreads();
    for (int e = t; e < 128 * 32; e += 256) {
        int r = e >> 5, c4 = e & 31;
        float4 v = *(float4*)&Cs[r * 132 + c4 * 4];
        float4 h, l;
        h.x = f2tf(v.x); l.x = f2tf(v.x - h.x);
        h.y = f2tf(v.y); l.y = f2tf(v.y - h.y);
        h.z = f2tf(v.z); l.z = f2tf(v.z - h.z);
        h.w = f2tf(v.w); l.w = f2tf(v.w - h.w);
        size_t idx = (size_t)(by * 128 + r) * 128 + c4 * 4;
        *(float4*)&CH[idx] = h;
        *(float4*)&CL[idx] = l;
    }
}

// ---------------- cp.async wmma GEMM engine, 256 threads --------------------
// D 128xTN, 8 warps 2x4, warp 64x(TN/4). Inputs tf32-exact in gmem.
// SPLIT: acc += AH*BL + AL*BH + AH*BH.
// EPI 1: transposed vT store (rounded)
// EPI 4: P = tf32(exp(acc - ESHIFT)) store + per-row partial sums -> C2
// EPI 5: C = gamma*acc*linv + x   (linv passed via C2)
template <int TN, int EPI, bool SPLIT>
__global__ __launch_bounds__(256) void gemm_async(
    const float* __restrict__ AH, const float* __restrict__ AL,
    const float* __restrict__ BH, const float* __restrict__ BL,
    float* __restrict__ C, float* __restrict__ C2, int K, int ldA, int ldB,
    int ldC, size_t sA, size_t sB, size_t sC, const float* __restrict__ xres,
    const float* __restrict__ gamma) {
    extern __shared__ float sm[];
    constexpr int ASZ = 128 * 36, BSZ = TN * 36;
    constexpr int CMP = SPLIT ? 2 : 1;
    constexpr int STG = CMP * (ASZ + BSZ);
    constexpr int NT = TN / 64;
    constexpr int NB = TN / 32;

    const int t = threadIdx.x, wid = t >> 5;
    const int warp_m = wid >> 2, warp_n = wid & 3;
    const int bx = blockIdx.x, by = blockIdx.y, bz = blockIdx.z;
    const uint32_t smb = smem_u32(sm);

    const float* AtH = AH + bz * sA + (size_t)(by * 128) * ldA;
    const float* BtH = BH + bz * sB + (size_t)(bx * TN) * ldB;
    const float* AtL = SPLIT ? AL + bz * sA + (size_t)(by * 128) * ldA : nullptr;
    const float* BtL = SPLIT ? BL + bz * sB + (size_t)(bx * TN) * ldB : nullptr;

    wmma::fragment<wmma::accumulator, 16, 16, 8, float> acc[4][NT];
#pragma unroll
    for (int i = 0; i < 4; i++)
#pragma unroll
        for (int j = 0; j < NT; j++) wmma::fill_fragment(acc[i][j], 0.f);

    auto issue = [&](int s, int k0) {
        uint32_t ab = smb + s * STG * 4;
        uint32_t bb = ab + CMP * ASZ * 4;
#pragma unroll
        for (int i = 0; i < 4; i++) {
            int id = t + i * 256, r = id >> 3, c = id & 7;
            uint32_t so = (r * 36 + c * 4) * 4;
            cp16(ab + so, AtH + (size_t)r * ldA + k0 + c * 4);
            if (SPLIT)
                cp16(ab + ASZ * 4 + so, AtL + (size_t)r * ldA + k0 + c * 4);
        }
#pragma unroll
        for (int i = 0; i < NB; i++) {
            int id = t + i * 256, r = id >> 3, c = id & 7;
            uint32_t so = (r * 36 + c * 4) * 4;
            cp16(bb + so, BtH + (size_t)r * ldB + k0 + c * 4);
            if (SPLIT)
                cp16(bb + BSZ * 4 + so, BtL + (size_t)r * ldB + k0 + c * 4);
        }
    };

    issue(0, 0);
    CP_COMMIT();
    CP_WAIT0();
    __syncthreads();

    const int KB = K / 32;
    for (int kb = 0; kb < KB; kb++) {
        const int p = kb & 1;
        if (kb + 1 < KB) {
            issue(p ^ 1, (kb + 1) * 32);
            CP_COMMIT();
        }
        float* AsH = sm + p * STG;
        float* AsL = AsH + ASZ;
        float* BsH = AsH + CMP * ASZ;
        float* BsL = BsH + BSZ;
#pragma unroll
        for (int ks = 0; ks < 4; ks++) {
            if (SPLIT) {
                wmma::fragment<wmma::matrix_a, 16, 16, 8,
                               wmma::precision::tf32, wmma::row_major>
                    faH[4], faL[4];
                wmma::fragment<wmma::matrix_b, 16, 16, 8,
                               wmma::precision::tf32, wmma::col_major>
                    fbH[NT], fbL[NT];
#pragma unroll
                for (int i = 0; i < 4; i++) {
                    int off = (warp_m * 64 + i * 16) * 36 + ks * 8;
                    wmma::load_matrix_sync(faH[i], AsH + off, 36);
                    wmma::load_matrix_sync(faL[i], AsL + off, 36);
                }
#pragma unroll
                for (int j = 0; j < NT; j++) {
                    int off = (warp_n * (TN / 4) + j * 16) * 36 + ks * 8;
                    wmma::load_matrix_sync(fbH[j], BsH + off, 36);
                    wmma::load_matrix_sync(fbL[j], BsL + off, 36);
                }
#pragma unroll
                for (int i = 0; i < 4; i++)
#pragma unroll
                    for (int j = 0; j < NT; j++) {
                        wmma::mma_sync(acc[i][j], faH[i], fbL[j], acc[i][j]);
                        wmma::mma_sync(acc[i][j], faL[i], fbH[j], acc[i][j]);
                        wmma::mma_sync(acc[i][j], faH[i], fbH[j], acc[i][j]);
                    }
            } else {
                wmma::fragment<wmma::matrix_a, 16, 16, 8,
                               wmma::precision::tf32, wmma::row_major> fa[4];
                wmma::fragment<wmma::matrix_b, 16, 16, 8,
                               wmma::precision::tf32, wmma::col_major> fb[NT];
#pragma unroll
                for (int i = 0; i < 4; i++)
                    wmma::load_matrix_sync(
                        fa[i], AsH + (warp_m * 64 + i * 16) * 36 + ks * 8, 36);
#pragma unroll
                for (int j = 0; j < NT; j++)
                    wmma::load_matrix_sync(
                        fb[j], BsH + (warp_n * (TN / 4) + j * 16) * 36 + ks * 8,
                        36);
#pragma unroll
                for (int i = 0; i < 4; i++)
#pragma unroll
                    for (int j = 0; j < NT; j++)
                        wmma::mma_sync(acc[i][j], fa[i], fb[j], acc[i][j]);
            }
        }
        if (kb + 1 < KB) CP_WAIT0();
        __syncthreads();
    }

    // ---------------- epilogue ----------------------------------------------
    float* Cs = sm;
    constexpr int LDCS = TN + 4;
#pragma unroll
    for (int i = 0; i < 4; i++)
#pragma unroll
        for (int j = 0; j < NT; j++)
            wmma::store_matrix_sync(
                Cs + (warp_m * 64 + i * 16) * LDCS + warp_n * (TN / 4) + j * 16,
                acc[i][j], LDCS, wmma::mem_row_major);
    __syncthreads();

    if (EPI == 1) {
        const int tok0 = by * 128;
        const int bglob = tok0 >> 12;
        const int tokin0 = tok0 & (NTOK - 1);
        for (int e = t; e < TN * 32; e += 256) {
            int j = e >> 5, tq = e & 31;
            float4 o;
            o.x = f2tf(Cs[(tq * 4 + 0) * LDCS + j]);
            o.y = f2tf(Cs[(tq * 4 + 1) * LDCS + j]);
            o.z = f2tf(Cs[(tq * 4 + 2) * LDCS + j]);
            o.w = f2tf(Cs[(tq * 4 + 3) * LDCS + j]);
            *(float4*)&C[((size_t)bglob * CC + bx * TN + j) * NTOK + tokin0 +
                         tq * 4] = o;
        }
    } else if (EPI == 4) {
        // P store + per-row partial sums. TN=128: warp w handles row w+8*it.
        const int lane = t & 31;
#pragma unroll 4
        for (int it = 0; it < 16; it++) {
            int e = t + it * 256;
            int r = e >> 5, c4 = e & 31;
            float4 v = *(float4*)&Cs[r * LDCS + c4 * 4];
            float4 p;
            p.x = __expf(v.x - ESHIFT);
            p.y = __expf(v.y - ESHIFT);
            p.z = __expf(v.z - ESHIFT);
            p.w = __expf(v.w - ESHIFT);
            float s4 = p.x + p.y + p.z + p.w;
            p.x = f2tf(p.x); p.y = f2tf(p.y);
            p.z = f2tf(p.z); p.w = f2tf(p.w);
            size_t base =
                bz * sC + (size_t)(by * 128 + r) * ldC + bx * TN + c4 * 4;
            *(float4*)&C[base] = p;
#pragma unroll
            for (int o = 16; o; o >>= 1)
                s4 += __shfl_xor_sync(~0u, s4, o);
            if (lane == 0)
                C2[((size_t)bz * 32 + bx) * NTOK + by * 128 + r] = s4;
        }
    } else {
        const float g = gamma[0];
        for (int e = t; e < 128 * (TN / 4); e += 256) {
            int r = e / (TN / 4), c4 = e % (TN / 4);
            float4 o = *(float4*)&Cs[r * LDCS + c4 * 4];
            size_t base =
                bz * sC + (size_t)(by * 128 + r) * ldC + bx * TN + c4 * 4;
            float gl = g * C2[bz * NTOK + by * 128 + r];
            float4 xr = *(const float4*)&xres[base];
            o.x = gl * o.x + xr.x;
            o.y = gl * o.y + xr.y;
            o.z = gl * o.z + xr.z;
            o.w = gl * o.w + xr.w;
            *(float4*)&C[base] = o;
        }
    }
}

// ---------------------------------------------------------------------------
static inline int smem_async(int TN, bool split) {
    int stage = (split ? 2 : 1) * (128 + TN) * 36 * 4;
    int buf = 2 * stage;
    int cs = 128 * (TN + 4) * 4;
    return buf > cs ? buf : cs;
}

extern "C" void kernel_launch(void* const* d_in, const int* in_sizes, int n_in,
                              void* d_out, int out_size) {
    const float* x = (const float*)d_in[0];
    const float* Wb = (const float*)d_in[1];
    const float* Wc = (const float*)d_in[2];
    const float* Wd = (const float*)d_in[3];
    const float* gamma = (const float*)d_in[4];
    float* out = (float*)d_out;

    float *qkH, *qkL, *xrp, *vTp, *Sp, *lpart, *linv, *WqkT, *WdT;
    cudaGetSymbolAddress((void**)&qkH, g_qkH);
    cudaGetSymbolAddress((void**)&qkL, g_qkL);
    cudaGetSymbolAddress((void**)&xrp, g_xr);
    cudaGetSymbolAddress((void**)&vTp, g_vT);
    cudaGetSymbolAddress((void**)&Sp, g_S);
    cudaGetSymbolAddress((void**)&lpart, g_lpart);
    cudaGetSymbolAddress((void**)&linv, g_linv);
    cudaGetSymbolAddress((void**)&WqkT, g_WqkT);
    cudaGetSymbolAddress((void**)&WdT, g_WdT);

    const int smem_qk = 2 * 2 * (128 + 128) * 36 * 4;
    cudaFuncSetAttribute(gemm_qk, cudaFuncAttributeMaxDynamicSharedMemorySize,
                         smem_qk);
    cudaFuncSetAttribute(gemm_async<128, 4, true>,
                         cudaFuncAttributeMaxDynamicSharedMemorySize,
                         smem_async(128, true));
    cudaFuncSetAttribute(gemm_async<256, 1, false>,
                         cudaFuncAttributeMaxDynamicSharedMemorySize,
                         smem_async(256, false));
    cudaFuncSetAttribute(gemm_async<256, 5, false>,
                         cudaFuncAttributeMaxDynamicSharedMemorySize,
                         smem_async(256, false));

    // producers
    round_x<<<(BNTOT * CC / 4 + 255) / 256, 256>>>((const float4*)x,
                                                   (float4*)xrp,
                                                   BNTOT * CC / 4);
    transpose_wqk<<<(128 * CC + 255) / 256, 256>>>(Wb, Wc, WqkT);
    transpose_w_round<<<(CC * CC + 255) / 256, 256>>>(Wd, WdT, CC, CC);

    // qk = X @ [Wb|Wc], split hi/lo outputs
    gemm_qk<<<dim3(1, BNTOT / 128), 256, smem_qk>>>(x, WqkT, qkH, qkL);
    // vT: v = X @ Wd transposed+rounded store (plain)
    gemm_async<256, 1, false><<<dim3(CC / 256, BNTOT / 128, 1), 256,
                                smem_async(256, false)>>>(
        xrp, nullptr, WdT, nullptr, vTp, nullptr, CC, CC, CC, 0, 0, 0, 0,
        nullptr, nullptr);
    // P_raw = exp(q k^T - 40), tf32-rounded, + row partial sums
    gemm_async<128, 4, true><<<dim3(NTOK / 128, NTOK / 128, B_), 256,
                               smem_async(128, true)>>>(
        qkH, qkL, qkH + CRD, qkL + CRD, Sp, lpart, CRD, 128, 128, NTOK,
        (size_t)NTOK * 128, (size_t)NTOK * 128, (size_t)NTOK * NTOK, nullptr,
        nullptr);
    // linv = 1 / rowsum
    reduce_l<<<(B_ * NTOK + 255) / 256, 256>>>(lpart, linv);
    // out = gamma * (P_raw @ v) * linv + x (plain)
    gemm_async<256, 5, false><<<dim3(CC / 256, NTOK / 128, B_), 256,
                                smem_async(256, false)>>>(
        Sp, nullptr, vTp, nullptr, out, linv, NTOK, NTOK, NTOK, CC,
        (size_t)NTOK * NTOK, (size_t)CC * NTOK, (size_t)NTOK * CC, x, gamma);
}

// round 11
// speedup vs baseline: 2.3789x; 2.0932x over previous
#include <cuda_runtime.h>
#include <cuda_fp16.h>
#include <mma.h>
#include <cstdint>

using namespace nvcuda;

// ---------------------------------------------------------------------------
// PAM, wmma fp16 (2x HMMA rate vs tf32) + selective 2-term splits (~22 bits).
//   qk GEMM: fp16-split -> qkH/qkL (fp16 pairs)
//   v GEMM:  tf32 plain -> vT fp16
//   S GEMM:  fp16-split, epilogue exp(s-40) -> P fp32 + row sum/max partials
//   reduce:  pscale = 2^k (row max -> 2^14), oscale = 1/(sum*pscale)
//   convert: P16 = fp16(P * pscale)     (exact pow2 scaling, cancels later)
//   PV GEMM: fp16 plain, out = gamma*acc*oscale + x
// ---------------------------------------------------------------------------

#define B_    4
#define NTOK  4096
#define CC    512
#define CRD   64
#define BNTOT (B_ * NTOK)
#define ESHIFT 40.0f

__device__ __half g_qkH[(size_t)BNTOT * 128];
__device__ __half g_qkL[(size_t)BNTOT * 128];
__device__ float  g_xr[(size_t)BNTOT * CC];        // tf32-rounded x (v GEMM)
__device__ __half g_vT[(size_t)B_ * CC * NTOK];    // [b][c][tok] fp16
__device__ float  g_S[(size_t)B_ * NTOK * NTOK];   // raw exp probs fp32
__device__ __half g_P16[(size_t)B_ * NTOK * NTOK]; // scaled fp16 probs
__device__ float  g_lpart[(size_t)B_ * 32 * NTOK];
__device__ float  g_mpart[(size_t)B_ * 32 * NTOK];
__device__ float  g_pscale[B_ * NTOK];
__device__ float  g_oscale[B_ * NTOK];
__device__ float  g_WqkT[128 * CC];                // raw
__device__ float  g_WdT[CC * CC];                  // tf32-rounded

__device__ __forceinline__ float f2tf(float f) {
    uint32_t u;
    asm("cvt.rna.tf32.f32 %0, %1;" : "=r"(u) : "f"(f));
    return __uint_as_float(u);
}
__device__ __forceinline__ uint32_t smem_u32(const void* p) {
    uint32_t a;
    asm("{ .reg .u64 t; cvta.to.shared.u64 t, %1; cvt.u32.u64 %0, t; }"
        : "=r"(a) : "l"(p));
    return a;
}
__device__ __forceinline__ void cp16(uint32_t saddr, const void* g) {
    asm volatile("cp.async.cg.shared.global [%0], [%1], 16;" ::"r"(saddr),
                 "l"(g));
}
#define CP_COMMIT() asm volatile("cp.async.commit_group;" ::: "memory")
#define CP_WAIT0()  asm volatile("cp.async.wait_group 0;" ::: "memory")

// ---------------- producers --------------------------------------------------
__global__ void round_x(const float4* __restrict__ in, float4* __restrict__ o,
                        int n4) {
    int i = blockIdx.x * 256 + threadIdx.x;
    if (i < n4) {
        float4 v = in[i];
        v.x = f2tf(v.x); v.y = f2tf(v.y); v.z = f2tf(v.z); v.w = f2tf(v.w);
        o[i] = v;
    }
}
__global__ void transpose_w_round(const float* __restrict__ W,
                                  float* __restrict__ WT, int K, int N) {
    int i = blockIdx.x * 256 + threadIdx.x;
    if (i < K * N) {
        int n = i / K, k = i - n * K;
        WT[i] = f2tf(W[(size_t)k * N + n]);
    }
}
__global__ void transpose_wqk(const float* __restrict__ Wb,
                              const float* __restrict__ Wc,
                              float* __restrict__ WT) {
    int i = blockIdx.x * 256 + threadIdx.x;
    if (i < 128 * CC) {
        int n = i / CC, k = i - n * CC;
        WT[i] = (n < CRD) ? Wb[(size_t)k * CRD + n]
                          : Wc[(size_t)k * CRD + (n - CRD)];
    }
}
__global__ void reduce2(const float* __restrict__ sp,
                        const float* __restrict__ mp,
                        float* __restrict__ pscale,
                        float* __restrict__ oscale) {
    int i = blockIdx.x * 256 + threadIdx.x;
    if (i < B_ * NTOK) {
        int b = i >> 12, row = i & (NTOK - 1);
        float s = 0.f, m = 0.f;
#pragma unroll
        for (int j = 0; j < 32; j++) {
            s += sp[((size_t)b * 32 + j) * NTOK + row];
            m = fmaxf(m, mp[((size_t)b * 32 + j) * NTOK + row]);
        }
        float ps = ldexpf(1.f, 14 - ilogbf(m));
        pscale[i] = ps;
        oscale[i] = 1.f / (s * ps);
    }
}
// P16 = fp16(P * pscale[row]); grid (NTOK/1024, B_*NTOK)
__global__ __launch_bounds__(256) void convert_P(const float* __restrict__ P,
                                                 const float* __restrict__ ps,
                                                 __half* __restrict__ P16) {
    int row = blockIdx.y;
    int cx = blockIdx.x * 1024 + threadIdx.x * 4;
    float s = ps[row];
    size_t base = (size_t)row * NTOK + cx;
    float4 v = *(const float4*)&P[base];
    __half2* o = (__half2*)&P16[base];
    o[0] = __floats2half2_rn(v.x * s, v.y * s);
    o[1] = __floats2half2_rn(v.z * s, v.w * s);
}

// ---------------- qk GEMM: register-staged fp16 split ------------------------
// D 128x128 fp32, A=x [M,512], B=WqkT [128,512] (both fp32, split to fp16 H/L
// at STS). Outputs qkH/qkL fp16 pairs. wmma 16x16x16, warp tile 64x32.
__global__ __launch_bounds__(256) void gemm_qk_h(const float* __restrict__ A,
                                                 const float* __restrict__ B,
                                                 __half* __restrict__ CH,
                                                 __half* __restrict__ CL) {
    extern __shared__ char smraw[];
    __half* sm = (__half*)smraw;
    constexpr int ASZ = 128 * 40, BSZ = 128 * 40;  // halfs per component
    constexpr int STG = 2 * (ASZ + BSZ);           // halfs per stage
    const int t = threadIdx.x, wid = t >> 5;
    const int warp_m = wid >> 2, warp_n = wid & 3;
    const int by = blockIdx.y;
    const float* At = A + (size_t)(by * 128) * CC;

    wmma::fragment<wmma::accumulator, 16, 16, 16, float> acc[4][2];
#pragma unroll
    for (int i = 0; i < 4; i++)
#pragma unroll
        for (int j = 0; j < 2; j++) wmma::fill_fragment(acc[i][j], 0.f);

    float4 ra[4], rb[4];
    auto ldg = [&](int k0) {
#pragma unroll
        for (int i = 0; i < 4; i++) {
            int id = t + i * 256, r = id >> 3, c = id & 7;
            ra[i] = *(const float4*)&At[(size_t)r * CC + k0 + c * 4];
            rb[i] = *(const float4*)&B[(size_t)r * CC + k0 + c * 4];
        }
    };
    auto sts = [&](int s) {
        __half* AsH = sm + s * STG;
        __half* AsL = AsH + ASZ;
        __half* BsH = AsL + ASZ;
        __half* BsL = BsH + BSZ;
        auto split4 = [](float4 v, __half* dh, __half* dl) {
            __half h;
            h = __float2half_rn(v.x); dh[0] = h;
            dl[0] = __float2half_rn(v.x - __half2float(h));
            h = __float2half_rn(v.y); dh[1] = h;
            dl[1] = __float2half_rn(v.y - __half2float(h));
            h = __float2half_rn(v.z); dh[2] = h;
            dl[2] = __float2half_rn(v.z - __half2float(h));
            h = __float2half_rn(v.w); dh[3] = h;
            dl[3] = __float2half_rn(v.w - __half2float(h));
        };
#pragma unroll
        for (int i = 0; i < 4; i++) {
            int id = t + i * 256, r = id >> 3, c = id & 7;
            split4(ra[i], &AsH[r * 40 + c * 4], &AsL[r * 40 + c * 4]);
            split4(rb[i], &BsH[r * 40 + c * 4], &BsL[r * 40 + c * 4]);
        }
    };

    ldg(0);
    sts(0);
    __syncthreads();

    const int KB = CC / 32;
    for (int kb = 0; kb < KB; kb++) {
        const int p = kb & 1;
        if (kb + 1 < KB) ldg((kb + 1) * 32);
        __half* AsH = sm + p * STG;
        __half* AsL = AsH + ASZ;
        __half* BsH = AsL + ASZ;
        __half* BsL = BsH + BSZ;
#pragma unroll
        for (int ks = 0; ks < 2; ks++) {
            wmma::fragment<wmma::matrix_a, 16, 16, 16, __half,
                           wmma::row_major> faH[4], faL[4];
            wmma::fragment<wmma::matrix_b, 16, 16, 16, __half,
                           wmma::col_major> fbH[2], fbL[2];
#pragma unroll
            for (int i = 0; i < 4; i++) {
                int off = (warp_m * 64 + i * 16) * 40 + ks * 16;
                wmma::load_matrix_sync(faH[i], AsH + off, 40);
                wmma::load_matrix_sync(faL[i], AsL + off, 40);
            }
#pragma unroll
            for (int j = 0; j < 2; j++) {
                int off = (warp_n * 32 + j * 16) * 40 + ks * 16;
                wmma::load_matrix_sync(fbH[j], BsH + off, 40);
                wmma::load_matrix_sync(fbL[j], BsL + off, 40);
            }
#pragma unroll
            for (int i = 0; i < 4; i++)
#pragma unroll
                for (int j = 0; j < 2; j++) {
                    wmma::mma_sync(acc[i][j], faH[i], fbL[j], acc[i][j]);
                    wmma::mma_sync(acc[i][j], faL[i], fbH[j], acc[i][j]);
                    wmma::mma_sync(acc[i][j], faH[i], fbH[j], acc[i][j]);
                }
        }
        if (kb + 1 < KB) sts(p ^ 1);
        __syncthreads();
    }

    float* Cs = (float*)smraw;
#pragma unroll
    for (int i = 0; i < 4; i++)
#pragma unroll
        for (int j = 0; j < 2; j++)
            wmma::store_matrix_sync(
                Cs + (warp_m * 64 + i * 16) * 132 + warp_n * 32 + j * 16,
                acc[i][j], 132, wmma::mem_row_major);
    __syncthreads();
    for (int e = t; e < 128 * 32; e += 256) {
        int r = e >> 5, c4 = e & 31;
        float4 v = *(float4*)&Cs[r * 132 + c4 * 4];
        size_t idx = (size_t)(by * 128 + r) * 128 + c4 * 4;
        float vv[4] = {v.x, v.y, v.z, v.w};
#pragma unroll
        for (int q = 0; q < 4; q++) {
            __half h = __float2half_rn(vv[q]);
            CH[idx + q] = h;
            CL[idx + q] = __float2half_rn(vv[q] - __half2float(h));
        }
    }
}

// ---------------- cp.async wmma fp16 GEMM engine ----------------------------
// D 128xTN fp32 acc, 8 warps 2x4, warp 64x(TN/4). K-chunk 32 halfs, 2 stages.
// SPLIT: acc += AH*BL + AL*BH + AH*BH.
// EPI 4: P = exp(acc-ESHIFT) fp32 store + row sum/max partials (TN=128 only)
// EPI 6: C = gamma*acc*oscale[row] + x
template <int TN, int EPI, bool SPLIT>
__global__ __launch_bounds__(256) void gemm_h(
    const __half* __restrict__ AH, const __half* __restrict__ AL,
    const __half* __restrict__ BH, const __half* __restrict__ BL,
    float* __restrict__ C, float* __restrict__ sump, float* __restrict__ maxp,
    const float* __restrict__ oscale, const float* __restrict__ xres,
    const float* __restrict__ gamma, int K, int ldA, int ldB, int ldC,
    size_t sA, size_t sB, size_t sC) {
    extern __shared__ char smraw[];
    __half* sm = (__half*)smraw;
    constexpr int ASZ = 128 * 40, BSZ = TN * 40;  // halfs
    constexpr int CMP = SPLIT ? 2 : 1;
    constexpr int STG = CMP * (ASZ + BSZ);        // halfs per stage
    constexpr int NT = TN / 64;
    constexpr int NBL = TN / 64;                  // B cp16 per thread

    const int t = threadIdx.x, wid = t >> 5;
    const int warp_m = wid >> 2, warp_n = wid & 3;
    const int bx = blockIdx.x, by = blockIdx.y, bz = blockIdx.z;
    const uint32_t smb = smem_u32(smraw);

    const __half* AtH = AH + bz * sA + (size_t)(by * 128) * ldA;
    const __half* BtH = BH + bz * sB + (size_t)(bx * TN) * ldB;
    const __half* AtL = SPLIT ? AL + bz * sA + (size_t)(by * 128) * ldA : nullptr;
    const __half* BtL = SPLIT ? BL + bz * sB + (size_t)(bx * TN) * ldB : nullptr;

    wmma::fragment<wmma::accumulator, 16, 16, 16, float> acc[4][NT];
#pragma unroll
    for (int i = 0; i < 4; i++)
#pragma unroll
        for (int j = 0; j < NT; j++) wmma::fill_fragment(acc[i][j], 0.f);

    auto issue = [&](int s, int k0) {
        uint32_t ab = smb + s * STG * 2;
        uint32_t bb = ab + CMP * ASZ * 2;
#pragma unroll
        for (int i = 0; i < 2; i++) {
            int id = t + i * 256, r = id >> 2, c = id & 3;
            uint32_t so = (r * 40 + c * 8) * 2;
            cp16(ab + so, AtH + (size_t)r * ldA + k0 + c * 8);
            if (SPLIT)
                cp16(ab + ASZ * 2 + so, AtL + (size_t)r * ldA + k0 + c * 8);
        }
#pragma unroll
        for (int i = 0; i < NBL; i++) {
            int id = t + i * 256, r = id >> 2, c = id & 3;
            uint32_t so = (r * 40 + c * 8) * 2;
            cp16(bb + so, BtH + (size_t)r * ldB + k0 + c * 8);
            if (SPLIT)
                cp16(bb + BSZ * 2 + so, BtL + (size_t)r * ldB + k0 + c * 8);
        }
    };

    issue(0, 0);
    CP_COMMIT();
    CP_WAIT0();
    __syncthreads();

    const int KB = K / 32;
    for (int kb = 0; kb < KB; kb++) {
        const int p = kb & 1;
        if (kb + 1 < KB) {
            issue(p ^ 1, (kb + 1) * 32);
            CP_COMMIT();
        }
        __half* AsH = sm + p * STG;
        __half* AsL = AsH + ASZ;
        __half* BsH = AsH + CMP * ASZ;
        __half* BsL = BsH + BSZ;
#pragma unroll
        for (int ks = 0; ks < 2; ks++) {
            if (SPLIT) {
                wmma::fragment<wmma::matrix_a, 16, 16, 16, __half,
                               wmma::row_major> faH[4], faL[4];
                wmma::fragment<wmma::matrix_b, 16, 16, 16, __half,
                               wmma::col_major> fbH[NT], fbL[NT];
#pragma unroll
                for (int i = 0; i < 4; i++) {
                    int off = (warp_m * 64 + i * 16) * 40 + ks * 16;
                    wmma::load_matrix_sync(faH[i], AsH + off, 40);
                    wmma::load_matrix_sync(faL[i], AsL + off, 40);
                }
#pragma unroll
                for (int j = 0; j < NT; j++) {
                    int off = (warp_n * (TN / 4) + j * 16) * 40 + ks * 16;
                    wmma::load_matrix_sync(fbH[j], BsH + off, 40);
                    wmma::load_matrix_sync(fbL[j], BsL + off, 40);
                }
#pragma unroll
                for (int i = 0; i < 4; i++)
#pragma unroll
                    for (int j = 0; j < NT; j++) {
                        wmma::mma_sync(acc[i][j], faH[i], fbL[j], acc[i][j]);
                        wmma::mma_sync(acc[i][j], faL[i], fbH[j], acc[i][j]);
                        wmma::mma_sync(acc[i][j], faH[i], fbH[j], acc[i][j]);
                    }
            } else {
                wmma::fragment<wmma::matrix_a, 16, 16, 16, __half,
                               wmma::row_major> fa[4];
#pragma unroll
                for (int i = 0; i < 4; i++)
                    wmma::load_matrix_sync(
                        fa[i], AsH + (warp_m * 64 + i * 16) * 40 + ks * 16, 40);
#pragma unroll
                for (int j = 0; j < NT; j++) {
                    wmma::fragment<wmma::matrix_b, 16, 16, 16, __half,
                                   wmma::col_major> fb;
                    wmma::load_matrix_sync(
                        fb, BsH + (warp_n * (TN / 4) + j * 16) * 40 + ks * 16,
                        40);
#pragma unroll
                    for (int i = 0; i < 4; i++)
                        wmma::mma_sync(acc[i][j], fa[i], fb, acc[i][j]);
                }
            }
        }
        if (kb + 1 < KB) CP_WAIT0();
        __syncthreads();
    }

    // ---------------- epilogue ----------------------------------------------
    float* Cs = (float*)smraw;
    constexpr int LDCS = TN + 4;
#pragma unroll
    for (int i = 0; i < 4; i++)
#pragma unroll
        for (int j = 0; j < NT; j++)
            wmma::store_matrix_sync(
                Cs + (warp_m * 64 + i * 16) * LDCS + warp_n * (TN / 4) + j * 16,
                acc[i][j], LDCS, wmma::mem_row_major);
    __syncthreads();

    if (EPI == 4) {
        const int lane = t & 31;
#pragma unroll 4
        for (int it = 0; it < 16; it++) {
            int e = t + it * 256;
            int r = e >> 5, c4 = e & 31;
            float4 v = *(float4*)&Cs[r * LDCS + c4 * 4];
            float4 p;
            p.x = __expf(v.x - ESHIFT);
            p.y = __expf(v.y - ESHIFT);
            p.z = __expf(v.z - ESHIFT);
            p.w = __expf(v.w - ESHIFT);
            float s4 = p.x + p.y + p.z + p.w;
            float m4 = fmaxf(fmaxf(p.x, p.y), fmaxf(p.z, p.w));
            size_t base =
                bz * sC + (size_t)(by * 128 + r) * ldC + bx * TN + c4 * 4;
            *(float4*)&C[base] = p;
#pragma unroll
            for (int o = 16; o; o >>= 1) {
                s4 += __shfl_xor_sync(~0u, s4, o);
                m4 = fmaxf(m4, __shfl_xor_sync(~0u, m4, o));
            }
            if (lane == 0) {
                size_t pi = ((size_t)bz * 32 + bx) * NTOK + by * 128 + r;
                sump[pi] = s4;
                maxp[pi] = m4;
            }
        }
    } else {
        const float g = gamma[0];
        for (int e = t; e < 128 * (TN / 4); e += 256) {
            int r = e / (TN / 4), c4 = e % (TN / 4);
            float4 o = *(float4*)&Cs[r * LDCS + c4 * 4];
            size_t base =
                bz * sC + (size_t)(by * 128 + r) * ldC + bx * TN + c4 * 4;
            float gl = g * oscale[bz * NTOK + by * 128 + r];
            float4 xr = *(const float4*)&xres[base];
            o.x = gl * o.x + xr.x;
            o.y = gl * o.y + xr.y;
            o.z = gl * o.z + xr.z;
            o.w = gl * o.w + xr.w;
            *(float4*)&C[base] = o;
        }
    }
}

// ---------------- v GEMM: tf32 plain cp.async, fp16 transposed store --------
__global__ __launch_bounds__(256) void gemm_v(const float* __restrict__ A,
                                              const float* __restrict__ B,
                                              __half* __restrict__ C) {
    extern __shared__ float sm[];
    constexpr int TN = 256;
    constexpr int ASZ = 128 * 36, BSZ = TN * 36;
    constexpr int STG = ASZ + BSZ;
    constexpr int NT = TN / 64, NB = TN / 32;

    const int t = threadIdx.x, wid = t >> 5;
    const int warp_m = wid >> 2, warp_n = wid & 3;
    const int bx = blockIdx.x, by = blockIdx.y;
    const uint32_t smb = smem_u32(sm);

    const float* At = A + (size_t)(by * 128) * CC;
    const float* Bt = B + (size_t)(bx * TN) * CC;

    wmma::fragment<wmma::accumulator, 16, 16, 8, float> acc[4][NT];
#pragma unroll
    for (int i = 0; i < 4; i++)
#pragma unroll
        for (int j = 0; j < NT; j++) wmma::fill_fragment(acc[i][j], 0.f);

    auto issue = [&](int s, int k0) {
        uint32_t ab = smb + s * STG * 4;
        uint32_t bb = ab + ASZ * 4;
#pragma unroll
        for (int i = 0; i < 4; i++) {
            int id = t + i * 256, r = id >> 3, c = id & 7;
            cp16(ab + (r * 36 + c * 4) * 4, At + (size_t)r * CC + k0 + c * 4);
        }
#pragma unroll
        for (int i = 0; i < NB; i++) {
            int id = t + i * 256, r = id >> 3, c = id & 7;
            cp16(bb + (r * 36 + c * 4) * 4, Bt + (size_t)r * CC + k0 + c * 4);
        }
    };

    issue(0, 0);
    CP_COMMIT();
    CP_WAIT0();
    __syncthreads();

    const int KB = CC / 32;
    for (int kb = 0; kb < KB; kb++) {
        const int p = kb & 1;
        if (kb + 1 < KB) {
            issue(p ^ 1, (kb + 1) * 32);
            CP_COMMIT();
        }
        float* As = sm + p * STG;
        float* Bs = As + ASZ;
#pragma unroll
        for (int ks = 0; ks < 4; ks++) {
            wmma::fragment<wmma::matrix_a, 16, 16, 8, wmma::precision::tf32,
                           wmma::row_major> fa[4];
#pragma unroll
            for (int i = 0; i < 4; i++)
                wmma::load_matrix_sync(
                    fa[i], As + (warp_m * 64 + i * 16) * 36 + ks * 8, 36);
#pragma unroll
            for (int j = 0; j < NT; j++) {
                wmma::fragment<wmma::matrix_b, 16, 16, 8,
                               wmma::precision::tf32, wmma::col_major> fb;
                wmma::load_matrix_sync(
                    fb, Bs + (warp_n * (TN / 4) + j * 16) * 36 + ks * 8, 36);
#pragma unroll
                for (int i = 0; i < 4; i++)
                    wmma::mma_sync(acc[i][j], fa[i], fb, acc[i][j]);
            }
        }
        if (kb + 1 < KB) CP_WAIT0();
        __syncthreads();
    }

    float* Cs = sm;
    constexpr int LDCS = TN + 4;
#pragma unroll
    for (int i = 0; i < 4; i++)
#pragma unroll
        for (int j = 0; j < NT; j++)
            wmma::store_matrix_sync(
                Cs + (warp_m * 64 + i * 16) * LDCS + warp_n * (TN / 4) + j * 16,
                acc[i][j], LDCS, wmma::mem_row_major);
    __syncthreads();

    const int tok0 = by * 128;
    const int bglob = tok0 >> 12;
    const int tokin0 = tok0 & (NTOK - 1);
    for (int e = t; e < TN * 32; e += 256) {
        int j = e >> 5, tq = e & 31;
        size_t ob = ((size_t)bglob * CC + bx * TN + j) * NTOK + tokin0 + tq * 4;
#pragma unroll
        for (int q = 0; q < 4; q++)
            C[ob + q] = __float2half_rn(Cs[(tq * 4 + q) * LDCS + j]);
    }
}

// ---------------------------------------------------------------------------
extern "C" void kernel_launch(void* const* d_in, const int* in_sizes, int n_in,
                              void* d_out, int out_size) {
    const float* x = (const float*)d_in[0];
    const float* Wb = (const float*)d_in[1];
    const float* Wc = (const float*)d_in[2];
    const float* Wd = (const float*)d_in[3];
    const float* gamma = (const float*)d_in[4];
    float* out = (float*)d_out;

    __half *qkH, *qkL, *vTp, *P16;
    float *xrp, *Sp, *lpart, *mpart, *pscale, *oscale, *WqkT, *WdT;
    cudaGetSymbolAddress((void**)&qkH, g_qkH);
    cudaGetSymbolAddress((void**)&qkL, g_qkL);
    cudaGetSymbolAddress((void**)&xrp, g_xr);
    cudaGetSymbolAddress((void**)&vTp, g_vT);
    cudaGetSymbolAddress((void**)&Sp, g_S);
    cudaGetSymbolAddress((void**)&P16, g_P16);
    cudaGetSymbolAddress((void**)&lpart, g_lpart);
    cudaGetSymbolAddress((void**)&mpart, g_mpart);
    cudaGetSymbolAddress((void**)&pscale, g_pscale);
    cudaGetSymbolAddress((void**)&oscale, g_oscale);
    cudaGetSymbolAddress((void**)&WqkT, g_WqkT);
    cudaGetSymbolAddress((void**)&WdT, g_WdT);

    const int smem_qk = 2 * 2 * 2 * (128 + 128) * 40;           // 81920 B
    const int smem_S = 81920;                                   // same shape
    const int smem_PV = 128 * (256 + 4) * 4;                    // 133120 B
    const int smem_v = 128 * (256 + 4) * 4;                     // 133120 B
    cudaFuncSetAttribute(gemm_qk_h,
                         cudaFuncAttributeMaxDynamicSharedMemorySize, smem_qk);
    cudaFuncSetAttribute(gemm_h<128, 4, true>,
                         cudaFuncAttributeMaxDynamicSharedMemorySize, smem_S);
    cudaFuncSetAttribute(gemm_h<256, 6, false>,
                         cudaFuncAttributeMaxDynamicSharedMemorySize, smem_PV);
    cudaFuncSetAttribute(gemm_v,
                         cudaFuncAttributeMaxDynamicSharedMemorySize, smem_v);

    // producers
    round_x<<<(BNTOT * CC / 4 + 255) / 256, 256>>>((const float4*)x,
                                                   (float4*)xrp,
                                                   BNTOT * CC / 4);
    transpose_wqk<<<(128 * CC + 255) / 256, 256>>>(Wb, Wc, WqkT);
    transpose_w_round<<<(CC * CC + 255) / 256, 256>>>(Wd, WdT, CC, CC);

    // qk = X @ [Wb|Wc]  (fp16 split; hi/lo fp16 outputs)
    gemm_qk_h<<<dim3(1, BNTOT / 128), 256, smem_qk>>>(x, WqkT, qkH, qkL);
    // vT: v = X @ Wd (tf32 plain), fp16 transposed store
    gemm_v<<<dim3(CC / 256, BNTOT / 128), 256, smem_v>>>(xrp, WdT, vTp);
    // P_raw = exp(q k^T - 40) fp32 + row sum/max partials (fp16 split)
    gemm_h<128, 4, true><<<dim3(NTOK / 128, NTOK / 128, B_), 256, smem_S>>>(
        qkH, qkL, qkH + CRD, qkL + CRD, Sp, lpart, mpart, nullptr, nullptr,
        nullptr, CRD, 128, 128, NTOK, (size_t)NTOK * 128, (size_t)NTOK * 128,
        (size_t)NTOK * NTOK);
    // per-row scales
    reduce2<<<(B_ * NTOK + 255) / 256, 256>>>(lpart, mpart, pscale, oscale);
    // P16 = fp16(P * pscale)
    convert_P<<<dim3(NTOK / 1024, B_ * NTOK), 256>>>(Sp, pscale, P16);
    // out = gamma * (P16 @ v) * oscale + x  (fp16 plain)
    gemm_h<256, 6, false><<<dim3(CC / 256, NTOK / 128, B_), 256, smem_PV>>>(
        P16, nullptr, vTp, nullptr, out, nullptr, nullptr, oscale, x, gamma,
        NTOK, NTOK, NTOK, CC, (size_t)NTOK * NTOK, (size_t)CC * NTOK,
        (size_t)NTOK * CC);
}

// round 12
// speedup vs baseline: 2.9838x; 1.2543x over previous
#include <cuda_runtime.h>
#include <cuda_fp16.h>
#include <mma.h>
#include <cstdint>

using namespace nvcuda;

// ---------------------------------------------------------------------------
// PAM, wmma fp16 everywhere (2x HMMA rate) + selective 2-term splits.
//   qk GEMM: fp16-split -> qkH/qkL
//   v GEMM:  fp16 plain (x,Wd fp16-rounded) -> vT fp16
//   S GEMM:  fp16-split, epilogue exp(s-40) -> P fp32 + row sum/max partials
//   reduce:  pscale = 2^k (row max -> 2^14), oscale = 1/(sum*pscale)
//   PV GEMM: A = fp32 P * pscale converted to fp16 at STS (fused convert),
//            B = vT fp16 cp.async; out = gamma*acc*oscale + x
// ---------------------------------------------------------------------------

#define B_    4
#define NTOK  4096
#define CC    512
#define CRD   64
#define BNTOT (B_ * NTOK)
#define ESHIFT 40.0f

__device__ __half g_qkH[(size_t)BNTOT * 128];
__device__ __half g_qkL[(size_t)BNTOT * 128];
__device__ __half g_xh[(size_t)BNTOT * CC];        // fp16-rounded x
__device__ __half g_vT[(size_t)B_ * CC * NTOK];    // [b][c][tok] fp16
__device__ float  g_S[(size_t)B_ * NTOK * NTOK];   // raw exp probs fp32
__device__ float  g_lpart[(size_t)B_ * 32 * NTOK];
__device__ float  g_mpart[(size_t)B_ * 32 * NTOK];
__device__ float  g_pscale[B_ * NTOK];
__device__ float  g_oscale[B_ * NTOK];
__device__ float  g_WqkT[128 * CC];                // raw fp32
__device__ __half g_WdT16[CC * CC];                // fp16 transposed

__device__ __forceinline__ uint32_t smem_u32(const void* p) {
    uint32_t a;
    asm("{ .reg .u64 t; cvta.to.shared.u64 t, %1; cvt.u32.u64 %0, t; }"
        : "=r"(a) : "l"(p));
    return a;
}
__device__ __forceinline__ void cp16(uint32_t saddr, const void* g) {
    asm volatile("cp.async.cg.shared.global [%0], [%1], 16;" ::"r"(saddr),
                 "l"(g));
}
#define CP_COMMIT() asm volatile("cp.async.commit_group;" ::: "memory")
#define CP_WAIT0()  asm volatile("cp.async.wait_group 0;" ::: "memory")

// ---------------- producers --------------------------------------------------
__global__ void half_x(const float4* __restrict__ in, __half2* __restrict__ o,
                       int n4) {
    int i = blockIdx.x * 256 + threadIdx.x;
    if (i < n4) {
        float4 v = in[i];
        o[i * 2 + 0] = __floats2half2_rn(v.x, v.y);
        o[i * 2 + 1] = __floats2half2_rn(v.z, v.w);
    }
}
__global__ void transpose_wd_h(const float* __restrict__ W,
                               __half* __restrict__ WT) {
    int i = blockIdx.x * 256 + threadIdx.x;
    if (i < CC * CC) {
        int n = i / CC, k = i - n * CC;
        WT[i] = __float2half_rn(W[(size_t)k * CC + n]);
    }
}
__global__ void transpose_wqk(const float* __restrict__ Wb,
                              const float* __restrict__ Wc,
                              float* __restrict__ WT) {
    int i = blockIdx.x * 256 + threadIdx.x;
    if (i < 128 * CC) {
        int n = i / CC, k = i - n * CC;
        WT[i] = (n < CRD) ? Wb[(size_t)k * CRD + n]
                          : Wc[(size_t)k * CRD + (n - CRD)];
    }
}
__global__ void reduce2(const float* __restrict__ sp,
                        const float* __restrict__ mp,
                        float* __restrict__ pscale,
                        float* __restrict__ oscale) {
    int i = blockIdx.x * 256 + threadIdx.x;
    if (i < B_ * NTOK) {
        int b = i >> 12, row = i & (NTOK - 1);
        float s = 0.f, m = 0.f;
#pragma unroll
        for (int j = 0; j < 32; j++) {
            s += sp[((size_t)b * 32 + j) * NTOK + row];
            m = fmaxf(m, mp[((size_t)b * 32 + j) * NTOK + row]);
        }
        float ps = ldexpf(1.f, 14 - ilogbf(m));
        pscale[i] = ps;
        oscale[i] = 1.f / (s * ps);
    }
}

// ---------------- qk GEMM: register-staged fp16 split ------------------------
__global__ __launch_bounds__(256) void gemm_qk_h(const float* __restrict__ A,
                                                 const float* __restrict__ B,
                                                 __half* __restrict__ CH,
                                                 __half* __restrict__ CL) {
    extern __shared__ char smraw[];
    __half* sm = (__half*)smraw;
    constexpr int ASZ = 128 * 40, BSZ = 128 * 40;
    constexpr int STG = 2 * (ASZ + BSZ);
    const int t = threadIdx.x, wid = t >> 5;
    const int warp_m = wid >> 2, warp_n = wid & 3;
    const int by = blockIdx.y;
    const float* At = A + (size_t)(by * 128) * CC;

    wmma::fragment<wmma::accumulator, 16, 16, 16, float> acc[4][2];
#pragma unroll
    for (int i = 0; i < 4; i++)
#pragma unroll
        for (int j = 0; j < 2; j++) wmma::fill_fragment(acc[i][j], 0.f);

    float4 ra[4], rb[4];
    auto ldg = [&](int k0) {
#pragma unroll
        for (int i = 0; i < 4; i++) {
            int id = t + i * 256, r = id >> 3, c = id & 7;
            ra[i] = *(const float4*)&At[(size_t)r * CC + k0 + c * 4];
            rb[i] = *(const float4*)&B[(size_t)r * CC + k0 + c * 4];
        }
    };
    auto sts = [&](int s) {
        __half* AsH = sm + s * STG;
        __half* AsL = AsH + ASZ;
        __half* BsH = AsL + ASZ;
        __half* BsL = BsH + BSZ;
        auto split4 = [](float4 v, __half* dh, __half* dl) {
            __half h;
            h = __float2half_rn(v.x); dh[0] = h;
            dl[0] = __float2half_rn(v.x - __half2float(h));
            h = __float2half_rn(v.y); dh[1] = h;
            dl[1] = __float2half_rn(v.y - __half2float(h));
            h = __float2half_rn(v.z); dh[2] = h;
            dl[2] = __float2half_rn(v.z - __half2float(h));
            h = __float2half_rn(v.w); dh[3] = h;
            dl[3] = __float2half_rn(v.w - __half2float(h));
        };
#pragma unroll
        for (int i = 0; i < 4; i++) {
            int id = t + i * 256, r = id >> 3, c = id & 7;
            split4(ra[i], &AsH[r * 40 + c * 4], &AsL[r * 40 + c * 4]);
            split4(rb[i], &BsH[r * 40 + c * 4], &BsL[r * 40 + c * 4]);
        }
    };

    ldg(0);
    sts(0);
    __syncthreads();

    const int KB = CC / 32;
    for (int kb = 0; kb < KB; kb++) {
        const int p = kb & 1;
        if (kb + 1 < KB) ldg((kb + 1) * 32);
        __half* AsH = sm + p * STG;
        __half* AsL = AsH + ASZ;
        __half* BsH = AsL + ASZ;
        __half* BsL = BsH + BSZ;
#pragma unroll
        for (int ks = 0; ks < 2; ks++) {
            wmma::fragment<wmma::matrix_a, 16, 16, 16, __half,
                           wmma::row_major> faH[4], faL[4];
            wmma::fragment<wmma::matrix_b, 16, 16, 16, __half,
                           wmma::col_major> fbH[2], fbL[2];
#pragma unroll
            for (int i = 0; i < 4; i++) {
                int off = (warp_m * 64 + i * 16) * 40 + ks * 16;
                wmma::load_matrix_sync(faH[i], AsH + off, 40);
                wmma::load_matrix_sync(faL[i], AsL + off, 40);
            }
#pragma unroll
            for (int j = 0; j < 2; j++) {
                int off = (warp_n * 32 + j * 16) * 40 + ks * 16;
                wmma::load_matrix_sync(fbH[j], BsH + off, 40);
                wmma::load_matrix_sync(fbL[j], BsL + off, 40);
            }
#pragma unroll
            for (int i = 0; i < 4; i++)
#pragma unroll
                for (int j = 0; j < 2; j++) {
                    wmma::mma_sync(acc[i][j], faH[i], fbL[j], acc[i][j]);
                    wmma::mma_sync(acc[i][j], faL[i], fbH[j], acc[i][j]);
                    wmma::mma_sync(acc[i][j], faH[i], fbH[j], acc[i][j]);
                }
        }
        if (kb + 1 < KB) sts(p ^ 1);
        __syncthreads();
    }

    float* Cs = (float*)smraw;
#pragma unroll
    for (int i = 0; i < 4; i++)
#pragma unroll
        for (int j = 0; j < 2; j++)
            wmma::store_matrix_sync(
                Cs + (warp_m * 64 + i * 16) * 132 + warp_n * 32 + j * 16,
                acc[i][j], 132, wmma::mem_row_major);
    __syncthreads();
    for (int e = t; e < 128 * 32; e += 256) {
        int r = e >> 5, c4 = e & 31;
        float4 v = *(float4*)&Cs[r * 132 + c4 * 4];
        size_t idx = (size_t)(by * 128 + r) * 128 + c4 * 4;
        float vv[4] = {v.x, v.y, v.z, v.w};
#pragma unroll
        for (int q = 0; q < 4; q++) {
            __half h = __float2half_rn(vv[q]);
            CH[idx + q] = h;
            CL[idx + q] = __float2half_rn(vv[q] - __half2float(h));
        }
    }
}

// ---------------- cp.async wmma fp16 GEMM engine ----------------------------
// D 128xTN fp32 acc, 8 warps 2x4, warp 64x(TN/4). K-chunk 32 halfs, 2 stages.
// SPLIT: acc += AH*BL + AL*BH + AH*BH.
// EPI 1: transposed fp16 vT store (C cast to __half*)
// EPI 4: P = exp(acc-ESHIFT) fp32 store + row sum/max partials (TN=128)
template <int TN, int EPI, bool SPLIT>
__global__ __launch_bounds__(256) void gemm_h(
    const __half* __restrict__ AH, const __half* __restrict__ AL,
    const __half* __restrict__ BH, const __half* __restrict__ BL,
    float* __restrict__ C, float* __restrict__ sump, float* __restrict__ maxp,
    int K, int ldA, int ldB, int ldC, size_t sA, size_t sB, size_t sC) {
    extern __shared__ char smraw[];
    __half* sm = (__half*)smraw;
    constexpr int ASZ = 128 * 40, BSZ = TN * 40;
    constexpr int CMP = SPLIT ? 2 : 1;
    constexpr int STG = CMP * (ASZ + BSZ);
    constexpr int NT = TN / 64;
    constexpr int NBL = TN / 64;

    const int t = threadIdx.x, wid = t >> 5;
    const int warp_m = wid >> 2, warp_n = wid & 3;
    const int bx = blockIdx.x, by = blockIdx.y, bz = blockIdx.z;
    const uint32_t smb = smem_u32(smraw);

    const __half* AtH = AH + bz * sA + (size_t)(by * 128) * ldA;
    const __half* BtH = BH + bz * sB + (size_t)(bx * TN) * ldB;
    const __half* AtL = SPLIT ? AL + bz * sA + (size_t)(by * 128) * ldA : nullptr;
    const __half* BtL = SPLIT ? BL + bz * sB + (size_t)(bx * TN) * ldB : nullptr;

    wmma::fragment<wmma::accumulator, 16, 16, 16, float> acc[4][NT];
#pragma unroll
    for (int i = 0; i < 4; i++)
#pragma unroll
        for (int j = 0; j < NT; j++) wmma::fill_fragment(acc[i][j], 0.f);

    auto issue = [&](int s, int k0) {
        uint32_t ab = smb + s * STG * 2;
        uint32_t bb = ab + CMP * ASZ * 2;
#pragma unroll
        for (int i = 0; i < 2; i++) {
            int id = t + i * 256, r = id >> 2, c = id & 3;
            uint32_t so = (r * 40 + c * 8) * 2;
            cp16(ab + so, AtH + (size_t)r * ldA + k0 + c * 8);
            if (SPLIT)
                cp16(ab + ASZ * 2 + so, AtL + (size_t)r * ldA + k0 + c * 8);
        }
#pragma unroll
        for (int i = 0; i < NBL; i++) {
            int id = t + i * 256, r = id >> 2, c = id & 3;
            uint32_t so = (r * 40 + c * 8) * 2;
            cp16(bb + so, BtH + (size_t)r * ldB + k0 + c * 8);
            if (SPLIT)
                cp16(bb + BSZ * 2 + so, BtL + (size_t)r * ldB + k0 + c * 8);
        }
    };

    issue(0, 0);
    CP_COMMIT();
    CP_WAIT0();
    __syncthreads();

    const int KB = K / 32;
    for (int kb = 0; kb < KB; kb++) {
        const int p = kb & 1;
        if (kb + 1 < KB) {
            issue(p ^ 1, (kb + 1) * 32);
            CP_COMMIT();
        }
        __half* AsH = sm + p * STG;
        __half* AsL = AsH + ASZ;
        __half* BsH = AsH + CMP * ASZ;
        __half* BsL = BsH + BSZ;
#pragma unroll
        for (int ks = 0; ks < 2; ks++) {
            if (SPLIT) {
                wmma::fragment<wmma::matrix_a, 16, 16, 16, __half,
                               wmma::row_major> faH[4], faL[4];
                wmma::fragment<wmma::matrix_b, 16, 16, 16, __half,
                               wmma::col_major> fbH[NT], fbL[NT];
#pragma unroll
                for (int i = 0; i < 4; i++) {
                    int off = (warp_m * 64 + i * 16) * 40 + ks * 16;
                    wmma::load_matrix_sync(faH[i], AsH + off, 40);
                    wmma::load_matrix_sync(faL[i], AsL + off, 40);
                }
#pragma unroll
                for (int j = 0; j < NT; j++) {
                    int off = (warp_n * (TN / 4) + j * 16) * 40 + ks * 16;
                    wmma::load_matrix_sync(fbH[j], BsH + off, 40);
                    wmma::load_matrix_sync(fbL[j], BsL + off, 40);
                }
#pragma unroll
                for (int i = 0; i < 4; i++)
#pragma unroll
                    for (int j = 0; j < NT; j++) {
                        wmma::mma_sync(acc[i][j], faH[i], fbL[j], acc[i][j]);
                        wmma::mma_sync(acc[i][j], faL[i], fbH[j], acc[i][j]);
                        wmma::mma_sync(acc[i][j], faH[i], fbH[j], acc[i][j]);
                    }
            } else {
                wmma::fragment<wmma::matrix_a, 16, 16, 16, __half,
                               wmma::row_major> fa[4];
#pragma unroll
                for (int i = 0; i < 4; i++)
                    wmma::load_matrix_sync(
                        fa[i], AsH + (warp_m * 64 + i * 16) * 40 + ks * 16, 40);
#pragma unroll
                for (int j = 0; j < NT; j++) {
                    wmma::fragment<wmma::matrix_b, 16, 16, 16, __half,
                                   wmma::col_major> fb;
                    wmma::load_matrix_sync(
                        fb, BsH + (warp_n * (TN / 4) + j * 16) * 40 + ks * 16,
                        40);
#pragma unroll
                    for (int i = 0; i < 4; i++)
                        wmma::mma_sync(acc[i][j], fa[i], fb, acc[i][j]);
                }
            }
        }
        if (kb + 1 < KB) CP_WAIT0();
        __syncthreads();
    }

    // ---------------- epilogue ----------------------------------------------
    float* Cs = (float*)smraw;
    constexpr int LDCS = TN + 4;
#pragma unroll
    for (int i = 0; i < 4; i++)
#pragma unroll
        for (int j = 0; j < NT; j++)
            wmma::store_matrix_sync(
                Cs + (warp_m * 64 + i * 16) * LDCS + warp_n * (TN / 4) + j * 16,
                acc[i][j], LDCS, wmma::mem_row_major);
    __syncthreads();

    if (EPI == 1) {
        __half* Ch = (__half*)C;
        const int tok0 = by * 128;
        const int bglob = tok0 >> 12;
        const int tokin0 = tok0 & (NTOK - 1);
        for (int e = t; e < TN * 32; e += 256) {
            int j = e >> 5, tq = e & 31;
            size_t ob =
                ((size_t)bglob * CC + bx * TN + j) * NTOK + tokin0 + tq * 4;
#pragma unroll
            for (int q = 0; q < 4; q++)
                Ch[ob + q] = __float2half_rn(Cs[(tq * 4 + q) * LDCS + j]);
        }
    } else if (EPI == 4) {
        const int lane = t & 31;
#pragma unroll 4
        for (int it = 0; it < 16; it++) {
            int e = t + it * 256;
            int r = e >> 5, c4 = e & 31;
            float4 v = *(float4*)&Cs[r * LDCS + c4 * 4];
            float4 p;
            p.x = __expf(v.x - ESHIFT);
            p.y = __expf(v.y - ESHIFT);
            p.z = __expf(v.z - ESHIFT);
            p.w = __expf(v.w - ESHIFT);
            float s4 = p.x + p.y + p.z + p.w;
            float m4 = fmaxf(fmaxf(p.x, p.y), fmaxf(p.z, p.w));
            size_t base =
                bz * sC + (size_t)(by * 128 + r) * ldC + bx * TN + c4 * 4;
            *(float4*)&C[base] = p;
#pragma unroll
            for (int o = 16; o; o >>= 1) {
                s4 += __shfl_xor_sync(~0u, s4, o);
                m4 = fmaxf(m4, __shfl_xor_sync(~0u, m4, o));
            }
            if (lane == 0) {
                size_t pi = ((size_t)bz * 32 + bx) * NTOK + by * 128 + r;
                sump[pi] = s4;
                maxp[pi] = m4;
            }
        }
    }
}

// ---------------- PV GEMM: fp32 P (staged, *pscale, ->fp16) x fp16 vT -------
// D 128x256. A: P fp32 [b][n][m] (K=NTOK). B: vT fp16. EPI: gamma*acc*oscale+x
__global__ __launch_bounds__(256) void gemm_pv(
    const float* __restrict__ P, const __half* __restrict__ vT,
    float* __restrict__ C, const float* __restrict__ pscale,
    const float* __restrict__ oscale, const float* __restrict__ xres,
    const float* __restrict__ gamma) {
    extern __shared__ char smraw[];
    __half* sm = (__half*)smraw;
    constexpr int TN = 256;
    constexpr int ASZ = 128 * 40, BSZ = TN * 40;  // halfs
    constexpr int STG = ASZ + BSZ;
    constexpr int NT = TN / 64;

    const int t = threadIdx.x, wid = t >> 5;
    const int warp_m = wid >> 2, warp_n = wid & 3;
    const int bx = blockIdx.x, by = blockIdx.y, bz = blockIdx.z;
    const uint32_t smb = smem_u32(smraw);

    const float* At = P + (size_t)bz * NTOK * NTOK + (size_t)(by * 128) * NTOK;
    const __half* Bt = vT + (size_t)bz * CC * NTOK + (size_t)(bx * TN) * NTOK;

    // per-thread loop-invariant row scales (4 A float4 loads, fixed rows)
    float psc[4];
#pragma unroll
    for (int i = 0; i < 4; i++) {
        int r = (t + i * 256) >> 3;
        psc[i] = pscale[bz * NTOK + by * 128 + r];
    }

    wmma::fragment<wmma::accumulator, 16, 16, 16, float> acc[4][NT];
#pragma unroll
    for (int i = 0; i < 4; i++)
#pragma unroll
        for (int j = 0; j < NT; j++) wmma::fill_fragment(acc[i][j], 0.f);

    float4 ra[4];
    auto ldgA = [&](int k0) {
#pragma unroll
        for (int i = 0; i < 4; i++) {
            int id = t + i * 256, r = id >> 3, c = id & 7;
            ra[i] = *(const float4*)&At[(size_t)r * NTOK + k0 + c * 4];
        }
    };
    auto stsA = [&](int s) {
        __half* As = sm + s * STG;
#pragma unroll
        for (int i = 0; i < 4; i++) {
            int id = t + i * 256, r = id >> 3, c = id & 7;
            __half* d = &As[r * 40 + c * 4];
            d[0] = __float2half_rn(ra[i].x * psc[i]);
            d[1] = __float2half_rn(ra[i].y * psc[i]);
            d[2] = __float2half_rn(ra[i].z * psc[i]);
            d[3] = __float2half_rn(ra[i].w * psc[i]);
        }
    };
    auto issueB = [&](int s, int k0) {
        uint32_t bb = smb + (s * STG + ASZ) * 2;
#pragma unroll
        for (int i = 0; i < 4; i++) {
            int id = t + i * 256, r = id >> 2, c = id & 3;
            cp16(bb + (r * 40 + c * 8) * 2, Bt + (size_t)r * NTOK + k0 + c * 8);
        }
    };

    issueB(0, 0);
    CP_COMMIT();
    ldgA(0);
    stsA(0);
    CP_WAIT0();
    __syncthreads();

    const int KB = NTOK / 32;
    for (int kb = 0; kb < KB; kb++) {
        const int p = kb & 1;
        if (kb + 1 < KB) {
            issueB(p ^ 1, (kb + 1) * 32);
            CP_COMMIT();
            ldgA((kb + 1) * 32);
        }
        __half* As = sm + p * STG;
        __half* Bs = As + ASZ;
#pragma unroll
        for (int ks = 0; ks < 2; ks++) {
            wmma::fragment<wmma::matrix_a, 16, 16, 16, __half,
                           wmma::row_major> fa[4];
#pragma unroll
            for (int i = 0; i < 4; i++)
                wmma::load_matrix_sync(
                    fa[i], As + (warp_m * 64 + i * 16) * 40 + ks * 16, 40);
#pragma unroll
            for (int j = 0; j < NT; j++) {
                wmma::fragment<wmma::matrix_b, 16, 16, 16, __half,
                               wmma::col_major> fb;
                wmma::load_matrix_sync(
                    fb, Bs + (warp_n * (TN / 4) + j * 16) * 40 + ks * 16, 40);
#pragma unroll
                for (int i = 0; i < 4; i++)
                    wmma::mma_sync(acc[i][j], fa[i], fb, acc[i][j]);
            }
        }
        if (kb + 1 < KB) {
            stsA(p ^ 1);
            CP_WAIT0();
        }
        __syncthreads();
    }

    float* Cs = (float*)smraw;
    constexpr int LDCS = TN + 4;
#pragma unroll
    for (int i = 0; i < 4; i++)
#pragma unroll
        for (int j = 0; j < NT; j++)
            wmma::store_matrix_sync(
                Cs + (warp_m * 64 + i * 16) * LDCS + warp_n * (TN / 4) + j * 16,
                acc[i][j], LDCS, wmma::mem_row_major);
    __syncthreads();

    const float g = gamma[0];
    for (int e = t; e < 128 * (TN / 4); e += 256) {
        int r = e / (TN / 4), c4 = e % (TN / 4);
        float4 o = *(float4*)&Cs[r * LDCS + c4 * 4];
        size_t base = (size_t)bz * NTOK * CC + (size_t)(by * 128 + r) * CC +
                      bx * TN + c4 * 4;
        float gl = g * oscale[bz * NTOK + by * 128 + r];
        float4 xr = *(const float4*)&xres[base];
        o.x = gl * o.x + xr.x;
        o.y = gl * o.y + xr.y;
        o.z = gl * o.z + xr.z;
        o.w = gl * o.w + xr.w;
        *(float4*)&C[base] = o;
    }
}

// ---------------------------------------------------------------------------
extern "C" void kernel_launch(void* const* d_in, const int* in_sizes, int n_in,
                              void* d_out, int out_size) {
    const float* x = (const float*)d_in[0];
    const float* Wb = (const float*)d_in[1];
    const float* Wc = (const float*)d_in[2];
    const float* Wd = (const float*)d_in[3];
    const float* gamma = (const float*)d_in[4];
    float* out = (float*)d_out;

    __half *qkH, *qkL, *xh, *vTp, *WdT16;
    float *Sp, *lpart, *mpart, *pscale, *oscale, *WqkT;
    cudaGetSymbolAddress((void**)&qkH, g_qkH);
    cudaGetSymbolAddress((void**)&qkL, g_qkL);
    cudaGetSymbolAddress((void**)&xh, g_xh);
    cudaGetSymbolAddress((void**)&vTp, g_vT);
    cudaGetSymbolAddress((void**)&Sp, g_S);
    cudaGetSymbolAddress((void**)&lpart, g_lpart);
    cudaGetSymbolAddress((void**)&mpart, g_mpart);
    cudaGetSymbolAddress((void**)&pscale, g_pscale);
    cudaGetSymbolAddress((void**)&oscale, g_oscale);
    cudaGetSymbolAddress((void**)&WqkT, g_WqkT);
    cudaGetSymbolAddress((void**)&WdT16, g_WdT16);

    const int smem_qk = 2 * 2 * 2 * (128 + 128) * 40;  // 81920
    const int smem_S = 81920;
    const int smem_v = 128 * (256 + 4) * 4;            // 133120
    const int smem_PV = 128 * (256 + 4) * 4;
    cudaFuncSetAttribute(gemm_qk_h,
                         cudaFuncAttributeMaxDynamicSharedMemorySize, smem_qk);
    cudaFuncSetAttribute(gemm_h<128, 4, true>,
                         cudaFuncAttributeMaxDynamicSharedMemorySize, smem_S);
    cudaFuncSetAttribute(gemm_h<256, 1, false>,
                         cudaFuncAttributeMaxDynamicSharedMemorySize, smem_v);
    cudaFuncSetAttribute(gemm_pv,
                         cudaFuncAttributeMaxDynamicSharedMemorySize, smem_PV);

    // producers
    half_x<<<(BNTOT * CC / 4 + 255) / 256, 256>>>((const float4*)x,
                                                  (__half2*)xh,
                                                  BNTOT * CC / 4);
    transpose_wqk<<<(128 * CC + 255) / 256, 256>>>(Wb, Wc, WqkT);
    transpose_wd_h<<<(CC * CC + 255) / 256, 256>>>(Wd, WdT16);

    // qk = X @ [Wb|Wc]  (fp16 split)
    gemm_qk_h<<<dim3(1, BNTOT / 128), 256, smem_qk>>>(x, WqkT, qkH, qkL);
    // vT: v = X @ Wd (fp16 plain), fp16 transposed store
    gemm_h<256, 1, false><<<dim3(CC / 256, BNTOT / 128, 1), 256, smem_v>>>(
        xh, nullptr, WdT16, nullptr, (float*)vTp, nullptr, nullptr, CC, CC, CC,
        0, 0, 0, 0);
    // P_raw = exp(q k^T - 40) fp32 + row sum/max partials (fp16 split)
    gemm_h<128, 4, true><<<dim3(NTOK / 128, NTOK / 128, B_), 256, smem_S>>>(
        qkH, qkL, qkH + CRD, qkL + CRD, Sp, lpart, mpart, CRD, 128, 128, NTOK,
        (size_t)NTOK * 128, (size_t)NTOK * 128, (size_t)NTOK * NTOK);
    // per-row scales
    reduce2<<<(B_ * NTOK + 255) / 256, 256>>>(lpart, mpart, pscale, oscale);
    // out = gamma * (P @ v) * oscale + x  (fused convert inside PV)
    gemm_pv<<<dim3(CC / 256, NTOK / 128, B_), 256, smem_PV>>>(
        Sp, vTp, out, pscale, oscale, x, gamma);
}

// round 13
// speedup vs baseline: 3.1257x; 1.0476x over previous
#include <cuda_runtime.h>
#include <cuda_fp16.h>
#include <mma.h>
#include <cstdint>

using namespace nvcuda;

// ---------------------------------------------------------------------------
// PAM, wmma fp16 (2x HMMA rate) + selective 2-term splits (~22 bits).
//   qk GEMM: fp16-split -> qkH/qkL
//   v GEMM:  fp16 plain -> vT fp16
//   S GEMM:  fp16-split TN=256, epilogue exp(s-40) -> P fp32 + sum/max partials
//   reduce:  pscale = 2^k (row max -> 2^14), oscale = 1/(sum*pscale)
//   PV GEMM: A = fp32 P * pscale -> fp16 at STS (fused convert), B = vT fp16
//            out = gamma*acc*oscale + x
// ---------------------------------------------------------------------------

#define B_    4
#define NTOK  4096
#define CC    512
#define CRD   64
#define BNTOT (B_ * NTOK)
#define ESHIFT 40.0f

__device__ __half g_qkH[(size_t)BNTOT * 128];
__device__ __half g_qkL[(size_t)BNTOT * 128];
__device__ __half g_xh[(size_t)BNTOT * CC];        // fp16-rounded x
__device__ __half g_vT[(size_t)B_ * CC * NTOK];    // [b][c][tok] fp16
__device__ float  g_S[(size_t)B_ * NTOK * NTOK];   // raw exp probs fp32
__device__ float  g_lpart[(size_t)B_ * 32 * NTOK];
__device__ float  g_mpart[(size_t)B_ * 32 * NTOK];
__device__ float  g_pscale[B_ * NTOK];
__device__ float  g_oscale[B_ * NTOK];
__device__ float  g_WqkT[128 * CC];                // raw fp32
__device__ __half g_WdT16[CC * CC];                // fp16 transposed

__device__ __forceinline__ uint32_t smem_u32(const void* p) {
    uint32_t a;
    asm("{ .reg .u64 t; cvta.to.shared.u64 t, %1; cvt.u32.u64 %0, t; }"
        : "=r"(a) : "l"(p));
    return a;
}
__device__ __forceinline__ void cp16(uint32_t saddr, const void* g) {
    asm volatile("cp.async.cg.shared.global [%0], [%1], 16;" ::"r"(saddr),
                 "l"(g));
}
#define CP_COMMIT() asm volatile("cp.async.commit_group;" ::: "memory")
#define CP_WAIT0()  asm volatile("cp.async.wait_group 0;" ::: "memory")

// ---------------- producers --------------------------------------------------
__global__ void half_x(const float4* __restrict__ in, __half2* __restrict__ o,
                       int n4) {
    int i = blockIdx.x * 256 + threadIdx.x;
    if (i < n4) {
        float4 v = in[i];
        o[i * 2 + 0] = __floats2half2_rn(v.x, v.y);
        o[i * 2 + 1] = __floats2half2_rn(v.z, v.w);
    }
}
__global__ void transpose_wd_h(const float* __restrict__ W,
                               __half* __restrict__ WT) {
    int i = blockIdx.x * 256 + threadIdx.x;
    if (i < CC * CC) {
        int n = i / CC, k = i - n * CC;
        WT[i] = __float2half_rn(W[(size_t)k * CC + n]);
    }
}
__global__ void transpose_wqk(const float* __restrict__ Wb,
                              const float* __restrict__ Wc,
                              float* __restrict__ WT) {
    int i = blockIdx.x * 256 + threadIdx.x;
    if (i < 128 * CC) {
        int n = i / CC, k = i - n * CC;
        WT[i] = (n < CRD) ? Wb[(size_t)k * CRD + n]
                          : Wc[(size_t)k * CRD + (n - CRD)];
    }
}
__global__ void reduce2(const float* __restrict__ sp,
                        const float* __restrict__ mp,
                        float* __restrict__ pscale,
                        float* __restrict__ oscale) {
    int i = blockIdx.x * 256 + threadIdx.x;
    if (i < B_ * NTOK) {
        int b = i >> 12, row = i & (NTOK - 1);
        float s = 0.f, m = 0.f;
#pragma unroll
        for (int j = 0; j < 32; j++) {
            s += sp[((size_t)b * 32 + j) * NTOK + row];
            m = fmaxf(m, mp[((size_t)b * 32 + j) * NTOK + row]);
        }
        float ps = ldexpf(1.f, 14 - ilogbf(m));
        pscale[i] = ps;
        oscale[i] = 1.f / (s * ps);
    }
}

// ---------------- qk GEMM: register-staged fp16 split ------------------------
__global__ __launch_bounds__(256) void gemm_qk_h(const float* __restrict__ A,
                                                 const float* __restrict__ B,
                                                 __half* __restrict__ CH,
                                                 __half* __restrict__ CL) {
    extern __shared__ char smraw[];
    __half* sm = (__half*)smraw;
    constexpr int ASZ = 128 * 40, BSZ = 128 * 40;
    constexpr int STG = 2 * (ASZ + BSZ);
    const int t = threadIdx.x, wid = t >> 5;
    const int warp_m = wid >> 2, warp_n = wid & 3;
    const int by = blockIdx.y;
    const float* At = A + (size_t)(by * 128) * CC;

    wmma::fragment<wmma::accumulator, 16, 16, 16, float> acc[4][2];
#pragma unroll
    for (int i = 0; i < 4; i++)
#pragma unroll
        for (int j = 0; j < 2; j++) wmma::fill_fragment(acc[i][j], 0.f);

    float4 ra[4], rb[4];
    auto ldg = [&](int k0) {
#pragma unroll
        for (int i = 0; i < 4; i++) {
            int id = t + i * 256, r = id >> 3, c = id & 7;
            ra[i] = *(const float4*)&At[(size_t)r * CC + k0 + c * 4];
            rb[i] = *(const float4*)&B[(size_t)r * CC + k0 + c * 4];
        }
    };
    auto sts = [&](int s) {
        __half* AsH = sm + s * STG;
        __half* AsL = AsH + ASZ;
        __half* BsH = AsL + ASZ;
        __half* BsL = BsH + BSZ;
        auto split4 = [](float4 v, __half* dh, __half* dl) {
            __half h;
            h = __float2half_rn(v.x); dh[0] = h;
            dl[0] = __float2half_rn(v.x - __half2float(h));
            h = __float2half_rn(v.y); dh[1] = h;
            dl[1] = __float2half_rn(v.y - __half2float(h));
            h = __float2half_rn(v.z); dh[2] = h;
            dl[2] = __float2half_rn(v.z - __half2float(h));
            h = __float2half_rn(v.w); dh[3] = h;
            dl[3] = __float2half_rn(v.w - __half2float(h));
        };
#pragma unroll
        for (int i = 0; i < 4; i++) {
            int id = t + i * 256, r = id >> 3, c = id & 7;
            split4(ra[i], &AsH[r * 40 + c * 4], &AsL[r * 40 + c * 4]);
            split4(rb[i], &BsH[r * 40 + c * 4], &BsL[r * 40 + c * 4]);
        }
    };

    ldg(0);
    sts(0);
    __syncthreads();

    const int KB = CC / 32;
    for (int kb = 0; kb < KB; kb++) {
        const int p = kb & 1;
        if (kb + 1 < KB) ldg((kb + 1) * 32);
        __half* AsH = sm + p * STG;
        __half* AsL = AsH + ASZ;
        __half* BsH = AsL + ASZ;
        __half* BsL = BsH + BSZ;
#pragma unroll
        for (int ks = 0; ks < 2; ks++) {
            wmma::fragment<wmma::matrix_a, 16, 16, 16, __half,
                           wmma::row_major> faH[4], faL[4];
#pragma unroll
            for (int i = 0; i < 4; i++) {
                int off = (warp_m * 64 + i * 16) * 40 + ks * 16;
                wmma::load_matrix_sync(faH[i], AsH + off, 40);
                wmma::load_matrix_sync(faL[i], AsL + off, 40);
            }
#pragma unroll
            for (int j = 0; j < 2; j++) {
                int off = (warp_n * 32 + j * 16) * 40 + ks * 16;
                wmma::fragment<wmma::matrix_b, 16, 16, 16, __half,
                               wmma::col_major> fbH, fbL;
                wmma::load_matrix_sync(fbH, BsH + off, 40);
                wmma::load_matrix_sync(fbL, BsL + off, 40);
#pragma unroll
                for (int i = 0; i < 4; i++) {
                    wmma::mma_sync(acc[i][j], faH[i], fbL, acc[i][j]);
                    wmma::mma_sync(acc[i][j], faL[i], fbH, acc[i][j]);
                    wmma::mma_sync(acc[i][j], faH[i], fbH, acc[i][j]);
                }
            }
        }
        if (kb + 1 < KB) sts(p ^ 1);
        __syncthreads();
    }

    float* Cs = (float*)smraw;
#pragma unroll
    for (int i = 0; i < 4; i++)
#pragma unroll
        for (int j = 0; j < 2; j++)
            wmma::store_matrix_sync(
                Cs + (warp_m * 64 + i * 16) * 132 + warp_n * 32 + j * 16,
                acc[i][j], 132, wmma::mem_row_major);
    __syncthreads();
    for (int e = t; e < 128 * 32; e += 256) {
        int r = e >> 5, c4 = e & 31;
        float4 v = *(float4*)&Cs[r * 132 + c4 * 4];
        size_t idx = (size_t)(by * 128 + r) * 128 + c4 * 4;
        float vv[4] = {v.x, v.y, v.z, v.w};
#pragma unroll
        for (int q = 0; q < 4; q++) {
            __half h = __float2half_rn(vv[q]);
            CH[idx + q] = h;
            CL[idx + q] = __float2half_rn(vv[q] - __half2float(h));
        }
    }
}

// ---------------- cp.async wmma fp16 GEMM engine ----------------------------
// D 128xTN fp32 acc, 8 warps 2x4, warp 64x(TN/4). K-chunk 32 halfs, 2 stages.
// SPLIT: acc += AH*BL + AL*BH + AH*BH.
// EPI 1: transposed fp16 vT store (C cast to __half*)
// EPI 4: P = exp(acc-ESHIFT) fp32 store + row sum/max partials.
//        Partial slot = bx*(TN/128) + half-of-row; needs grid.x*(TN/128)<=32.
template <int TN, int EPI, bool SPLIT>
__global__ __launch_bounds__(256) void gemm_h(
    const __half* __restrict__ AH, const __half* __restrict__ AL,
    const __half* __restrict__ BH, const __half* __restrict__ BL,
    float* __restrict__ C, float* __restrict__ sump, float* __restrict__ maxp,
    int K, int ldA, int ldB, int ldC, size_t sA, size_t sB, size_t sC) {
    extern __shared__ char smraw[];
    __half* sm = (__half*)smraw;
    constexpr int ASZ = 128 * 40, BSZ = TN * 40;
    constexpr int CMP = SPLIT ? 2 : 1;
    constexpr int STG = CMP * (ASZ + BSZ);
    constexpr int NT = TN / 64;
    constexpr int NBL = TN / 64;

    const int t = threadIdx.x, wid = t >> 5;
    const int warp_m = wid >> 2, warp_n = wid & 3;
    const int bx = blockIdx.x, by = blockIdx.y, bz = blockIdx.z;
    const uint32_t smb = smem_u32(smraw);

    const __half* AtH = AH + bz * sA + (size_t)(by * 128) * ldA;
    const __half* BtH = BH + bz * sB + (size_t)(bx * TN) * ldB;
    const __half* AtL = SPLIT ? AL + bz * sA + (size_t)(by * 128) * ldA : nullptr;
    const __half* BtL = SPLIT ? BL + bz * sB + (size_t)(bx * TN) * ldB : nullptr;

    wmma::fragment<wmma::accumulator, 16, 16, 16, float> acc[4][NT];
#pragma unroll
    for (int i = 0; i < 4; i++)
#pragma unroll
        for (int j = 0; j < NT; j++) wmma::fill_fragment(acc[i][j], 0.f);

    auto issue = [&](int s, int k0) {
        uint32_t ab = smb + s * STG * 2;
        uint32_t bb = ab + CMP * ASZ * 2;
#pragma unroll
        for (int i = 0; i < 2; i++) {
            int id = t + i * 256, r = id >> 2, c = id & 3;
            uint32_t so = (r * 40 + c * 8) * 2;
            cp16(ab + so, AtH + (size_t)r * ldA + k0 + c * 8);
            if (SPLIT)
                cp16(ab + ASZ * 2 + so, AtL + (size_t)r * ldA + k0 + c * 8);
        }
#pragma unroll
        for (int i = 0; i < NBL; i++) {
            int id = t + i * 256, r = id >> 2, c = id & 3;
            uint32_t so = (r * 40 + c * 8) * 2;
            cp16(bb + so, BtH + (size_t)r * ldB + k0 + c * 8);
            if (SPLIT)
                cp16(bb + BSZ * 2 + so, BtL + (size_t)r * ldB + k0 + c * 8);
        }
    };

    issue(0, 0);
    CP_COMMIT();
    CP_WAIT0();
    __syncthreads();

    const int KB = K / 32;
    for (int kb = 0; kb < KB; kb++) {
        const int p = kb & 1;
        if (kb + 1 < KB) {
            issue(p ^ 1, (kb + 1) * 32);
            CP_COMMIT();
        }
        __half* AsH = sm + p * STG;
        __half* AsL = AsH + ASZ;
        __half* BsH = AsH + CMP * ASZ;
        __half* BsL = BsH + BSZ;
#pragma unroll
        for (int ks = 0; ks < 2; ks++) {
            if (SPLIT) {
                wmma::fragment<wmma::matrix_a, 16, 16, 16, __half,
                               wmma::row_major> faH[4], faL[4];
#pragma unroll
                for (int i = 0; i < 4; i++) {
                    int off = (warp_m * 64 + i * 16) * 40 + ks * 16;
                    wmma::load_matrix_sync(faH[i], AsH + off, 40);
                    wmma::load_matrix_sync(faL[i], AsL + off, 40);
                }
#pragma unroll
                for (int j = 0; j < NT; j++) {
                    int off = (warp_n * (TN / 4) + j * 16) * 40 + ks * 16;
                    wmma::fragment<wmma::matrix_b, 16, 16, 16, __half,
                                   wmma::col_major> fbH, fbL;
                    wmma::load_matrix_sync(fbH, BsH + off, 40);
                    wmma::load_matrix_sync(fbL, BsL + off, 40);
#pragma unroll
                    for (int i = 0; i < 4; i++) {
                        wmma::mma_sync(acc[i][j], faH[i], fbL, acc[i][j]);
                        wmma::mma_sync(acc[i][j], faL[i], fbH, acc[i][j]);
                        wmma::mma_sync(acc[i][j], faH[i], fbH, acc[i][j]);
                    }
                }
            } else {
                wmma::fragment<wmma::matrix_a, 16, 16, 16, __half,
                               wmma::row_major> fa[4];
#pragma unroll
                for (int i = 0; i < 4; i++)
                    wmma::load_matrix_sync(
                        fa[i], AsH + (warp_m * 64 + i * 16) * 40 + ks * 16, 40);
#pragma unroll
                for (int j = 0; j < NT; j++) {
                    wmma::fragment<wmma::matrix_b, 16, 16, 16, __half,
                                   wmma::col_major> fb;
                    wmma::load_matrix_sync(
                        fb, BsH + (warp_n * (TN / 4) + j * 16) * 40 + ks * 16,
                        40);
#pragma unroll
                    for (int i = 0; i < 4; i++)
                        wmma::mma_sync(acc[i][j], fa[i], fb, acc[i][j]);
                }
            }
        }
        if (kb + 1 < KB) CP_WAIT0();
        __syncthreads();
    }

    // ---------------- epilogue ----------------------------------------------
    float* Cs = (float*)smraw;
    constexpr int LDCS = TN + 4;
#pragma unroll
    for (int i = 0; i < 4; i++)
#pragma unroll
        for (int j = 0; j < NT; j++)
            wmma::store_matrix_sync(
                Cs + (warp_m * 64 + i * 16) * LDCS + warp_n * (TN / 4) + j * 16,
                acc[i][j], LDCS, wmma::mem_row_major);
    __syncthreads();

    if (EPI == 1) {
        __half* Ch = (__half*)C;
        const int tok0 = by * 128;
        const int bglob = tok0 >> 12;
        const int tokin0 = tok0 & (NTOK - 1);
        for (int e = t; e < TN * 32; e += 256) {
            int j = e >> 5, tq = e & 31;
            size_t ob =
                ((size_t)bglob * CC + bx * TN + j) * NTOK + tokin0 + tq * 4;
#pragma unroll
            for (int q = 0; q < 4; q++)
                Ch[ob + q] = __float2half_rn(Cs[(tq * 4 + q) * LDCS + j]);
        }
    } else if (EPI == 4) {
        constexpr int C4 = TN / 4;       // float4 per row
        constexpr int ITER = 128 * C4 / 256;
        const int lane = t & 31;
#pragma unroll 4
        for (int it = 0; it < ITER; it++) {
            int e = t + it * 256;
            int r = e / C4, c4 = e % C4;
            float4 v = *(float4*)&Cs[r * LDCS + c4 * 4];
            float4 p;
            p.x = __expf(v.x - ESHIFT);
            p.y = __expf(v.y - ESHIFT);
            p.z = __expf(v.z - ESHIFT);
            p.w = __expf(v.w - ESHIFT);
            float s4 = p.x + p.y + p.z + p.w;
            float m4 = fmaxf(fmaxf(p.x, p.y), fmaxf(p.z, p.w));
            size_t base =
                bz * sC + (size_t)(by * 128 + r) * ldC + bx * TN + c4 * 4;
            *(float4*)&C[base] = p;
#pragma unroll
            for (int o = 16; o; o >>= 1) {
                s4 += __shfl_xor_sync(~0u, s4, o);
                m4 = fmaxf(m4, __shfl_xor_sync(~0u, m4, o));
            }
            if (lane == 0) {
                int slot = bx * (TN / 128) + ((c4 >> 5) & ((TN / 128) - 1));
                size_t pi = ((size_t)bz * 32 + slot) * NTOK + by * 128 + r;
                sump[pi] = s4;
                maxp[pi] = m4;
            }
        }
    }
}

// ---------------- PV GEMM: fp32 P (staged, *pscale, ->fp16) x fp16 vT -------
__global__ __launch_bounds__(256) void gemm_pv(
    const float* __restrict__ P, const __half* __restrict__ vT,
    float* __restrict__ C, const float* __restrict__ pscale,
    const float* __restrict__ oscale, const float* __restrict__ xres,
    const float* __restrict__ gamma) {
    extern __shared__ char smraw[];
    __half* sm = (__half*)smraw;
    constexpr int TN = 256;
    constexpr int ASZ = 128 * 40, BSZ = TN * 40;
    constexpr int STG = ASZ + BSZ;
    constexpr int NT = TN / 64;

    const int t = threadIdx.x, wid = t >> 5;
    const int warp_m = wid >> 2, warp_n = wid & 3;
    const int bx = blockIdx.x, by = blockIdx.y, bz = blockIdx.z;
    const uint32_t smb = smem_u32(smraw);

    const float* At = P + (size_t)bz * NTOK * NTOK + (size_t)(by * 128) * NTOK;
    const __half* Bt = vT + (size_t)bz * CC * NTOK + (size_t)(bx * TN) * NTOK;

    float psc[4];
#pragma unroll
    for (int i = 0; i < 4; i++) {
        int r = (t + i * 256) >> 3;
        psc[i] = pscale[bz * NTOK + by * 128 + r];
    }

    wmma::fragment<wmma::accumulator, 16, 16, 16, float> acc[4][NT];
#pragma unroll
    for (int i = 0; i < 4; i++)
#pragma unroll
        for (int j = 0; j < NT; j++) wmma::fill_fragment(acc[i][j], 0.f);

    float4 ra[4];
    auto ldgA = [&](int k0) {
#pragma unroll
        for (int i = 0; i < 4; i++) {
            int id = t + i * 256, r = id >> 3, c = id & 7;
            ra[i] = *(const float4*)&At[(size_t)r * NTOK + k0 + c * 4];
        }
    };
    auto stsA = [&](int s) {
        __half* As = sm + s * STG;
#pragma unroll
        for (int i = 0; i < 4; i++) {
            int id = t + i * 256, r = id >> 3, c = id & 7;
            __half* d = &As[r * 40 + c * 4];
            d[0] = __float2half_rn(ra[i].x * psc[i]);
            d[1] = __float2half_rn(ra[i].y * psc[i]);
            d[2] = __float2half_rn(ra[i].z * psc[i]);
            d[3] = __float2half_rn(ra[i].w * psc[i]);
        }
    };
    auto issueB = [&](int s, int k0) {
        uint32_t bb = smb + (s * STG + ASZ) * 2;
#pragma unroll
        for (int i = 0; i < 4; i++) {
            int id = t + i * 256, r = id >> 2, c = id & 3;
            cp16(bb + (r * 40 + c * 8) * 2, Bt + (size_t)r * NTOK + k0 + c * 8);
        }
    };

    issueB(0, 0);
    CP_COMMIT();
    ldgA(0);
    stsA(0);
    CP_WAIT0();
    __syncthreads();

    const int KB = NTOK / 32;
    for (int kb = 0; kb < KB; kb++) {
        const int p = kb & 1;
        if (kb + 1 < KB) {
            issueB(p ^ 1, (kb + 1) * 32);
            CP_COMMIT();
            ldgA((kb + 1) * 32);
        }
        __half* As = sm + p * STG;
        __half* Bs = As + ASZ;
#pragma unroll
        for (int ks = 0; ks < 2; ks++) {
            wmma::fragment<wmma::matrix_a, 16, 16, 16, __half,
                           wmma::row_major> fa[4];
#pragma unroll
            for (int i = 0; i < 4; i++)
                wmma::load_matrix_sync(
                    fa[i], As + (warp_m * 64 + i * 16) * 40 + ks * 16, 40);
#pragma unroll
            for (int j = 0; j < NT; j++) {
                wmma::fragment<wmma::matrix_b, 16, 16, 16, __half,
                               wmma::col_major> fb;
                wmma::load_matrix_sync(
                    fb, Bs + (warp_n * (TN / 4) + j * 16) * 40 + ks * 16, 40);
#pragma unroll
                for (int i = 0; i < 4; i++)
                    wmma::mma_sync(acc[i][j], fa[i], fb, acc[i][j]);
            }
        }
        if (kb + 1 < KB) {
            stsA(p ^ 1);
            CP_WAIT0();
        }
        __syncthreads();
    }

    float* Cs = (float*)smraw;
    constexpr int LDCS = TN + 4;
#pragma unroll
    for (int i = 0; i < 4; i++)
#pragma unroll
        for (int j = 0; j < NT; j++)
            wmma::store_matrix_sync(
                Cs + (warp_m * 64 + i * 16) * LDCS + warp_n * (TN / 4) + j * 16,
                acc[i][j], LDCS, wmma::mem_row_major);
    __syncthreads();

    const float g = gamma[0];
    for (int e = t; e < 128 * (TN / 4); e += 256) {
        int r = e / (TN / 4), c4 = e % (TN / 4);
        float4 o = *(float4*)&Cs[r * LDCS + c4 * 4];
        size_t base = (size_t)bz * NTOK * CC + (size_t)(by * 128 + r) * CC +
                      bx * TN + c4 * 4;
        float gl = g * oscale[bz * NTOK + by * 128 + r];
        float4 xr = *(const float4*)&xres[base];
        o.x = gl * o.x + xr.x;
        o.y = gl * o.y + xr.y;
        o.z = gl * o.z + xr.z;
        o.w = gl * o.w + xr.w;
        *(float4*)&C[base] = o;
    }
}

// ---------------------------------------------------------------------------
extern "C" void kernel_launch(void* const* d_in, const int* in_sizes, int n_in,
                              void* d_out, int out_size) {
    const float* x = (const float*)d_in[0];
    const float* Wb = (const float*)d_in[1];
    const float* Wc = (const float*)d_in[2];
    const float* Wd = (const float*)d_in[3];
    const float* gamma = (const float*)d_in[4];
    float* out = (float*)d_out;

    __half *qkH, *qkL, *xh, *vTp, *WdT16;
    float *Sp, *lpart, *mpart, *pscale, *oscale, *WqkT;
    cudaGetSymbolAddress((void**)&qkH, g_qkH);
    cudaGetSymbolAddress((void**)&qkL, g_qkL);
    cudaGetSymbolAddress((void**)&xh, g_xh);
    cudaGetSymbolAddress((void**)&vTp, g_vT);
    cudaGetSymbolAddress((void**)&Sp, g_S);
    cudaGetSymbolAddress((void**)&lpart, g_lpart);
    cudaGetSymbolAddress((void**)&mpart, g_mpart);
    cudaGetSymbolAddress((void**)&pscale, g_pscale);
    cudaGetSymbolAddress((void**)&oscale, g_oscale);
    cudaGetSymbolAddress((void**)&WqkT, g_WqkT);
    cudaGetSymbolAddress((void**)&WdT16, g_WdT16);

    const int smem_qk = 2 * 2 * 2 * (128 + 128) * 40;  // 81920
    // S TN=256 split: stage = 2*(128+256)*40*2 B = 61440; 2 stages = 122880;
    // epilogue Cs = 128*260*4 = 133120 -> max
    const int smem_S = 133120;
    const int smem_v = 128 * (256 + 4) * 4;            // 133120
    const int smem_PV = 128 * (256 + 4) * 4;
    cudaFuncSetAttribute(gemm_qk_h,
                         cudaFuncAttributeMaxDynamicSharedMemorySize, smem_qk);
    cudaFuncSetAttribute(gemm_h<256, 4, true>,
                         cudaFuncAttributeMaxDynamicSharedMemorySize, smem_S);
    cudaFuncSetAttribute(gemm_h<256, 1, false>,
                         cudaFuncAttributeMaxDynamicSharedMemorySize, smem_v);
    cudaFuncSetAttribute(gemm_pv,
                         cudaFuncAttributeMaxDynamicSharedMemorySize, smem_PV);

    // producers
    half_x<<<(BNTOT * CC / 4 + 255) / 256, 256>>>((const float4*)x,
                                                  (__half2*)xh,
                                                  BNTOT * CC / 4);
    transpose_wqk<<<(128 * CC + 255) / 256, 256>>>(Wb, Wc, WqkT);
    transpose_wd_h<<<(CC * CC + 255) / 256, 256>>>(Wd, WdT16);

    // qk = X @ [Wb|Wc]  (fp16 split)
    gemm_qk_h<<<dim3(1, BNTOT / 128), 256, smem_qk>>>(x, WqkT, qkH, qkL);
    // vT: v = X @ Wd (fp16 plain), fp16 transposed store
    gemm_h<256, 1, false><<<dim3(CC / 256, BNTOT / 128, 1), 256, smem_v>>>(
        xh, nullptr, WdT16, nullptr, (float*)vTp, nullptr, nullptr, CC, CC, CC,
        0, 0, 0, 0);
    // P_raw = exp(q k^T - 40) fp32 + row sum/max partials (fp16 split, TN=256)
    gemm_h<256, 4, true><<<dim3(NTOK / 256, NTOK / 128, B_), 256, smem_S>>>(
        qkH, qkL, qkH + CRD, qkL + CRD, Sp, lpart, mpart, CRD, 128, 128, NTOK,
        (size_t)NTOK * 128, (size_t)NTOK * 128, (size_t)NTOK * NTOK);
    // per-row scales
    reduce2<<<(B_ * NTOK + 255) / 256, 256>>>(lpart, mpart, pscale, oscale);
    // out = gamma * (P @ v) * oscale + x  (fused convert inside PV)
    gemm_pv<<<dim3(CC / 256, NTOK / 128, B_), 256, smem_PV>>>(
        Sp, vTp, out, pscale, oscale, x, gamma);
}

// round 14
// speedup vs baseline: 3.2921x; 1.0532x over previous
#include <cuda_runtime.h>
#include <cuda_fp16.h>
#include <mma.h>
#include <cstdint>

using namespace nvcuda;

// ---------------------------------------------------------------------------
// PAM, wmma fp16 + selective 2-term splits (~22 bits on score path).
//   qk GEMM: fp16-split -> qkH/qkL
//   v GEMM:  fp16 plain -> vT fp16
//   S GEMM:  fp16-split, SINGLE-SHOT K=64 (no pipeline), epilogue exp(s-40)
//            -> P fp32 + row sum/max partials
//   reduce:  pscale = 2^k (row max -> 2^14), oscale = 1/(sum*pscale)
//   PV GEMM: A = fp32 P * pscale -> fp16 at STS, B = vT fp16 3-stage cp.async
//            out = gamma*acc*oscale + x
// ---------------------------------------------------------------------------

#define B_    4
#define NTOK  4096
#define CC    512
#define CRD   64
#define BNTOT (B_ * NTOK)
#define ESHIFT 40.0f

__device__ __half g_qkH[(size_t)BNTOT * 128];
__device__ __half g_qkL[(size_t)BNTOT * 128];
__device__ __half g_xh[(size_t)BNTOT * CC];        // fp16-rounded x
__device__ __half g_vT[(size_t)B_ * CC * NTOK];    // [b][c][tok] fp16
__device__ float  g_S[(size_t)B_ * NTOK * NTOK];   // raw exp probs fp32
__device__ float  g_lpart[(size_t)B_ * 32 * NTOK];
__device__ float  g_mpart[(size_t)B_ * 32 * NTOK];
__device__ float  g_pscale[B_ * NTOK];
__device__ float  g_oscale[B_ * NTOK];
__device__ float  g_WqkT[128 * CC];                // raw fp32
__device__ __half g_WdT16[CC * CC];                // fp16 transposed

__device__ __forceinline__ uint32_t smem_u32(const void* p) {
    uint32_t a;
    asm("{ .reg .u64 t; cvta.to.shared.u64 t, %1; cvt.u32.u64 %0, t; }"
        : "=r"(a) : "l"(p));
    return a;
}
__device__ __forceinline__ void cp16(uint32_t saddr, const void* g) {
    asm volatile("cp.async.cg.shared.global [%0], [%1], 16;" ::"r"(saddr),
                 "l"(g));
}
#define CP_COMMIT() asm volatile("cp.async.commit_group;" ::: "memory")
#define CP_WAIT0()  asm volatile("cp.async.wait_group 0;" ::: "memory")
#define CP_WAIT1()  asm volatile("cp.async.wait_group 1;" ::: "memory")

// ---------------- producers --------------------------------------------------
__global__ void half_x(const float4* __restrict__ in, __half2* __restrict__ o,
                       int n4) {
    int i = blockIdx.x * 256 + threadIdx.x;
    if (i < n4) {
        float4 v = in[i];
        o[i * 2 + 0] = __floats2half2_rn(v.x, v.y);
        o[i * 2 + 1] = __floats2half2_rn(v.z, v.w);
    }
}
__global__ void transpose_wd_h(const float* __restrict__ W,
                               __half* __restrict__ WT) {
    int i = blockIdx.x * 256 + threadIdx.x;
    if (i < CC * CC) {
        int n = i / CC, k = i - n * CC;
        WT[i] = __float2half_rn(W[(size_t)k * CC + n]);
    }
}
__global__ void transpose_wqk(const float* __restrict__ Wb,
                              const float* __restrict__ Wc,
                              float* __restrict__ WT) {
    int i = blockIdx.x * 256 + threadIdx.x;
    if (i < 128 * CC) {
        int n = i / CC, k = i - n * CC;
        WT[i] = (n < CRD) ? Wb[(size_t)k * CRD + n]
                          : Wc[(size_t)k * CRD + (n - CRD)];
    }
}
__global__ void reduce2(const float* __restrict__ sp,
                        const float* __restrict__ mp,
                        float* __restrict__ pscale,
                        float* __restrict__ oscale) {
    int i = blockIdx.x * 256 + threadIdx.x;
    if (i < B_ * NTOK) {
        int b = i >> 12, row = i & (NTOK - 1);
        float s = 0.f, m = 0.f;
#pragma unroll
        for (int j = 0; j < 32; j++) {
            s += sp[((size_t)b * 32 + j) * NTOK + row];
            m = fmaxf(m, mp[((size_t)b * 32 + j) * NTOK + row]);
        }
        float ps = ldexpf(1.f, 14 - ilogbf(m));
        pscale[i] = ps;
        oscale[i] = 1.f / (s * ps);
    }
}

// ---------------- qk GEMM: register-staged fp16 split ------------------------
__global__ __launch_bounds__(256) void gemm_qk_h(const float* __restrict__ A,
                                                 const float* __restrict__ B,
                                                 __half* __restrict__ CH,
                                                 __half* __restrict__ CL) {
    extern __shared__ char smraw[];
    __half* sm = (__half*)smraw;
    constexpr int ASZ = 128 * 40, BSZ = 128 * 40;
    constexpr int STG = 2 * (ASZ + BSZ);
    const int t = threadIdx.x, wid = t >> 5;
    const int warp_m = wid >> 2, warp_n = wid & 3;
    const int by = blockIdx.y;
    const float* At = A + (size_t)(by * 128) * CC;

    wmma::fragment<wmma::accumulator, 16, 16, 16, float> acc[4][2];
#pragma unroll
    for (int i = 0; i < 4; i++)
#pragma unroll
        for (int j = 0; j < 2; j++) wmma::fill_fragment(acc[i][j], 0.f);

    float4 ra[4], rb[4];
    auto ldg = [&](int k0) {
#pragma unroll
        for (int i = 0; i < 4; i++) {
            int id = t + i * 256, r = id >> 3, c = id & 7;
            ra[i] = *(const float4*)&At[(size_t)r * CC + k0 + c * 4];
            rb[i] = *(const float4*)&B[(size_t)r * CC + k0 + c * 4];
        }
    };
    auto sts = [&](int s) {
        __half* AsH = sm + s * STG;
        __half* AsL = AsH + ASZ;
        __half* BsH = AsL + ASZ;
        __half* BsL = BsH + BSZ;
        auto split4 = [](float4 v, __half* dh, __half* dl) {
            __half h;
            h = __float2half_rn(v.x); dh[0] = h;
            dl[0] = __float2half_rn(v.x - __half2float(h));
            h = __float2half_rn(v.y); dh[1] = h;
            dl[1] = __float2half_rn(v.y - __half2float(h));
            h = __float2half_rn(v.z); dh[2] = h;
            dl[2] = __float2half_rn(v.z - __half2float(h));
            h = __float2half_rn(v.w); dh[3] = h;
            dl[3] = __float2half_rn(v.w - __half2float(h));
        };
#pragma unroll
        for (int i = 0; i < 4; i++) {
            int id = t + i * 256, r = id >> 3, c = id & 7;
            split4(ra[i], &AsH[r * 40 + c * 4], &AsL[r * 40 + c * 4]);
            split4(rb[i], &BsH[r * 40 + c * 4], &BsL[r * 40 + c * 4]);
        }
    };

    ldg(0);
    sts(0);
    __syncthreads();

    const int KB = CC / 32;
    for (int kb = 0; kb < KB; kb++) {
        const int p = kb & 1;
        if (kb + 1 < KB) ldg((kb + 1) * 32);
        __half* AsH = sm + p * STG;
        __half* AsL = AsH + ASZ;
        __half* BsH = AsL + ASZ;
        __half* BsL = BsH + BSZ;
#pragma unroll
        for (int ks = 0; ks < 2; ks++) {
            wmma::fragment<wmma::matrix_a, 16, 16, 16, __half,
                           wmma::row_major> faH[4], faL[4];
#pragma unroll
            for (int i = 0; i < 4; i++) {
                int off = (warp_m * 64 + i * 16) * 40 + ks * 16;
                wmma::load_matrix_sync(faH[i], AsH + off, 40);
                wmma::load_matrix_sync(faL[i], AsL + off, 40);
            }
#pragma unroll
            for (int j = 0; j < 2; j++) {
                int off = (warp_n * 32 + j * 16) * 40 + ks * 16;
                wmma::fragment<wmma::matrix_b, 16, 16, 16, __half,
                               wmma::col_major> fbH, fbL;
                wmma::load_matrix_sync(fbH, BsH + off, 40);
                wmma::load_matrix_sync(fbL, BsL + off, 40);
#pragma unroll
                for (int i = 0; i < 4; i++) {
                    wmma::mma_sync(acc[i][j], faH[i], fbL, acc[i][j]);
                    wmma::mma_sync(acc[i][j], faL[i], fbH, acc[i][j]);
                    wmma::mma_sync(acc[i][j], faH[i], fbH, acc[i][j]);
                }
            }
        }
        if (kb + 1 < KB) sts(p ^ 1);
        __syncthreads();
    }

    float* Cs = (float*)smraw;
#pragma unroll
    for (int i = 0; i < 4; i++)
#pragma unroll
        for (int j = 0; j < 2; j++)
            wmma::store_matrix_sync(
                Cs + (warp_m * 64 + i * 16) * 132 + warp_n * 32 + j * 16,
                acc[i][j], 132, wmma::mem_row_major);
    __syncthreads();
    for (int e = t; e < 128 * 32; e += 256) {
        int r = e >> 5, c4 = e & 31;
        float4 v = *(float4*)&Cs[r * 132 + c4 * 4];
        size_t idx = (size_t)(by * 128 + r) * 128 + c4 * 4;
        float vv[4] = {v.x, v.y, v.z, v.w};
#pragma unroll
        for (int q = 0; q < 4; q++) {
            __half h = __float2half_rn(vv[q]);
            CH[idx + q] = h;
            CL[idx + q] = __float2half_rn(vv[q] - __half2float(h));
        }
    }
}

// ---------------- v GEMM engine (plain fp16, cp.async, EPI: vT store) -------
__global__ __launch_bounds__(256) void gemm_v16(const __half* __restrict__ A,
                                                const __half* __restrict__ B,
                                                __half* __restrict__ C) {
    extern __shared__ char smraw[];
    __half* sm = (__half*)smraw;
    constexpr int TN = 256;
    constexpr int ASZ = 128 * 40, BSZ = TN * 40;
    constexpr int STG = ASZ + BSZ;
    constexpr int NT = TN / 64;

    const int t = threadIdx.x, wid = t >> 5;
    const int warp_m = wid >> 2, warp_n = wid & 3;
    const int bx = blockIdx.x, by = blockIdx.y;
    const uint32_t smb = smem_u32(smraw);

    const __half* At = A + (size_t)(by * 128) * CC;
    const __half* Bt = B + (size_t)(bx * TN) * CC;

    wmma::fragment<wmma::accumulator, 16, 16, 16, float> acc[4][NT];
#pragma unroll
    for (int i = 0; i < 4; i++)
#pragma unroll
        for (int j = 0; j < NT; j++) wmma::fill_fragment(acc[i][j], 0.f);

    auto issue = [&](int s, int k0) {
        uint32_t ab = smb + s * STG * 2;
        uint32_t bb = ab + ASZ * 2;
#pragma unroll
        for (int i = 0; i < 2; i++) {
            int id = t + i * 256, r = id >> 2, c = id & 3;
            cp16(ab + (r * 40 + c * 8) * 2, At + (size_t)r * CC + k0 + c * 8);
        }
#pragma unroll
        for (int i = 0; i < 4; i++) {
            int id = t + i * 256, r = id >> 2, c = id & 3;
            cp16(bb + (r * 40 + c * 8) * 2, Bt + (size_t)r * CC + k0 + c * 8);
        }
    };

    issue(0, 0);
    CP_COMMIT();
    CP_WAIT0();
    __syncthreads();

    const int KB = CC / 32;
    for (int kb = 0; kb < KB; kb++) {
        const int p = kb & 1;
        if (kb + 1 < KB) {
            issue(p ^ 1, (kb + 1) * 32);
            CP_COMMIT();
        }
        __half* As = sm + p * STG;
        __half* Bs = As + ASZ;
#pragma unroll
        for (int ks = 0; ks < 2; ks++) {
            wmma::fragment<wmma::matrix_a, 16, 16, 16, __half,
                           wmma::row_major> fa[4];
#pragma unroll
            for (int i = 0; i < 4; i++)
                wmma::load_matrix_sync(
                    fa[i], As + (warp_m * 64 + i * 16) * 40 + ks * 16, 40);
#pragma unroll
            for (int j = 0; j < NT; j++) {
                wmma::fragment<wmma::matrix_b, 16, 16, 16, __half,
                               wmma::col_major> fb;
                wmma::load_matrix_sync(
                    fb, Bs + (warp_n * (TN / 4) + j * 16) * 40 + ks * 16, 40);
#pragma unroll
                for (int i = 0; i < 4; i++)
                    wmma::mma_sync(acc[i][j], fa[i], fb, acc[i][j]);
            }
        }
        if (kb + 1 < KB) CP_WAIT0();
        __syncthreads();
    }

    float* Cs = (float*)smraw;
    constexpr int LDCS = TN + 4;
#pragma unroll
    for (int i = 0; i < 4; i++)
#pragma unroll
        for (int j = 0; j < NT; j++)
            wmma::store_matrix_sync(
                Cs + (warp_m * 64 + i * 16) * LDCS + warp_n * (TN / 4) + j * 16,
                acc[i][j], LDCS, wmma::mem_row_major);
    __syncthreads();

    const int tok0 = by * 128;
    const int bglob = tok0 >> 12;
    const int tokin0 = tok0 & (NTOK - 1);
    for (int e = t; e < TN * 32; e += 256) {
        int j = e >> 5, tq = e & 31;
        size_t ob = ((size_t)bglob * CC + bx * TN + j) * NTOK + tokin0 + tq * 4;
#pragma unroll
        for (int q = 0; q < 4; q++)
            C[ob + q] = __float2half_rn(Cs[(tq * 4 + q) * LDCS + j]);
    }
}

// ---------------- S GEMM: single-shot K=64, fp16 split ----------------------
// D 128x256. A = q (rows, 64 dims), B = k (256 tokens, 64 dims), both as
// hi/lo fp16 pairs in g_qkH/g_qkL (q at col 0, k at col 64 of the 128-wide
// qk rows). Everything loaded once via cp.async, straight-line MMA, then
// exp epilogue with row sum/max partials (slot = bx*2 + col-half).
__global__ __launch_bounds__(256) void gemm_s(
    const __half* __restrict__ qkH, const __half* __restrict__ qkL,
    float* __restrict__ C, float* __restrict__ sump,
    float* __restrict__ maxp) {
    extern __shared__ char smraw[];
    __half* sm = (__half*)smraw;
    constexpr int AS = 128 * 72;  // halfs per A component
    constexpr int BS = 256 * 72;  // halfs per B component
    const int t = threadIdx.x, wid = t >> 5;
    const int warp_m = wid >> 2, warp_n = wid & 3;
    const int bx = blockIdx.x, by = blockIdx.y, bz = blockIdx.z;
    const uint32_t smb = smem_u32(smraw);

    const __half* AtH = qkH + (size_t)(bz * NTOK + by * 128) * 128;
    const __half* AtL = qkL + (size_t)(bz * NTOK + by * 128) * 128;
    const __half* BtH = qkH + (size_t)(bz * NTOK + bx * 256) * 128 + CRD;
    const __half* BtL = qkL + (size_t)(bz * NTOK + bx * 256) * 128 + CRD;

    const uint32_t aH = smb, aL = smb + AS * 2;
    const uint32_t bH = smb + 2 * AS * 2, bL = smb + (2 * AS + BS) * 2;
#pragma unroll
    for (int i = 0; i < 4; i++) {
        int id = t + i * 256, r = id >> 3, c = id & 7;
        uint32_t so = (r * 72 + c * 8) * 2;
        cp16(aH + so, AtH + (size_t)r * 128 + c * 8);
        cp16(aL + so, AtL + (size_t)r * 128 + c * 8);
    }
#pragma unroll
    for (int i = 0; i < 8; i++) {
        int id = t + i * 256, r = id >> 3, c = id & 7;
        uint32_t so = (r * 72 + c * 8) * 2;
        cp16(bH + so, BtH + (size_t)r * 128 + c * 8);
        cp16(bL + so, BtL + (size_t)r * 128 + c * 8);
    }
    CP_COMMIT();
    CP_WAIT0();
    __syncthreads();

    wmma::fragment<wmma::accumulator, 16, 16, 16, float> acc[4][4];
#pragma unroll
    for (int i = 0; i < 4; i++)
#pragma unroll
        for (int j = 0; j < 4; j++) wmma::fill_fragment(acc[i][j], 0.f);

    __half* AsH = sm;
    __half* AsL = sm + AS;
    __half* BsH = sm + 2 * AS;
    __half* BsL = sm + 2 * AS + BS;
#pragma unroll
    for (int ks = 0; ks < 4; ks++) {
        wmma::fragment<wmma::matrix_a, 16, 16, 16, __half, wmma::row_major>
            faH[4], faL[4];
#pragma unroll
        for (int i = 0; i < 4; i++) {
            int off = (warp_m * 64 + i * 16) * 72 + ks * 16;
            wmma::load_matrix_sync(faH[i], AsH + off, 72);
            wmma::load_matrix_sync(faL[i], AsL + off, 72);
        }
#pragma unroll
        for (int j = 0; j < 4; j++) {
            int off = (warp_n * 64 + j * 16) * 72 + ks * 16;
            wmma::fragment<wmma::matrix_b, 16, 16, 16, __half,
                           wmma::col_major> fbH, fbL;
            wmma::load_matrix_sync(fbH, BsH + off, 72);
            wmma::load_matrix_sync(fbL, BsL + off, 72);
#pragma unroll
            for (int i = 0; i < 4; i++) {
                wmma::mma_sync(acc[i][j], faH[i], fbL, acc[i][j]);
                wmma::mma_sync(acc[i][j], faL[i], fbH, acc[i][j]);
                wmma::mma_sync(acc[i][j], faH[i], fbH, acc[i][j]);
            }
        }
    }
    __syncthreads();  // smem reuse: tiles -> Cs

    float* Cs = (float*)smraw;
    constexpr int LDCS = 260;
#pragma unroll
    for (int i = 0; i < 4; i++)
#pragma unroll
        for (int j = 0; j < 4; j++)
            wmma::store_matrix_sync(
                Cs + (warp_m * 64 + i * 16) * LDCS + warp_n * 64 + j * 16,
                acc[i][j], LDCS, wmma::mem_row_major);
    __syncthreads();

    const int lane = t & 31;
#pragma unroll 4
    for (int it = 0; it < 32; it++) {
        int e = t + it * 256;
        int r = e >> 6, c4 = e & 63;
        float4 v = *(float4*)&Cs[r * LDCS + c4 * 4];
        float4 p;
        p.x = __expf(v.x - ESHIFT);
        p.y = __expf(v.y - ESHIFT);
        p.z = __expf(v.z - ESHIFT);
        p.w = __expf(v.w - ESHIFT);
        float s4 = p.x + p.y + p.z + p.w;
        float m4 = fmaxf(fmaxf(p.x, p.y), fmaxf(p.z, p.w));
        size_t base = (size_t)bz * NTOK * NTOK + (size_t)(by * 128 + r) * NTOK +
                      bx * 256 + c4 * 4;
        *(float4*)&C[base] = p;
#pragma unroll
        for (int o = 16; o; o >>= 1) {
            s4 += __shfl_xor_sync(~0u, s4, o);
            m4 = fmaxf(m4, __shfl_xor_sync(~0u, m4, o));
        }
        if (lane == 0) {
            int slot = bx * 2 + ((c4 >> 5) & 1);
            size_t pi = ((size_t)bz * 32 + slot) * NTOK + by * 128 + r;
            sump[pi] = s4;
            maxp[pi] = m4;
        }
    }
}

// ---------------- PV GEMM: fp32 P (staged,*pscale,->fp16) x fp16 vT ---------
// 3-stage cp.async pipeline on B; A register-staged 1 chunk ahead.
__global__ __launch_bounds__(256) void gemm_pv(
    const float* __restrict__ P, const __half* __restrict__ vT,
    float* __restrict__ C, const float* __restrict__ pscale,
    const float* __restrict__ oscale, const float* __restrict__ xres,
    const float* __restrict__ gamma) {
    extern __shared__ char smraw[];
    __half* sm = (__half*)smraw;
    constexpr int TN = 256;
    constexpr int ASTG = 128 * 40;  // halfs per A stage (2 stages)
    constexpr int BSTG = TN * 40;   // halfs per B stage (3 stages)
    constexpr int NT = TN / 64;

    const int t = threadIdx.x, wid = t >> 5;
    const int warp_m = wid >> 2, warp_n = wid & 3;
    const int bx = blockIdx.x, by = blockIdx.y, bz = blockIdx.z;
    const uint32_t smb = smem_u32(smraw);

    const float* At = P + (size_t)bz * NTOK * NTOK + (size_t)(by * 128) * NTOK;
    const __half* Bt = vT + (size_t)bz * CC * NTOK + (size_t)(bx * TN) * NTOK;

    float psc[4];
#pragma unroll
    for (int i = 0; i < 4; i++) {
        int r = (t + i * 256) >> 3;
        psc[i] = pscale[bz * NTOK + by * 128 + r];
    }

    wmma::fragment<wmma::accumulator, 16, 16, 16, float> acc[4][NT];
#pragma unroll
    for (int i = 0; i < 4; i++)
#pragma unroll
        for (int j = 0; j < NT; j++) wmma::fill_fragment(acc[i][j], 0.f);

    float4 ra[4];
    auto ldgA = [&](int k0) {
#pragma unroll
        for (int i = 0; i < 4; i++) {
            int id = t + i * 256, r = id >> 3, c = id & 7;
            ra[i] = *(const float4*)&At[(size_t)r * NTOK + k0 + c * 4];
        }
    };
    auto stsA = [&](int s) {
        __half* As = sm + s * ASTG;
#pragma unroll
        for (int i = 0; i < 4; i++) {
            int id = t + i * 256, r = id >> 3, c = id & 7;
            __half* d = &As[r * 40 + c * 4];
            d[0] = __float2half_rn(ra[i].x * psc[i]);
            d[1] = __float2half_rn(ra[i].y * psc[i]);
            d[2] = __float2half_rn(ra[i].z * psc[i]);
            d[3] = __float2half_rn(ra[i].w * psc[i]);
        }
    };
    auto issueB = [&](int s, int k0) {
        uint32_t bb = smb + (2 * ASTG + s * BSTG) * 2;
#pragma unroll
        for (int i = 0; i < 4; i++) {
            int id = t + i * 256, r = id >> 2, c = id & 3;
            cp16(bb + (r * 40 + c * 8) * 2, Bt + (size_t)r * NTOK + k0 + c * 8);
        }
    };

    // prologue: B0, B1 in flight; A0 staged
    issueB(0, 0);
    CP_COMMIT();
    issueB(1, 32);
    CP_COMMIT();
    ldgA(0);
    stsA(0);
    CP_WAIT1();  // B0 complete, B1 may fly
    __syncthreads();

    const int KB = NTOK / 32;
    for (int kb = 0; kb < KB; kb++) {
        const int pa = kb & 1;
        const int pb = kb % 3;
        if (kb + 1 < KB) ldgA((kb + 1) * 32);
        if (kb + 2 < KB) {
            issueB((kb + 2) % 3, (kb + 2) * 32);
            CP_COMMIT();
        }
        __half* As = sm + pa * ASTG;
        __half* Bs = sm + 2 * ASTG + pb * BSTG;
#pragma unroll
        for (int ks = 0; ks < 2; ks++) {
            wmma::fragment<wmma::matrix_a, 16, 16, 16, __half,
                           wmma::row_major> fa[4];
#pragma unroll
            for (int i = 0; i < 4; i++)
                wmma::load_matrix_sync(
                    fa[i], As + (warp_m * 64 + i * 16) * 40 + ks * 16, 40);
#pragma unroll
            for (int j = 0; j < NT; j++) {
                wmma::fragment<wmma::matrix_b, 16, 16, 16, __half,
                               wmma::col_major> fb;
                wmma::load_matrix_sync(
                    fb, Bs + (warp_n * (TN / 4) + j * 16) * 40 + ks * 16, 40);
#pragma unroll
                for (int i = 0; i < 4; i++)
                    wmma::mma_sync(acc[i][j], fa[i], fb, acc[i][j]);
            }
        }
        if (kb + 1 < KB) {
            stsA(pa ^ 1);
            if (kb + 2 < KB) CP_WAIT1();
            else CP_WAIT0();
        }
        __syncthreads();
    }

    float* Cs = (float*)smraw;
    constexpr int LDCS = TN + 4;
#pragma unroll
    for (int i = 0; i < 4; i++)
#pragma unroll
        for (int j = 0; j < NT; j++)
            wmma::store_matrix_sync(
                Cs + (warp_m * 64 + i * 16) * LDCS + warp_n * (TN / 4) + j * 16,
                acc[i][j], LDCS, wmma::mem_row_major);
    __syncthreads();

    const float g = gamma[0];
    for (int e = t; e < 128 * (TN / 4); e += 256) {
        int r = e / (TN / 4), c4 = e % (TN / 4);
        float4 o = *(float4*)&Cs[r * LDCS + c4 * 4];
        size_t base = (size_t)bz * NTOK * CC + (size_t)(by * 128 + r) * CC +
                      bx * TN + c4 * 4;
        float gl = g * oscale[bz * NTOK + by * 128 + r];
        float4 xr = *(const float4*)&xres[base];
        o.x = gl * o.x + xr.x;
        o.y = gl * o.y + xr.y;
        o.z = gl * o.z + xr.z;
        o.w = gl * o.w + xr.w;
        *(float4*)&C[base] = o;
    }
}

// ---------------------------------------------------------------------------
extern "C" void kernel_launch(void* const* d_in, const int* in_sizes, int n_in,
                              void* d_out, int out_size) {
    const float* x = (const float*)d_in[0];
    const float* Wb = (const float*)d_in[1];
    const float* Wc = (const float*)d_in[2];
    const float* Wd = (const float*)d_in[3];
    const float* gamma = (const float*)d_in[4];
    float* out = (float*)d_out;

    __half *qkH, *qkL, *xh, *vTp, *WdT16;
    float *Sp, *lpart, *mpart, *pscale, *oscale, *WqkT;
    cudaGetSymbolAddress((void**)&qkH, g_qkH);
    cudaGetSymbolAddress((void**)&qkL, g_qkL);
    cudaGetSymbolAddress((void**)&xh, g_xh);
    cudaGetSymbolAddress((void**)&vTp, g_vT);
    cudaGetSymbolAddress((void**)&Sp, g_S);
    cudaGetSymbolAddress((void**)&lpart, g_lpart);
    cudaGetSymbolAddress((void**)&mpart, g_mpart);
    cudaGetSymbolAddress((void**)&pscale, g_pscale);
    cudaGetSymbolAddress((void**)&oscale, g_oscale);
    cudaGetSymbolAddress((void**)&WqkT, g_WqkT);
    cudaGetSymbolAddress((void**)&WdT16, g_WdT16);

    const int smem_qk = 2 * 2 * 2 * (128 + 128) * 40;  // 81920
    const int smem_S = 133120;   // max(tiles 110592, Cs 133120)
    const int smem_v = 133120;
    const int smem_PV = 133120;  // max(pipe 81920, Cs 133120)
    cudaFuncSetAttribute(gemm_qk_h,
                         cudaFuncAttributeMaxDynamicSharedMemorySize, smem_qk);
    cudaFuncSetAttribute(gemm_s,
                         cudaFuncAttributeMaxDynamicSharedMemorySize, smem_S);
    cudaFuncSetAttribute(gemm_v16,
                         cudaFuncAttributeMaxDynamicSharedMemorySize, smem_v);
    cudaFuncSetAttribute(gemm_pv,
                         cudaFuncAttributeMaxDynamicSharedMemorySize, smem_PV);

    // producers
    half_x<<<(BNTOT * CC / 4 + 255) / 256, 256>>>((const float4*)x,
                                                  (__half2*)xh,
                                                  BNTOT * CC / 4);
    transpose_wqk<<<(128 * CC + 255) / 256, 256>>>(Wb, Wc, WqkT);
    transpose_wd_h<<<(CC * CC + 255) / 256, 256>>>(Wd, WdT16);

    // qk = X @ [Wb|Wc]  (fp16 split)
    gemm_qk_h<<<dim3(1, BNTOT / 128), 256, smem_qk>>>(x, WqkT, qkH, qkL);
    // vT: v = X @ Wd (fp16 plain), fp16 transposed store
    gemm_v16<<<dim3(CC / 256, BNTOT / 128), 256, smem_v>>>(xh, WdT16, vTp);
    // P_raw = exp(q k^T - 40) fp32 + row sum/max partials (single-shot K)
    gemm_s<<<dim3(NTOK / 256, NTOK / 128, B_), 256, smem_S>>>(qkH, qkL, Sp,
                                                              lpart, mpart);
    // per-row scales
    reduce2<<<(B_ * NTOK + 255) / 256, 256>>>(lpart, mpart, pscale, oscale);
    // out = gamma * (P @ v) * oscale + x  (fused convert inside PV)
    gemm_pv<<<dim3(CC / 256, NTOK / 128, B_), 256, smem_PV>>>(
        Sp, vTp, out, pscale, oscale, x, gamma);
}

// round 15
// speedup vs baseline: 3.3115x; 1.0059x over previous
#include <cuda_runtime.h>
#include <cuda_fp16.h>
#include <mma.h>
#include <cstdint>

using namespace nvcuda;

// ---------------------------------------------------------------------------
// PAM, wmma fp16 + selective 2-term splits (~22 bits on score path).
//   Stream A (s2):  transpose_wqk -> qk GEMM (fp16-split)
//   Stream 0:       half_x, transpose_wd -> v GEMM (fp16 plain, vT store)
//   join -> S GEMM (single-shot K=64 split, exp epilogue, sum/max partials)
//   -> reduce (pscale/oscale) -> PV GEMM (fused P convert, 3-stage B pipe)
// ---------------------------------------------------------------------------

#define B_    4
#define NTOK  4096
#define CC    512
#define CRD   64
#define BNTOT (B_ * NTOK)
#define ESHIFT 40.0f

__device__ __half g_qkH[(size_t)BNTOT * 128];
__device__ __half g_qkL[(size_t)BNTOT * 128];
__device__ __half g_xh[(size_t)BNTOT * CC];        // fp16-rounded x
__device__ __half g_vT[(size_t)B_ * CC * NTOK];    // [b][c][tok] fp16
__device__ float  g_S[(size_t)B_ * NTOK * NTOK];   // raw exp probs fp32
__device__ float  g_lpart[(size_t)B_ * 32 * NTOK];
__device__ float  g_mpart[(size_t)B_ * 32 * NTOK];
__device__ float  g_pscale[B_ * NTOK];
__device__ float  g_oscale[B_ * NTOK];
__device__ float  g_WqkT[128 * CC];                // raw fp32
__device__ __half g_WdT16[CC * CC];                // fp16 transposed

__device__ __forceinline__ uint32_t smem_u32(const void* p) {
    uint32_t a;
    asm("{ .reg .u64 t; cvta.to.shared.u64 t, %1; cvt.u32.u64 %0, t; }"
        : "=r"(a) : "l"(p));
    return a;
}
__device__ __forceinline__ void cp16(uint32_t saddr, const void* g) {
    asm volatile("cp.async.cg.shared.global [%0], [%1], 16;" ::"r"(saddr),
                 "l"(g));
}
#define CP_COMMIT() asm volatile("cp.async.commit_group;" ::: "memory")
#define CP_WAIT0()  asm volatile("cp.async.wait_group 0;" ::: "memory")
#define CP_WAIT1()  asm volatile("cp.async.wait_group 1;" ::: "memory")

// ---------------- producers --------------------------------------------------
__global__ void half_x(const float4* __restrict__ in, __half2* __restrict__ o,
                       int n4) {
    int i = blockIdx.x * 256 + threadIdx.x;
    if (i < n4) {
        float4 v = in[i];
        o[i * 2 + 0] = __floats2half2_rn(v.x, v.y);
        o[i * 2 + 1] = __floats2half2_rn(v.z, v.w);
    }
}
__global__ void transpose_wd_h(const float* __restrict__ W,
                               __half* __restrict__ WT) {
    int i = blockIdx.x * 256 + threadIdx.x;
    if (i < CC * CC) {
        int n = i / CC, k = i - n * CC;
        WT[i] = __float2half_rn(W[(size_t)k * CC + n]);
    }
}
__global__ void transpose_wqk(const float* __restrict__ Wb,
                              const float* __restrict__ Wc,
                              float* __restrict__ WT) {
    int i = blockIdx.x * 256 + threadIdx.x;
    if (i < 128 * CC) {
        int n = i / CC, k = i - n * CC;
        WT[i] = (n < CRD) ? Wb[(size_t)k * CRD + n]
                          : Wc[(size_t)k * CRD + (n - CRD)];
    }
}
__global__ void reduce2(const float* __restrict__ sp,
                        const float* __restrict__ mp,
                        float* __restrict__ pscale,
                        float* __restrict__ oscale) {
    int i = blockIdx.x * 256 + threadIdx.x;
    if (i < B_ * NTOK) {
        int b = i >> 12, row = i & (NTOK - 1);
        float s = 0.f, m = 0.f;
#pragma unroll
        for (int j = 0; j < 32; j++) {
            s += sp[((size_t)b * 32 + j) * NTOK + row];
            m = fmaxf(m, mp[((size_t)b * 32 + j) * NTOK + row]);
        }
        float ps = ldexpf(1.f, 14 - ilogbf(m));
        pscale[i] = ps;
        oscale[i] = 1.f / (s * ps);
    }
}

// ---------------- qk GEMM: register-staged fp16 split ------------------------
__global__ __launch_bounds__(256) void gemm_qk_h(const float* __restrict__ A,
                                                 const float* __restrict__ B,
                                                 __half* __restrict__ CH,
                                                 __half* __restrict__ CL) {
    extern __shared__ char smraw[];
    __half* sm = (__half*)smraw;
    constexpr int ASZ = 128 * 40, BSZ = 128 * 40;
    constexpr int STG = 2 * (ASZ + BSZ);
    const int t = threadIdx.x, wid = t >> 5;
    const int warp_m = wid >> 2, warp_n = wid & 3;
    const int by = blockIdx.y;
    const float* At = A + (size_t)(by * 128) * CC;

    wmma::fragment<wmma::accumulator, 16, 16, 16, float> acc[4][2];
#pragma unroll
    for (int i = 0; i < 4; i++)
#pragma unroll
        for (int j = 0; j < 2; j++) wmma::fill_fragment(acc[i][j], 0.f);

    float4 ra[4], rb[4];
    auto ldg = [&](int k0) {
#pragma unroll
        for (int i = 0; i < 4; i++) {
            int id = t + i * 256, r = id >> 3, c = id & 7;
            ra[i] = *(const float4*)&At[(size_t)r * CC + k0 + c * 4];
            rb[i] = *(const float4*)&B[(size_t)r * CC + k0 + c * 4];
        }
    };
    auto sts = [&](int s) {
        __half* AsH = sm + s * STG;
        __half* AsL = AsH + ASZ;
        __half* BsH = AsL + ASZ;
        __half* BsL = BsH + BSZ;
        auto split4 = [](float4 v, __half* dh, __half* dl) {
            __half h;
            h = __float2half_rn(v.x); dh[0] = h;
            dl[0] = __float2half_rn(v.x - __half2float(h));
            h = __float2half_rn(v.y); dh[1] = h;
            dl[1] = __float2half_rn(v.y - __half2float(h));
            h = __float2half_rn(v.z); dh[2] = h;
            dl[2] = __float2half_rn(v.z - __half2float(h));
            h = __float2half_rn(v.w); dh[3] = h;
            dl[3] = __float2half_rn(v.w - __half2float(h));
        };
#pragma unroll
        for (int i = 0; i < 4; i++) {
            int id = t + i * 256, r = id >> 3, c = id & 7;
            split4(ra[i], &AsH[r * 40 + c * 4], &AsL[r * 40 + c * 4]);
            split4(rb[i], &BsH[r * 40 + c * 4], &BsL[r * 40 + c * 4]);
        }
    };

    ldg(0);
    sts(0);
    __syncthreads();

    const int KB = CC / 32;
    for (int kb = 0; kb < KB; kb++) {
        const int p = kb & 1;
        if (kb + 1 < KB) ldg((kb + 1) * 32);
        __half* AsH = sm + p * STG;
        __half* AsL = AsH + ASZ;
        __half* BsH = AsL + ASZ;
        __half* BsL = BsH + BSZ;
#pragma unroll
        for (int ks = 0; ks < 2; ks++) {
            wmma::fragment<wmma::matrix_a, 16, 16, 16, __half,
                           wmma::row_major> faH[4], faL[4];
#pragma unroll
            for (int i = 0; i < 4; i++) {
                int off = (warp_m * 64 + i * 16) * 40 + ks * 16;
                wmma::load_matrix_sync(faH[i], AsH + off, 40);
                wmma::load_matrix_sync(faL[i], AsL + off, 40);
            }
#pragma unroll
            for (int j = 0; j < 2; j++) {
                int off = (warp_n * 32 + j * 16) * 40 + ks * 16;
                wmma::fragment<wmma::matrix_b, 16, 16, 16, __half,
                               wmma::col_major> fbH, fbL;
                wmma::load_matrix_sync(fbH, BsH + off, 40);
                wmma::load_matrix_sync(fbL, BsL + off, 40);
#pragma unroll
                for (int i = 0; i < 4; i++) {
                    wmma::mma_sync(acc[i][j], faH[i], fbL, acc[i][j]);
                    wmma::mma_sync(acc[i][j], faL[i], fbH, acc[i][j]);
                    wmma::mma_sync(acc[i][j], faH[i], fbH, acc[i][j]);
                }
            }
        }
        if (kb + 1 < KB) sts(p ^ 1);
        __syncthreads();
    }

    float* Cs = (float*)smraw;
#pragma unroll
    for (int i = 0; i < 4; i++)
#pragma unroll
        for (int j = 0; j < 2; j++)
            wmma::store_matrix_sync(
                Cs + (warp_m * 64 + i * 16) * 132 + warp_n * 32 + j * 16,
                acc[i][j], 132, wmma::mem_row_major);
    __syncthreads();
    for (int e = t; e < 128 * 32; e += 256) {
        int r = e >> 5, c4 = e & 31;
        float4 v = *(float4*)&Cs[r * 132 + c4 * 4];
        size_t idx = (size_t)(by * 128 + r) * 128 + c4 * 4;
        float vv[4] = {v.x, v.y, v.z, v.w};
#pragma unroll
        for (int q = 0; q < 4; q++) {
            __half h = __float2half_rn(vv[q]);
            CH[idx + q] = h;
            CL[idx + q] = __float2half_rn(vv[q] - __half2float(h));
        }
    }
}

// ---------------- v GEMM engine (plain fp16, cp.async, EPI: vT store) -------
__global__ __launch_bounds__(256) void gemm_v16(const __half* __restrict__ A,
                                                const __half* __restrict__ B,
                                                __half* __restrict__ C) {
    extern __shared__ char smraw[];
    __half* sm = (__half*)smraw;
    constexpr int TN = 256;
    constexpr int ASZ = 128 * 40, BSZ = TN * 40;
    constexpr int STG = ASZ + BSZ;
    constexpr int NT = TN / 64;

    const int t = threadIdx.x, wid = t >> 5;
    const int warp_m = wid >> 2, warp_n = wid & 3;
    const int bx = blockIdx.x, by = blockIdx.y;
    const uint32_t smb = smem_u32(smraw);

    const __half* At = A + (size_t)(by * 128) * CC;
    const __half* Bt = B + (size_t)(bx * TN) * CC;

    wmma::fragment<wmma::accumulator, 16, 16, 16, float> acc[4][NT];
#pragma unroll
    for (int i = 0; i < 4; i++)
#pragma unroll
        for (int j = 0; j < NT; j++) wmma::fill_fragment(acc[i][j], 0.f);

    auto issue = [&](int s, int k0) {
        uint32_t ab = smb + s * STG * 2;
        uint32_t bb = ab + ASZ * 2;
#pragma unroll
        for (int i = 0; i < 2; i++) {
            int id = t + i * 256, r = id >> 2, c = id & 3;
            cp16(ab + (r * 40 + c * 8) * 2, At + (size_t)r * CC + k0 + c * 8);
        }
#pragma unroll
        for (int i = 0; i < 4; i++) {
            int id = t + i * 256, r = id >> 2, c = id & 3;
            cp16(bb + (r * 40 + c * 8) * 2, Bt + (size_t)r * CC + k0 + c * 8);
        }
    };

    issue(0, 0);
    CP_COMMIT();
    CP_WAIT0();
    __syncthreads();

    const int KB = CC / 32;
    for (int kb = 0; kb < KB; kb++) {
        const int p = kb & 1;
        if (kb + 1 < KB) {
            issue(p ^ 1, (kb + 1) * 32);
            CP_COMMIT();
        }
        __half* As = sm + p * STG;
        __half* Bs = As + ASZ;
#pragma unroll
        for (int ks = 0; ks < 2; ks++) {
            wmma::fragment<wmma::matrix_a, 16, 16, 16, __half,
                           wmma::row_major> fa[4];
#pragma unroll
            for (int i = 0; i < 4; i++)
                wmma::load_matrix_sync(
                    fa[i], As + (warp_m * 64 + i * 16) * 40 + ks * 16, 40);
#pragma unroll
            for (int j = 0; j < NT; j++) {
                wmma::fragment<wmma::matrix_b, 16, 16, 16, __half,
                               wmma::col_major> fb;
                wmma::load_matrix_sync(
                    fb, Bs + (warp_n * (TN / 4) + j * 16) * 40 + ks * 16, 40);
#pragma unroll
                for (int i = 0; i < 4; i++)
                    wmma::mma_sync(acc[i][j], fa[i], fb, acc[i][j]);
            }
        }
        if (kb + 1 < KB) CP_WAIT0();
        __syncthreads();
    }

    float* Cs = (float*)smraw;
    constexpr int LDCS = TN + 4;
#pragma unroll
    for (int i = 0; i < 4; i++)
#pragma unroll
        for (int j = 0; j < NT; j++)
            wmma::store_matrix_sync(
                Cs + (warp_m * 64 + i * 16) * LDCS + warp_n * (TN / 4) + j * 16,
                acc[i][j], LDCS, wmma::mem_row_major);
    __syncthreads();

    const int tok0 = by * 128;
    const int bglob = tok0 >> 12;
    const int tokin0 = tok0 & (NTOK - 1);
    for (int e = t; e < TN * 32; e += 256) {
        int j = e >> 5, tq = e & 31;
        size_t ob = ((size_t)bglob * CC + bx * TN + j) * NTOK + tokin0 + tq * 4;
#pragma unroll
        for (int q = 0; q < 4; q++)
            C[ob + q] = __float2half_rn(Cs[(tq * 4 + q) * LDCS + j]);
    }
}

// ---------------- S GEMM: single-shot K=64, fp16 split ----------------------
__global__ __launch_bounds__(256) void gemm_s(
    const __half* __restrict__ qkH, const __half* __restrict__ qkL,
    float* __restrict__ C, float* __restrict__ sump,
    float* __restrict__ maxp) {
    extern __shared__ char smraw[];
    __half* sm = (__half*)smraw;
    constexpr int AS = 128 * 72;
    constexpr int BS = 256 * 72;
    const int t = threadIdx.x, wid = t >> 5;
    const int warp_m = wid >> 2, warp_n = wid & 3;
    const int bx = blockIdx.x, by = blockIdx.y, bz = blockIdx.z;
    const uint32_t smb = smem_u32(smraw);

    const __half* AtH = qkH + (size_t)(bz * NTOK + by * 128) * 128;
    const __half* AtL = qkL + (size_t)(bz * NTOK + by * 128) * 128;
    const __half* BtH = qkH + (size_t)(bz * NTOK + bx * 256) * 128 + CRD;
    const __half* BtL = qkL + (size_t)(bz * NTOK + bx * 256) * 128 + CRD;

    const uint32_t aH = smb, aL = smb + AS * 2;
    const uint32_t bH = smb + 2 * AS * 2, bL = smb + (2 * AS + BS) * 2;
#pragma unroll
    for (int i = 0; i < 4; i++) {
        int id = t + i * 256, r = id >> 3, c = id & 7;
        uint32_t so = (r * 72 + c * 8) * 2;
        cp16(aH + so, AtH + (size_t)r * 128 + c * 8);
        cp16(aL + so, AtL + (size_t)r * 128 + c * 8);
    }
#pragma unroll
    for (int i = 0; i < 8; i++) {
        int id = t + i * 256, r = id >> 3, c = id & 7;
        uint32_t so = (r * 72 + c * 8) * 2;
        cp16(bH + so, BtH + (size_t)r * 128 + c * 8);
        cp16(bL + so, BtL + (size_t)r * 128 + c * 8);
    }
    CP_COMMIT();
    CP_WAIT0();
    __syncthreads();

    wmma::fragment<wmma::accumulator, 16, 16, 16, float> acc[4][4];
#pragma unroll
    for (int i = 0; i < 4; i++)
#pragma unroll
        for (int j = 0; j < 4; j++) wmma::fill_fragment(acc[i][j], 0.f);

    __half* AsH = sm;
    __half* AsL = sm + AS;
    __half* BsH = sm + 2 * AS;
    __half* BsL = sm + 2 * AS + BS;
#pragma unroll
    for (int ks = 0; ks < 4; ks++) {
        wmma::fragment<wmma::matrix_a, 16, 16, 16, __half, wmma::row_major>
            faH[4], faL[4];
#pragma unroll
        for (int i = 0; i < 4; i++) {
            int off = (warp_m * 64 + i * 16) * 72 + ks * 16;
            wmma::load_matrix_sync(faH[i], AsH + off, 72);
            wmma::load_matrix_sync(faL[i], AsL + off, 72);
        }
#pragma unroll
        for (int j = 0; j < 4; j++) {
            int off = (warp_n * 64 + j * 16) * 72 + ks * 16;
            wmma::fragment<wmma::matrix_b, 16, 16, 16, __half,
                           wmma::col_major> fbH, fbL;
            wmma::load_matrix_sync(fbH, BsH + off, 72);
            wmma::load_matrix_sync(fbL, BsL + off, 72);
#pragma unroll
            for (int i = 0; i < 4; i++) {
                wmma::mma_sync(acc[i][j], faH[i], fbL, acc[i][j]);
                wmma::mma_sync(acc[i][j], faL[i], fbH, acc[i][j]);
                wmma::mma_sync(acc[i][j], faH[i], fbH, acc[i][j]);
            }
        }
    }
    __syncthreads();  // smem reuse: tiles -> Cs

    float* Cs = (float*)smraw;
    constexpr int LDCS = 260;
#pragma unroll
    for (int i = 0; i < 4; i++)
#pragma unroll
        for (int j = 0; j < 4; j++)
            wmma::store_matrix_sync(
                Cs + (warp_m * 64 + i * 16) * LDCS + warp_n * 64 + j * 16,
                acc[i][j], LDCS, wmma::mem_row_major);
    __syncthreads();

    const int lane = t & 31;
#pragma unroll 4
    for (int it = 0; it < 32; it++) {
        int e = t + it * 256;
        int r = e >> 6, c4 = e & 63;
        float4 v = *(float4*)&Cs[r * LDCS + c4 * 4];
        float4 p;
        p.x = __expf(v.x - ESHIFT);
        p.y = __expf(v.y - ESHIFT);
        p.z = __expf(v.z - ESHIFT);
        p.w = __expf(v.w - ESHIFT);
        float s4 = p.x + p.y + p.z + p.w;
        float m4 = fmaxf(fmaxf(p.x, p.y), fmaxf(p.z, p.w));
        size_t base = (size_t)bz * NTOK * NTOK + (size_t)(by * 128 + r) * NTOK +
                      bx * 256 + c4 * 4;
        *(float4*)&C[base] = p;
#pragma unroll
        for (int o = 16; o; o >>= 1) {
            s4 += __shfl_xor_sync(~0u, s4, o);
            m4 = fmaxf(m4, __shfl_xor_sync(~0u, m4, o));
        }
        if (lane == 0) {
            int slot = bx * 2 + ((c4 >> 5) & 1);
            size_t pi = ((size_t)bz * 32 + slot) * NTOK + by * 128 + r;
            sump[pi] = s4;
            maxp[pi] = m4;
        }
    }
}

// ---------------- PV GEMM: fp32 P (staged,*pscale,->fp16) x fp16 vT ---------
__global__ __launch_bounds__(256) void gemm_pv(
    const float* __restrict__ P, const __half* __restrict__ vT,
    float* __restrict__ C, const float* __restrict__ pscale,
    const float* __restrict__ oscale, const float* __restrict__ xres,
    const float* __restrict__ gamma) {
    extern __shared__ char smraw[];
    __half* sm = (__half*)smraw;
    constexpr int TN = 256;
    constexpr int ASTG = 128 * 40;  // halfs per A stage (2 stages)
    constexpr int BSTG = TN * 40;   // halfs per B stage (3 stages)
    constexpr int NT = TN / 64;

    const int t = threadIdx.x, wid = t >> 5;
    const int warp_m = wid >> 2, warp_n = wid & 3;
    const int bx = blockIdx.x, by = blockIdx.y, bz = blockIdx.z;
    const uint32_t smb = smem_u32(smraw);

    const float* At = P + (size_t)bz * NTOK * NTOK + (size_t)(by * 128) * NTOK;
    const __half* Bt = vT + (size_t)bz * CC * NTOK + (size_t)(bx * TN) * NTOK;

    float psc[4];
#pragma unroll
    for (int i = 0; i < 4; i++) {
        int r = (t + i * 256) >> 3;
        psc[i] = pscale[bz * NTOK + by * 128 + r];
    }

    wmma::fragment<wmma::accumulator, 16, 16, 16, float> acc[4][NT];
#pragma unroll
    for (int i = 0; i < 4; i++)
#pragma unroll
        for (int j = 0; j < NT; j++) wmma::fill_fragment(acc[i][j], 0.f);

    float4 ra[4];
    auto ldgA = [&](int k0) {
#pragma unroll
        for (int i = 0; i < 4; i++) {
            int id = t + i * 256, r = id >> 3, c = id & 7;
            ra[i] = *(const float4*)&At[(size_t)r * NTOK + k0 + c * 4];
        }
    };
    auto stsA = [&](int s) {
        __half* As = sm + s * ASTG;
#pragma unroll
        for (int i = 0; i < 4; i++) {
            int id = t + i * 256, r = id >> 3, c = id & 7;
            __half* d = &As[r * 40 + c * 4];
            d[0] = __float2half_rn(ra[i].x * psc[i]);
            d[1] = __float2half_rn(ra[i].y * psc[i]);
            d[2] = __float2half_rn(ra[i].z * psc[i]);
            d[3] = __float2half_rn(ra[i].w * psc[i]);
        }
    };
    auto issueB = [&](int s, int k0) {
        uint32_t bb = smb + (2 * ASTG + s * BSTG) * 2;
#pragma unroll
        for (int i = 0; i < 4; i++) {
            int id = t + i * 256, r = id >> 2, c = id & 3;
            cp16(bb + (r * 40 + c * 8) * 2, Bt + (size_t)r * NTOK + k0 + c * 8);
        }
    };

    issueB(0, 0);
    CP_COMMIT();
    issueB(1, 32);
    CP_COMMIT();
    ldgA(0);
    stsA(0);
    CP_WAIT1();
    __syncthreads();

    const int KB = NTOK / 32;
    for (int kb = 0; kb < KB; kb++) {
        const int pa = kb & 1;
        const int pb = kb % 3;
        if (kb + 1 < KB) ldgA((kb + 1) * 32);
        if (kb + 2 < KB) {
            issueB((kb + 2) % 3, (kb + 2) * 32);
            CP_COMMIT();
        }
        __half* As = sm + pa * ASTG;
        __half* Bs = sm + 2 * ASTG + pb * BSTG;
#pragma unroll
        for (int ks = 0; ks < 2; ks++) {
            wmma::fragment<wmma::matrix_a, 16, 16, 16, __half,
                           wmma::row_major> fa[4];
#pragma unroll
            for (int i = 0; i < 4; i++)
                wmma::load_matrix_sync(
                    fa[i], As + (warp_m * 64 + i * 16) * 40 + ks * 16, 40);
#pragma unroll
            for (int j = 0; j < NT; j++) {
                wmma::fragment<wmma::matrix_b, 16, 16, 16, __half,
                               wmma::col_major> fb;
                wmma::load_matrix_sync(
                    fb, Bs + (warp_n * (TN / 4) + j * 16) * 40 + ks * 16, 40);
#pragma unroll
                for (int i = 0; i < 4; i++)
                    wmma::mma_sync(acc[i][j], fa[i], fb, acc[i][j]);
            }
        }
        if (kb + 1 < KB) {
            stsA(pa ^ 1);
            if (kb + 2 < KB) CP_WAIT1();
            else CP_WAIT0();
        }
        __syncthreads();
    }

    float* Cs = (float*)smraw;
    constexpr int LDCS = TN + 4;
#pragma unroll
    for (int i = 0; i < 4; i++)
#pragma unroll
        for (int j = 0; j < NT; j++)
            wmma::store_matrix_sync(
                Cs + (warp_m * 64 + i * 16) * LDCS + warp_n * (TN / 4) + j * 16,
                acc[i][j], LDCS, wmma::mem_row_major);
    __syncthreads();

    const float g = gamma[0];
    for (int e = t; e < 128 * (TN / 4); e += 256) {
        int r = e / (TN / 4), c4 = e % (TN / 4);
        float4 o = *(float4*)&Cs[r * LDCS + c4 * 4];
        size_t base = (size_t)bz * NTOK * CC + (size_t)(by * 128 + r) * CC +
                      bx * TN + c4 * 4;
        float gl = g * oscale[bz * NTOK + by * 128 + r];
        float4 xr = *(const float4*)&xres[base];
        o.x = gl * o.x + xr.x;
        o.y = gl * o.y + xr.y;
        o.z = gl * o.z + xr.z;
        o.w = gl * o.w + xr.w;
        *(float4*)&C[base] = o;
    }
}

// ---------------------------------------------------------------------------
extern "C" void kernel_launch(void* const* d_in, const int* in_sizes, int n_in,
                              void* d_out, int out_size) {
    const float* x = (const float*)d_in[0];
    const float* Wb = (const float*)d_in[1];
    const float* Wc = (const float*)d_in[2];
    const float* Wd = (const float*)d_in[3];
    const float* gamma = (const float*)d_in[4];
    float* out = (float*)d_out;

    __half *qkH, *qkL, *xh, *vTp, *WdT16;
    float *Sp, *lpart, *mpart, *pscale, *oscale, *WqkT;
    cudaGetSymbolAddress((void**)&qkH, g_qkH);
    cudaGetSymbolAddress((void**)&qkL, g_qkL);
    cudaGetSymbolAddress((void**)&xh, g_xh);
    cudaGetSymbolAddress((void**)&vTp, g_vT);
    cudaGetSymbolAddress((void**)&Sp, g_S);
    cudaGetSymbolAddress((void**)&lpart, g_lpart);
    cudaGetSymbolAddress((void**)&mpart, g_mpart);
    cudaGetSymbolAddress((void**)&pscale, g_pscale);
    cudaGetSymbolAddress((void**)&oscale, g_oscale);
    cudaGetSymbolAddress((void**)&WqkT, g_WqkT);
    cudaGetSymbolAddress((void**)&WdT16, g_WdT16);

    const int smem_qk = 2 * 2 * 2 * (128 + 128) * 40;  // 81920
    const int smem_S = 133120;
    const int smem_v = 133120;
    const int smem_PV = 133120;
    cudaFuncSetAttribute(gemm_qk_h,
                         cudaFuncAttributeMaxDynamicSharedMemorySize, smem_qk);
    cudaFuncSetAttribute(gemm_s,
                         cudaFuncAttributeMaxDynamicSharedMemorySize, smem_S);
    cudaFuncSetAttribute(gemm_v16,
                         cudaFuncAttributeMaxDynamicSharedMemorySize, smem_v);
    cudaFuncSetAttribute(gemm_pv,
                         cudaFuncAttributeMaxDynamicSharedMemorySize, smem_PV);

    // lazily created side stream + fork/join events (host resources only;
    // created on the uncaptured first call, reused — launched work identical)
    static cudaStream_t s2 = nullptr;
    static cudaEvent_t evb = nullptr, evq = nullptr;
    if (!s2) {
        cudaStreamCreateWithFlags(&s2, cudaStreamNonBlocking);
        cudaEventCreateWithFlags(&evb, cudaEventDisableTiming);
        cudaEventCreateWithFlags(&evq, cudaEventDisableTiming);
    }

    // fork: qk chain on s2, v chain on default
    cudaEventRecord(evb, 0);
    cudaStreamWaitEvent(s2, evb, 0);

    // s2: qk chain
    transpose_wqk<<<(128 * CC + 255) / 256, 256, 0, s2>>>(Wb, Wc, WqkT);
    gemm_qk_h<<<dim3(1, BNTOT / 128), 256, smem_qk, s2>>>(x, WqkT, qkH, qkL);
    cudaEventRecord(evq, s2);

    // default: v chain
    half_x<<<(BNTOT * CC / 4 + 255) / 256, 256>>>((const float4*)x,
                                                  (__half2*)xh,
                                                  BNTOT * CC / 4);
    transpose_wd_h<<<(CC * CC + 255) / 256, 256>>>(Wd, WdT16);
    gemm_v16<<<dim3(CC / 256, BNTOT / 128), 256, smem_v>>>(xh, WdT16, vTp);

    // join: S depends on qk
    cudaStreamWaitEvent(0, evq, 0);

    // P_raw = exp(q k^T - 40) fp32 + row sum/max partials (single-shot K)
    gemm_s<<<dim3(NTOK / 256, NTOK / 128, B_), 256, smem_S>>>(qkH, qkL, Sp,
                                                              lpart, mpart);
    // per-row scales
    reduce2<<<(B_ * NTOK + 255) / 256, 256>>>(lpart, mpart, pscale, oscale);
    // out = gamma * (P @ v) * oscale + x  (fused convert inside PV)
    gemm_pv<<<dim3(CC / 256, NTOK / 128, B_), 256, smem_PV>>>(
        Sp, vTp, out, pscale, oscale, x, gamma);
}

// round 16
// speedup vs baseline: 3.4872x; 1.0531x over previous
#include <cuda_runtime.h>
#include <cuda_fp16.h>
#include <mma.h>
#include <cstdint>

using namespace nvcuda;

// ---------------------------------------------------------------------------
// PAM, wmma fp16 + selective 2-term splits (~22 bits on score path).
//   s2:      transpose_wqk -> qk GEMM (split) -> S GEMM -> reduce
//   default: half_x, transpose_wd -> v GEMM -> (wait reduce) -> PV GEMM
// K-chunk 64 on v/PV mainloops (halved sync count vs round 15).
// ---------------------------------------------------------------------------

#define B_    4
#define NTOK  4096
#define CC    512
#define CRD   64
#define BNTOT (B_ * NTOK)
#define ESHIFT 40.0f

__device__ __half g_qkH[(size_t)BNTOT * 128];
__device__ __half g_qkL[(size_t)BNTOT * 128];
__device__ __half g_xh[(size_t)BNTOT * CC];        // fp16-rounded x
__device__ __half g_vT[(size_t)B_ * CC * NTOK];    // [b][c][tok] fp16
__device__ float  g_S[(size_t)B_ * NTOK * NTOK];   // raw exp probs fp32
__device__ float  g_lpart[(size_t)B_ * 32 * NTOK];
__device__ float  g_mpart[(size_t)B_ * 32 * NTOK];
__device__ float  g_pscale[B_ * NTOK];
__device__ float  g_oscale[B_ * NTOK];
__device__ float  g_WqkT[128 * CC];                // raw fp32
__device__ __half g_WdT16[CC * CC];                // fp16 transposed

__device__ __forceinline__ uint32_t smem_u32(const void* p) {
    uint32_t a;
    asm("{ .reg .u64 t; cvta.to.shared.u64 t, %1; cvt.u32.u64 %0, t; }"
        : "=r"(a) : "l"(p));
    return a;
}
__device__ __forceinline__ void cp16(uint32_t saddr, const void* g) {
    asm volatile("cp.async.cg.shared.global [%0], [%1], 16;" ::"r"(saddr),
                 "l"(g));
}
#define CP_COMMIT() asm volatile("cp.async.commit_group;" ::: "memory")
#define CP_WAIT0()  asm volatile("cp.async.wait_group 0;" ::: "memory")

// ---------------- producers --------------------------------------------------
__global__ void half_x(const float4* __restrict__ in, __half2* __restrict__ o,
                       int n4) {
    int i = blockIdx.x * 256 + threadIdx.x;
    if (i < n4) {
        float4 v = in[i];
        o[i * 2 + 0] = __floats2half2_rn(v.x, v.y);
        o[i * 2 + 1] = __floats2half2_rn(v.z, v.w);
    }
}
__global__ void transpose_wd_h(const float* __restrict__ W,
                               __half* __restrict__ WT) {
    int i = blockIdx.x * 256 + threadIdx.x;
    if (i < CC * CC) {
        int n = i / CC, k = i - n * CC;
        WT[i] = __float2half_rn(W[(size_t)k * CC + n]);
    }
}
__global__ void transpose_wqk(const float* __restrict__ Wb,
                              const float* __restrict__ Wc,
                              float* __restrict__ WT) {
    int i = blockIdx.x * 256 + threadIdx.x;
    if (i < 128 * CC) {
        int n = i / CC, k = i - n * CC;
        WT[i] = (n < CRD) ? Wb[(size_t)k * CRD + n]
                          : Wc[(size_t)k * CRD + (n - CRD)];
    }
}
__global__ void reduce2(const float* __restrict__ sp,
                        const float* __restrict__ mp,
                        float* __restrict__ pscale,
                        float* __restrict__ oscale) {
    int i = blockIdx.x * 256 + threadIdx.x;
    if (i < B_ * NTOK) {
        int b = i >> 12, row = i & (NTOK - 1);
        float s = 0.f, m = 0.f;
#pragma unroll
        for (int j = 0; j < 32; j++) {
            s += sp[((size_t)b * 32 + j) * NTOK + row];
            m = fmaxf(m, mp[((size_t)b * 32 + j) * NTOK + row]);
        }
        float ps = ldexpf(1.f, 14 - ilogbf(m));
        pscale[i] = ps;
        oscale[i] = 1.f / (s * ps);
    }
}

// ---------------- qk GEMM: register-staged fp16 split ------------------------
__global__ __launch_bounds__(256) void gemm_qk_h(const float* __restrict__ A,
                                                 const float* __restrict__ B,
                                                 __half* __restrict__ CH,
                                                 __half* __restrict__ CL) {
    extern __shared__ char smraw[];
    __half* sm = (__half*)smraw;
    constexpr int ASZ = 128 * 40, BSZ = 128 * 40;
    constexpr int STG = 2 * (ASZ + BSZ);
    const int t = threadIdx.x, wid = t >> 5;
    const int warp_m = wid >> 2, warp_n = wid & 3;
    const int by = blockIdx.y;
    const float* At = A + (size_t)(by * 128) * CC;

    wmma::fragment<wmma::accumulator, 16, 16, 16, float> acc[4][2];
#pragma unroll
    for (int i = 0; i < 4; i++)
#pragma unroll
        for (int j = 0; j < 2; j++) wmma::fill_fragment(acc[i][j], 0.f);

    float4 ra[4], rb[4];
    auto ldg = [&](int k0) {
#pragma unroll
        for (int i = 0; i < 4; i++) {
            int id = t + i * 256, r = id >> 3, c = id & 7;
            ra[i] = *(const float4*)&At[(size_t)r * CC + k0 + c * 4];
            rb[i] = *(const float4*)&B[(size_t)r * CC + k0 + c * 4];
        }
    };
    auto sts = [&](int s) {
        __half* AsH = sm + s * STG;
        __half* AsL = AsH + ASZ;
        __half* BsH = AsL + ASZ;
        __half* BsL = BsH + BSZ;
        auto split4 = [](float4 v, __half* dh, __half* dl) {
            __half h;
            h = __float2half_rn(v.x); dh[0] = h;
            dl[0] = __float2half_rn(v.x - __half2float(h));
            h = __float2half_rn(v.y); dh[1] = h;
            dl[1] = __float2half_rn(v.y - __half2float(h));
            h = __float2half_rn(v.z); dh[2] = h;
            dl[2] = __float2half_rn(v.z - __half2float(h));
            h = __float2half_rn(v.w); dh[3] = h;
            dl[3] = __float2half_rn(v.w - __half2float(h));
        };
#pragma unroll
        for (int i = 0; i < 4; i++) {
            int id = t + i * 256, r = id >> 3, c = id & 7;
            split4(ra[i], &AsH[r * 40 + c * 4], &AsL[r * 40 + c * 4]);
            split4(rb[i], &BsH[r * 40 + c * 4], &BsL[r * 40 + c * 4]);
        }
    };

    ldg(0);
    sts(0);
    __syncthreads();

    const int KB = CC / 32;
    for (int kb = 0; kb < KB; kb++) {
        const int p = kb & 1;
        if (kb + 1 < KB) ldg((kb + 1) * 32);
        __half* AsH = sm + p * STG;
        __half* AsL = AsH + ASZ;
        __half* BsH = AsL + ASZ;
        __half* BsL = BsH + BSZ;
#pragma unroll
        for (int ks = 0; ks < 2; ks++) {
            wmma::fragment<wmma::matrix_a, 16, 16, 16, __half,
                           wmma::row_major> faH[4], faL[4];
#pragma unroll
            for (int i = 0; i < 4; i++) {
                int off = (warp_m * 64 + i * 16) * 40 + ks * 16;
                wmma::load_matrix_sync(faH[i], AsH + off, 40);
                wmma::load_matrix_sync(faL[i], AsL + off, 40);
            }
#pragma unroll
            for (int j = 0; j < 2; j++) {
                int off = (warp_n * 32 + j * 16) * 40 + ks * 16;
                wmma::fragment<wmma::matrix_b, 16, 16, 16, __half,
                               wmma::col_major> fbH, fbL;
                wmma::load_matrix_sync(fbH, BsH + off, 40);
                wmma::load_matrix_sync(fbL, BsL + off, 40);
#pragma unroll
                for (int i = 0; i < 4; i++) {
                    wmma::mma_sync(acc[i][j], faH[i], fbL, acc[i][j]);
                    wmma::mma_sync(acc[i][j], faL[i], fbH, acc[i][j]);
                    wmma::mma_sync(acc[i][j], faH[i], fbH, acc[i][j]);
                }
            }
        }
        if (kb + 1 < KB) sts(p ^ 1);
        __syncthreads();
    }

    float* Cs = (float*)smraw;
#pragma unroll
    for (int i = 0; i < 4; i++)
#pragma unroll
        for (int j = 0; j < 2; j++)
            wmma::store_matrix_sync(
                Cs + (warp_m * 64 + i * 16) * 132 + warp_n * 32 + j * 16,
                acc[i][j], 132, wmma::mem_row_major);
    __syncthreads();
    for (int e = t; e < 128 * 32; e += 256) {
        int r = e >> 5, c4 = e & 31;
        float4 v = *(float4*)&Cs[r * 132 + c4 * 4];
        size_t idx = (size_t)(by * 128 + r) * 128 + c4 * 4;
        float vv[4] = {v.x, v.y, v.z, v.w};
#pragma unroll
        for (int q = 0; q < 4; q++) {
            __half h = __float2half_rn(vv[q]);
            CH[idx + q] = h;
            CL[idx + q] = __float2half_rn(vv[q] - __half2float(h));
        }
    }
}

// ---------------- v GEMM (plain fp16, cp.async, K-chunk 64, vT store) -------
__global__ __launch_bounds__(256) void gemm_v16(const __half* __restrict__ A,
                                                const __half* __restrict__ B,
                                                __half* __restrict__ C) {
    extern __shared__ char smraw[];
    __half* sm = (__half*)smraw;
    constexpr int TN = 256;
    constexpr int ASZ = 128 * 72, BSZ = TN * 72;   // halfs per stage comp
    constexpr int STG = ASZ + BSZ;
    constexpr int NT = TN / 64;

    const int t = threadIdx.x, wid = t >> 5;
    const int warp_m = wid >> 2, warp_n = wid & 3;
    const int bx = blockIdx.x, by = blockIdx.y;
    const uint32_t smb = smem_u32(smraw);

    const __half* At = A + (size_t)(by * 128) * CC;
    const __half* Bt = B + (size_t)(bx * TN) * CC;

    wmma::fragment<wmma::accumulator, 16, 16, 16, float> acc[4][NT];
#pragma unroll
    for (int i = 0; i < 4; i++)
#pragma unroll
        for (int j = 0; j < NT; j++) wmma::fill_fragment(acc[i][j], 0.f);

    auto issue = [&](int s, int k0) {
        uint32_t ab = smb + s * STG * 2;
        uint32_t bb = ab + ASZ * 2;
#pragma unroll
        for (int i = 0; i < 4; i++) {
            int id = t + i * 256, r = id >> 3, c = id & 7;
            cp16(ab + (r * 72 + c * 8) * 2, At + (size_t)r * CC + k0 + c * 8);
        }
#pragma unroll
        for (int i = 0; i < 8; i++) {
            int id = t + i * 256, r = id >> 3, c = id & 7;
            cp16(bb + (r * 72 + c * 8) * 2, Bt + (size_t)r * CC + k0 + c * 8);
        }
    };

    issue(0, 0);
    CP_COMMIT();
    CP_WAIT0();
    __syncthreads();

    const int KB = CC / 64;
    for (int kb = 0; kb < KB; kb++) {
        const int p = kb & 1;
        if (kb + 1 < KB) {
            issue(p ^ 1, (kb + 1) * 64);
            CP_COMMIT();
        }
        __half* As = sm + p * STG;
        __half* Bs = As + ASZ;
#pragma unroll
        for (int ks = 0; ks < 4; ks++) {
            wmma::fragment<wmma::matrix_a, 16, 16, 16, __half,
                           wmma::row_major> fa[4];
#pragma unroll
            for (int i = 0; i < 4; i++)
                wmma::load_matrix_sync(
                    fa[i], As + (warp_m * 64 + i * 16) * 72 + ks * 16, 72);
#pragma unroll
            for (int j = 0; j < NT; j++) {
                wmma::fragment<wmma::matrix_b, 16, 16, 16, __half,
                               wmma::col_major> fb;
                wmma::load_matrix_sync(
                    fb, Bs + (warp_n * (TN / 4) + j * 16) * 72 + ks * 16, 72);
#pragma unroll
                for (int i = 0; i < 4; i++)
                    wmma::mma_sync(acc[i][j], fa[i], fb, acc[i][j]);
            }
        }
        if (kb + 1 < KB) CP_WAIT0();
        __syncthreads();
    }

    float* Cs = (float*)smraw;
    constexpr int LDCS = TN + 4;
#pragma unroll
    for (int i = 0; i < 4; i++)
#pragma unroll
        for (int j = 0; j < NT; j++)
            wmma::store_matrix_sync(
                Cs + (warp_m * 64 + i * 16) * LDCS + warp_n * (TN / 4) + j * 16,
                acc[i][j], LDCS, wmma::mem_row_major);
    __syncthreads();

    const int tok0 = by * 128;
    const int bglob = tok0 >> 12;
    const int tokin0 = tok0 & (NTOK - 1);
    for (int e = t; e < TN * 32; e += 256) {
        int j = e >> 5, tq = e & 31;
        size_t ob = ((size_t)bglob * CC + bx * TN + j) * NTOK + tokin0 + tq * 4;
#pragma unroll
        for (int q = 0; q < 4; q++)
            C[ob + q] = __float2half_rn(Cs[(tq * 4 + q) * LDCS + j]);
    }
}

// ---------------- S GEMM: single-shot K=64, fp16 split ----------------------
__global__ __launch_bounds__(256) void gemm_s(
    const __half* __restrict__ qkH, const __half* __restrict__ qkL,
    float* __restrict__ C, float* __restrict__ sump,
    float* __restrict__ maxp) {
    extern __shared__ char smraw[];
    __half* sm = (__half*)smraw;
    constexpr int AS = 128 * 72;
    constexpr int BS = 256 * 72;
    const int t = threadIdx.x, wid = t >> 5;
    const int warp_m = wid >> 2, warp_n = wid & 3;
    const int bx = blockIdx.x, by = blockIdx.y, bz = blockIdx.z;
    const uint32_t smb = smem_u32(smraw);

    const __half* AtH = qkH + (size_t)(bz * NTOK + by * 128) * 128;
    const __half* AtL = qkL + (size_t)(bz * NTOK + by * 128) * 128;
    const __half* BtH = qkH + (size_t)(bz * NTOK + bx * 256) * 128 + CRD;
    const __half* BtL = qkL + (size_t)(bz * NTOK + bx * 256) * 128 + CRD;

    const uint32_t aH = smb, aL = smb + AS * 2;
    const uint32_t bH = smb + 2 * AS * 2, bL = smb + (2 * AS + BS) * 2;
#pragma unroll
    for (int i = 0; i < 4; i++) {
        int id = t + i * 256, r = id >> 3, c = id & 7;
        uint32_t so = (r * 72 + c * 8) * 2;
        cp16(aH + so, AtH + (size_t)r * 128 + c * 8);
        cp16(aL + so, AtL + (size_t)r * 128 + c * 8);
    }
#pragma unroll
    for (int i = 0; i < 8; i++) {
        int id = t + i * 256, r = id >> 3, c = id & 7;
        uint32_t so = (r * 72 + c * 8) * 2;
        cp16(bH + so, BtH + (size_t)r * 128 + c * 8);
        cp16(bL + so, BtL + (size_t)r * 128 + c * 8);
    }
    CP_COMMIT();
    CP_WAIT0();
    __syncthreads();

    wmma::fragment<wmma::accumulator, 16, 16, 16, float> acc[4][4];
#pragma unroll
    for (int i = 0; i < 4; i++)
#pragma unroll
        for (int j = 0; j < 4; j++) wmma::fill_fragment(acc[i][j], 0.f);

    __half* AsH = sm;
    __half* AsL = sm + AS;
    __half* BsH = sm + 2 * AS;
    __half* BsL = sm + 2 * AS + BS;
#pragma unroll
    for (int ks = 0; ks < 4; ks++) {
        wmma::fragment<wmma::matrix_a, 16, 16, 16, __half, wmma::row_major>
            faH[4], faL[4];
#pragma unroll
        for (int i = 0; i < 4; i++) {
            int off = (warp_m * 64 + i * 16) * 72 + ks * 16;
            wmma::load_matrix_sync(faH[i], AsH + off, 72);
            wmma::load_matrix_sync(faL[i], AsL + off, 72);
        }
#pragma unroll
        for (int j = 0; j < 4; j++) {
            int off = (warp_n * 64 + j * 16) * 72 + ks * 16;
            wmma::fragment<wmma::matrix_b, 16, 16, 16, __half,
                           wmma::col_major> fbH, fbL;
            wmma::load_matrix_sync(fbH, BsH + off, 72);
            wmma::load_matrix_sync(fbL, BsL + off, 72);
#pragma unroll
            for (int i = 0; i < 4; i++) {
                wmma::mma_sync(acc[i][j], faH[i], fbL, acc[i][j]);
                wmma::mma_sync(acc[i][j], faL[i], fbH, acc[i][j]);
                wmma::mma_sync(acc[i][j], faH[i], fbH, acc[i][j]);
            }
        }
    }
    __syncthreads();  // smem reuse: tiles -> Cs

    float* Cs = (float*)smraw;
    constexpr int LDCS = 260;
#pragma unroll
    for (int i = 0; i < 4; i++)
#pragma unroll
        for (int j = 0; j < 4; j++)
            wmma::store_matrix_sync(
                Cs + (warp_m * 64 + i * 16) * LDCS + warp_n * 64 + j * 16,
                acc[i][j], LDCS, wmma::mem_row_major);
    __syncthreads();

    const int lane = t & 31;
#pragma unroll 4
    for (int it = 0; it < 32; it++) {
        int e = t + it * 256;
        int r = e >> 6, c4 = e & 63;
        float4 v = *(float4*)&Cs[r * LDCS + c4 * 4];
        float4 p;
        p.x = __expf(v.x - ESHIFT);
        p.y = __expf(v.y - ESHIFT);
        p.z = __expf(v.z - ESHIFT);
        p.w = __expf(v.w - ESHIFT);
        float s4 = p.x + p.y + p.z + p.w;
        float m4 = fmaxf(fmaxf(p.x, p.y), fmaxf(p.z, p.w));
        size_t base = (size_t)bz * NTOK * NTOK + (size_t)(by * 128 + r) * NTOK +
                      bx * 256 + c4 * 4;
        *(float4*)&C[base] = p;
#pragma unroll
        for (int o = 16; o; o >>= 1) {
            s4 += __shfl_xor_sync(~0u, s4, o);
            m4 = fmaxf(m4, __shfl_xor_sync(~0u, m4, o));
        }
        if (lane == 0) {
            int slot = bx * 2 + ((c4 >> 5) & 1);
            size_t pi = ((size_t)bz * 32 + slot) * NTOK + by * 128 + r;
            sump[pi] = s4;
            maxp[pi] = m4;
        }
    }
}

// ---------------- PV GEMM: K-chunk 64, interleaved half-staged A ------------
// A: fp32 P * pscale -> fp16 at STS (two half-chunk batches, interleaved with
// MMA). B: vT fp16 cp.async 2-stage. out = gamma*acc*oscale + x.
__global__ __launch_bounds__(256) void gemm_pv(
    const float* __restrict__ P, const __half* __restrict__ vT,
    float* __restrict__ C, const float* __restrict__ pscale,
    const float* __restrict__ oscale, const float* __restrict__ xres,
    const float* __restrict__ gamma) {
    extern __shared__ char smraw[];
    __half* sm = (__half*)smraw;
    constexpr int TN = 256;
    constexpr int ASTG = 128 * 72;  // halfs per A stage
    constexpr int BSTG = TN * 72;   // halfs per B stage
    constexpr int STG = ASTG + BSTG;
    constexpr int NT = TN / 64;

    const int t = threadIdx.x, wid = t >> 5;
    const int warp_m = wid >> 2, warp_n = wid & 3;
    const int bx = blockIdx.x, by = blockIdx.y, bz = blockIdx.z;
    const uint32_t smb = smem_u32(smraw);

    const float* At = P + (size_t)bz * NTOK * NTOK + (size_t)(by * 128) * NTOK;
    const __half* Bt = vT + (size_t)bz * CC * NTOK + (size_t)(bx * TN) * NTOK;

    // per-thread loop-invariant row scales (rows fixed by id>>3 mapping)
    float psc[4];
#pragma unroll
    for (int i = 0; i < 4; i++) {
        int r = (t + i * 256) >> 3;
        psc[i] = pscale[bz * NTOK + by * 128 + r];
    }

    wmma::fragment<wmma::accumulator, 16, 16, 16, float> acc[4][NT];
#pragma unroll
    for (int i = 0; i < 4; i++)
#pragma unroll
        for (int j = 0; j < NT; j++) wmma::fill_fragment(acc[i][j], 0.f);

    float4 ra[4];
    // half h of chunk k0: float4 cols h*8+c (c=0..7) of the 16-wide chunk row
    auto ldgA = [&](int k0, int h) {
#pragma unroll
        for (int i = 0; i < 4; i++) {
            int id = t + i * 256, r = id >> 3, c = id & 7;
            ra[i] = *(const float4*)&At[(size_t)r * NTOK + k0 + h * 32 + c * 4];
        }
    };
    auto stsA = [&](int s, int h) {
        __half* As = sm + s * STG;
#pragma unroll
        for (int i = 0; i < 4; i++) {
            int id = t + i * 256, r = id >> 3, c = id & 7;
            __half* d = &As[r * 72 + h * 32 + c * 4];
            d[0] = __float2half_rn(ra[i].x * psc[i]);
            d[1] = __float2half_rn(ra[i].y * psc[i]);
            d[2] = __float2half_rn(ra[i].z * psc[i]);
            d[3] = __float2half_rn(ra[i].w * psc[i]);
        }
    };
    auto issueB = [&](int s, int k0) {
        uint32_t bb = smb + (s * STG + ASTG) * 2;
#pragma unroll
        for (int i = 0; i < 8; i++) {
            int id = t + i * 256, r = id >> 3, c = id & 7;
            cp16(bb + (r * 72 + c * 8) * 2, Bt + (size_t)r * NTOK + k0 + c * 8);
        }
    };

    issueB(0, 0);
    CP_COMMIT();
    ldgA(0, 0);
    stsA(0, 0);
    ldgA(0, 1);
    stsA(0, 1);
    CP_WAIT0();
    __syncthreads();

    const int KB = NTOK / 64;
    for (int kb = 0; kb < KB; kb++) {
        const int p = kb & 1;
        if (kb + 1 < KB) {
            issueB(p ^ 1, (kb + 1) * 64);
            CP_COMMIT();
            ldgA((kb + 1) * 64, 0);
        }
        __half* As = sm + p * STG;
        __half* Bs = As + ASTG;
#pragma unroll
        for (int ks = 0; ks < 4; ks++) {
            wmma::fragment<wmma::matrix_a, 16, 16, 16, __half,
                           wmma::row_major> fa[4];
#pragma unroll
            for (int i = 0; i < 4; i++)
                wmma::load_matrix_sync(
                    fa[i], As + (warp_m * 64 + i * 16) * 72 + ks * 16, 72);
#pragma unroll
            for (int j = 0; j < NT; j++) {
                wmma::fragment<wmma::matrix_b, 16, 16, 16, __half,
                               wmma::col_major> fb;
                wmma::load_matrix_sync(
                    fb, Bs + (warp_n * (TN / 4) + j * 16) * 72 + ks * 16, 72);
#pragma unroll
                for (int i = 0; i < 4; i++)
                    wmma::mma_sync(acc[i][j], fa[i], fb, acc[i][j]);
            }
            if (ks == 1 && kb + 1 < KB) {
                stsA(p ^ 1, 0);
                ldgA((kb + 1) * 64, 1);
            }
        }
        if (kb + 1 < KB) {
            stsA(p ^ 1, 1);
            CP_WAIT0();
        }
        __syncthreads();
    }

    float* Cs = (float*)smraw;
    constexpr int LDCS = TN + 4;
#pragma unroll
    for (int i = 0; i < 4; i++)
#pragma unroll
        for (int j = 0; j < NT; j++)
            wmma::store_matrix_sync(
                Cs + (warp_m * 64 + i * 16) * LDCS + warp_n * (TN / 4) + j * 16,
                acc[i][j], LDCS, wmma::mem_row_major);
    __syncthreads();

    const float g = gamma[0];
    for (int e = t; e < 128 * (TN / 4); e += 256) {
        int r = e / (TN / 4), c4 = e % (TN / 4);
        float4 o = *(float4*)&Cs[r * LDCS + c4 * 4];
        size_t base = (size_t)bz * NTOK * CC + (size_t)(by * 128 + r) * CC +
                      bx * TN + c4 * 4;
        float gl = g * oscale[bz * NTOK + by * 128 + r];
        float4 xr = *(const float4*)&xres[base];
        o.x = gl * o.x + xr.x;
        o.y = gl * o.y + xr.y;
        o.z = gl * o.z + xr.z;
        o.w = gl * o.w + xr.w;
        *(float4*)&C[base] = o;
    }
}

// ---------------------------------------------------------------------------
extern "C" void kernel_launch(void* const* d_in, const int* in_sizes, int n_in,
                              void* d_out, int out_size) {
    const float* x = (const float*)d_in[0];
    const float* Wb = (const float*)d_in[1];
    const float* Wc = (const float*)d_in[2];
    const float* Wd = (const float*)d_in[3];
    const float* gamma = (const float*)d_in[4];
    float* out = (float*)d_out;

    __half *qkH, *qkL, *xh, *vTp, *WdT16;
    float *Sp, *lpart, *mpart, *pscale, *oscale, *WqkT;
    cudaGetSymbolAddress((void**)&qkH, g_qkH);
    cudaGetSymbolAddress((void**)&qkL, g_qkL);
    cudaGetSymbolAddress((void**)&xh, g_xh);
    cudaGetSymbolAddress((void**)&vTp, g_vT);
    cudaGetSymbolAddress((void**)&Sp, g_S);
    cudaGetSymbolAddress((void**)&lpart, g_lpart);
    cudaGetSymbolAddress((void**)&mpart, g_mpart);
    cudaGetSymbolAddress((void**)&pscale, g_pscale);
    cudaGetSymbolAddress((void**)&oscale, g_oscale);
    cudaGetSymbolAddress((void**)&WqkT, g_WqkT);
    cudaGetSymbolAddress((void**)&WdT16, g_WdT16);

    const int smem_qk = 2 * 2 * 2 * (128 + 128) * 40;  // 81920
    const int smem_S = 133120;
    const int smem_v = 133120;   // max(2*(128+256)*72*2=110592, Cs 133120)
    const int smem_PV = 133120;
    cudaFuncSetAttribute(gemm_qk_h,
                         cudaFuncAttributeMaxDynamicSharedMemorySize, smem_qk);
    cudaFuncSetAttribute(gemm_s,
                         cudaFuncAttributeMaxDynamicSharedMemorySize, smem_S);
    cudaFuncSetAttribute(gemm_v16,
                         cudaFuncAttributeMaxDynamicSharedMemorySize, smem_v);
    cudaFuncSetAttribute(gemm_pv,
                         cudaFuncAttributeMaxDynamicSharedMemorySize, smem_PV);

    // lazily created side stream + fork/join events (host resources only)
    static cudaStream_t s2 = nullptr;
    static cudaEvent_t evb = nullptr, evr = nullptr;
    if (!s2) {
        cudaStreamCreateWithFlags(&s2, cudaStreamNonBlocking);
        cudaEventCreateWithFlags(&evb, cudaEventDisableTiming);
        cudaEventCreateWithFlags(&evr, cudaEventDisableTiming);
    }

    // fork
    cudaEventRecord(evb, 0);
    cudaStreamWaitEvent(s2, evb, 0);

    // s2: qk chain -> S -> reduce
    transpose_wqk<<<(128 * CC + 255) / 256, 256, 0, s2>>>(Wb, Wc, WqkT);
    gemm_qk_h<<<dim3(1, BNTOT / 128), 256, smem_qk, s2>>>(x, WqkT, qkH, qkL);
    gemm_s<<<dim3(NTOK / 256, NTOK / 128, B_), 256, smem_S, s2>>>(
        qkH, qkL, Sp, lpart, mpart);
    reduce2<<<(B_ * NTOK + 255) / 256, 256, 0, s2>>>(lpart, mpart, pscale,
                                                     oscale);
    cudaEventRecord(evr, s2);

    // default: v chain
    half_x<<<(BNTOT * CC / 4 + 255) / 256, 256>>>((const float4*)x,
                                                  (__half2*)xh,
                                                  BNTOT * CC / 4);
    transpose_wd_h<<<(CC * CC + 255) / 256, 256>>>(Wd, WdT16);
    gemm_v16<<<dim3(CC / 256, BNTOT / 128), 256, smem_v>>>(xh, WdT16, vTp);

    // join: PV needs reduce (s2) and v (default program order)
    cudaStreamWaitEvent(0, evr, 0);

    // out = gamma * (P @ v) * oscale + x  (fused convert inside PV)
    gemm_pv<<<dim3(CC / 256, NTOK / 128, B_), 256, smem_PV>>>(
        Sp, vTp, out, pscale, oscale, x, gamma);
}